// round 1
// baseline (speedup 1.0000x reference)
#include <cuda_runtime.h>
#include <cuda_bf16.h>
#include <math_constants.h>

// Problem constants
#define BB 2
#define TT 2048
#define NE 2048
#define NH 16
#define NKV 4
#define HD 128
#define GRP (NH / NKV)
#define MROWS (BB * TT)          // 4096
#define KVE (NKV * HD)           // 512
static const float ATT_SCALE = 0.08838834764831845f; // 1/sqrt(128)

// Scratch (no allocations allowed)
__device__ float g_q[MROWS * NE];   // (B,T,H,D)
__device__ float g_k[MROWS * KVE];  // (B,T,Hkv,D)
__device__ float g_v[MROWS * KVE];
__device__ float g_y[MROWS * NE];   // attention output (B,T,H,D)

// ---------------------------------------------------------------------------
// NT GEMM: C[m,n] = sum_k A[m,k] * B[n,k]
// A: M x K row-major, B: N x K row-major, C: M x N row-major
// Tiles: 64x64, K-step 32, 256 threads, 4x4 per thread.
// ---------------------------------------------------------------------------
#define GBM 64
#define GBN 64
#define GBK 32

__global__ __launch_bounds__(256) void gemm_nt(const float* __restrict__ A,
                                               const float* __restrict__ B,
                                               float* __restrict__ C,
                                               int M, int N, int K) {
    __shared__ float As[GBM][GBK];        // row-major, stride 32
    __shared__ float Bst[GBK][GBN + 1];   // transposed B tile, stride 65

    const int t  = threadIdx.x;
    const int tx = t & 15;
    const int ty = t >> 4;
    const int row0 = blockIdx.y * GBM;
    const int col0 = blockIdx.x * GBN;

    float acc[4][4];
#pragma unroll
    for (int i = 0; i < 4; i++)
#pragma unroll
        for (int j = 0; j < 4; j++) acc[i][j] = 0.0f;

    for (int kb = 0; kb < K; kb += GBK) {
        // Load A tile: 64x32 = 512 float4, 2 per thread (coalesced)
#pragma unroll
        for (int i = 0; i < 2; i++) {
            int f4 = t + i * 256;
            int r = f4 >> 3, c4 = f4 & 7;
            float4 va = *(const float4*)(A + (size_t)(row0 + r) * K + kb + c4 * 4);
            *(float4*)(&As[r][c4 * 4]) = va;
        }
        // Load B tile transposed: rows n, cols k -> Bst[k][n]
#pragma unroll
        for (int i = 0; i < 2; i++) {
            int f4 = t + i * 256;
            int n = f4 >> 3, c4 = f4 & 7;
            float4 vb = *(const float4*)(B + (size_t)(col0 + n) * K + kb + c4 * 4);
            Bst[c4 * 4 + 0][n] = vb.x;
            Bst[c4 * 4 + 1][n] = vb.y;
            Bst[c4 * 4 + 2][n] = vb.z;
            Bst[c4 * 4 + 3][n] = vb.w;
        }
        __syncthreads();

#pragma unroll
        for (int kk = 0; kk < GBK; kk++) {
            float a[4], b[4];
#pragma unroll
            for (int i = 0; i < 4; i++) a[i] = As[ty * 4 + i][kk];
#pragma unroll
            for (int j = 0; j < 4; j++) b[j] = Bst[kk][tx + 16 * j];
#pragma unroll
            for (int i = 0; i < 4; i++)
#pragma unroll
                for (int j = 0; j < 4; j++) acc[i][j] += a[i] * b[j];
        }
        __syncthreads();
    }

#pragma unroll
    for (int i = 0; i < 4; i++)
#pragma unroll
        for (int j = 0; j < 4; j++)
            C[(size_t)(row0 + ty * 4 + i) * N + col0 + tx + 16 * j] = acc[i][j];
}

// ---------------------------------------------------------------------------
// Causal GQA flash attention, fp32, online softmax.
// Grid: (T/64, B*H). Block: 256 threads (16x16).
// Thread (ty,tx): S rows ty*4+i, S cols tx+16*j; O rows ty*4+i, O cols tx+16*j.
// ---------------------------------------------------------------------------
#define AQ 64
#define AKV 64
// smem floats: Qs 64*128, Kt 128*65, Vs 64*128, Ps 64*65
#define SM_QS 0
#define SM_KT (64 * 128)
#define SM_VS (SM_KT + 128 * 65)
#define SM_PS (SM_VS + 64 * 128)
#define SM_TOT (SM_PS + 64 * 65)

__global__ __launch_bounds__(256) void attn_kernel(const float* __restrict__ q,
                                                   const float* __restrict__ k,
                                                   const float* __restrict__ v,
                                                   float* __restrict__ y) {
    extern __shared__ float sm[];
    float* Qs = sm + SM_QS;   // [64][128]
    float* Kt = sm + SM_KT;   // [128][65]  (d-major)
    float* Vs = sm + SM_VS;   // [64][128]
    float* Ps = sm + SM_PS;   // [64][65]

    const int t  = threadIdx.x;
    const int tx = t & 15;
    const int ty = t >> 4;
    const int qb = blockIdx.x;
    const int bh = blockIdx.y;
    const int b  = bh >> 4;
    const int h  = bh & 15;
    const int hk = h / GRP;
    const int q0 = qb * AQ;

    // Load Q tile: 64 rows x 128 d = 2048 float4, 8 per thread
#pragma unroll
    for (int i = 0; i < 8; i++) {
        int f4 = t + i * 256;
        int r = f4 >> 5, d4 = f4 & 31;
        float4 vq = *(const float4*)(q + ((size_t)(b * TT + q0 + r) * NH + h) * HD + d4 * 4);
        *(float4*)(&Qs[r * 128 + d4 * 4]) = vq;
    }

    float mrow[4], lrow[4], acc[4][8];
#pragma unroll
    for (int i = 0; i < 4; i++) {
        mrow[i] = -CUDART_INF_F;
        lrow[i] = 0.0f;
#pragma unroll
        for (int j = 0; j < 8; j++) acc[i][j] = 0.0f;
    }

    for (int kb = 0; kb <= qb; kb++) {
        const int k0 = kb * AKV;
        // Load K (transposed to d-major) and V tiles
#pragma unroll
        for (int i = 0; i < 8; i++) {
            int f4 = t + i * 256;
            int c = f4 >> 5, d4 = f4 & 31;
            size_t gidx = ((size_t)(b * TT + k0 + c) * NKV + hk) * HD + d4 * 4;
            float4 vk = *(const float4*)(k + gidx);
            Kt[(d4 * 4 + 0) * 65 + c] = vk.x;
            Kt[(d4 * 4 + 1) * 65 + c] = vk.y;
            Kt[(d4 * 4 + 2) * 65 + c] = vk.z;
            Kt[(d4 * 4 + 3) * 65 + c] = vk.w;
            float4 vv = *(const float4*)(v + gidx);
            *(float4*)(&Vs[c * 128 + d4 * 4]) = vv;
        }
        __syncthreads();

        // S = Q K^T (64x64), per-thread 4x4
        float S[4][4];
#pragma unroll
        for (int i = 0; i < 4; i++)
#pragma unroll
            for (int j = 0; j < 4; j++) S[i][j] = 0.0f;

#pragma unroll 8
        for (int d = 0; d < HD; d++) {
            float a[4], bb[4];
#pragma unroll
            for (int i = 0; i < 4; i++) a[i] = Qs[(ty * 4 + i) * 128 + d];
#pragma unroll
            for (int j = 0; j < 4; j++) bb[j] = Kt[d * 65 + tx + 16 * j];
#pragma unroll
            for (int i = 0; i < 4; i++)
#pragma unroll
                for (int j = 0; j < 4; j++) S[i][j] += a[i] * bb[j];
        }

        const bool diag = (kb == qb);
#pragma unroll
        for (int i = 0; i < 4; i++) {
            const int r = ty * 4 + i;
            float rmax = -CUDART_INF_F;
#pragma unroll
            for (int j = 0; j < 4; j++) {
                int c = tx + 16 * j;
                float s = S[i][j] * ATT_SCALE;
                if (diag && c > r) s = -CUDART_INF_F;
                S[i][j] = s;
                rmax = fmaxf(rmax, s);
            }
            // reduce max over the 16-lane tx group
#pragma unroll
            for (int off = 1; off < 16; off <<= 1)
                rmax = fmaxf(rmax, __shfl_xor_sync(0xffffffffu, rmax, off));

            float mnew = fmaxf(mrow[i], rmax);
            float alpha = __expf(mrow[i] - mnew);
            float rsum = 0.0f;
#pragma unroll
            for (int j = 0; j < 4; j++) {
                float p = __expf(S[i][j] - mnew);
                S[i][j] = p;
                rsum += p;
            }
#pragma unroll
            for (int off = 1; off < 16; off <<= 1)
                rsum += __shfl_xor_sync(0xffffffffu, rsum, off);

            lrow[i] = lrow[i] * alpha + rsum;
            mrow[i] = mnew;
#pragma unroll
            for (int j = 0; j < 8; j++) acc[i][j] *= alpha;
#pragma unroll
            for (int j = 0; j < 4; j++) Ps[r * 65 + tx + 16 * j] = S[i][j];
        }
        __syncthreads();

        // O += P V : per-thread rows ty*4+i, cols tx+16*j (j=0..7)
#pragma unroll 4
        for (int c = 0; c < AKV; c++) {
            float pv[4];
#pragma unroll
            for (int i = 0; i < 4; i++) pv[i] = Ps[(ty * 4 + i) * 65 + c];
            float vv[8];
#pragma unroll
            for (int j = 0; j < 8; j++) vv[j] = Vs[c * 128 + tx + 16 * j];
#pragma unroll
            for (int i = 0; i < 4; i++)
#pragma unroll
                for (int j = 0; j < 8; j++) acc[i][j] += pv[i] * vv[j];
        }
        __syncthreads();
    }

    // Write O = acc / l to y in (B,T,H,D)
#pragma unroll
    for (int i = 0; i < 4; i++) {
        float inv = 1.0f / lrow[i];
        size_t base = ((size_t)(b * TT + q0 + ty * 4 + i) * NH + h) * HD;
#pragma unroll
        for (int j = 0; j < 8; j++)
            y[base + tx + 16 * j] = acc[i][j] * inv;
    }
}

// ---------------------------------------------------------------------------
extern "C" void kernel_launch(void* const* d_in, const int* in_sizes, int n_in,
                              void* d_out, int out_size) {
    const float* x  = (const float*)d_in[0];
    const float* wq = (const float*)d_in[1];
    const float* wk = (const float*)d_in[2];
    const float* wv = (const float*)d_in[3];
    const float* wo = (const float*)d_in[4];
    float* out = (float*)d_out;

    float *qp, *kp, *vp, *yp;
    cudaGetSymbolAddress((void**)&qp, g_q);
    cudaGetSymbolAddress((void**)&kp, g_k);
    cudaGetSymbolAddress((void**)&vp, g_v);
    cudaGetSymbolAddress((void**)&yp, g_y);

    // Projections: y = x @ W^T  (NT gemm)
    dim3 blk(256);
    dim3 grdQ(NE / GBN, MROWS / GBM);   // (32, 64)
    dim3 grdKV(KVE / GBN, MROWS / GBM); // (8, 64)
    gemm_nt<<<grdQ, blk>>>(x, wq, qp, MROWS, NE, NE);
    gemm_nt<<<grdKV, blk>>>(x, wk, kp, MROWS, KVE, NE);
    gemm_nt<<<grdKV, blk>>>(x, wv, vp, MROWS, KVE, NE);

    // Attention
    size_t smem = SM_TOT * sizeof(float);
    cudaFuncSetAttribute(attn_kernel, cudaFuncAttributeMaxDynamicSharedMemorySize, (int)smem);
    dim3 agrd(TT / AQ, BB * NH);        // (32, 32)
    attn_kernel<<<agrd, blk, smem>>>(qp, kp, vp, yp);

    // Output projection
    gemm_nt<<<grdQ, blk>>>(yp, wo, out, MROWS, NE, NE);
}

// round 2
// speedup vs baseline: 1.4054x; 1.4054x over previous
#include <cuda_runtime.h>
#include <cuda_bf16.h>
#include <math_constants.h>
#include <mma.h>

using namespace nvcuda;

// Problem constants
#define BB 2
#define TT 2048
#define NE 2048
#define NH 16
#define NKV 4
#define HD 128
#define GRP (NH / NKV)
#define MROWS (BB * TT)          // 4096
#define KVE (NKV * HD)           // 512
static const float ATT_SCALE = 0.08838834764831845f; // 1/sqrt(128)

// fp32 scratch
__device__ float g_q[MROWS * NE];   // (B,T,H,D)
__device__ float g_k[MROWS * KVE];  // (B,T,Hkv,D)
__device__ float g_v[MROWS * KVE];
__device__ float g_y[MROWS * NE];   // attention output (B,T,H,D)

// bf16 split scratch
__device__ __nv_bfloat16 g_xh[MROWS * NE],  g_xl[MROWS * NE];
__device__ __nv_bfloat16 g_wqh[NE * NE],    g_wql[NE * NE];
__device__ __nv_bfloat16 g_wkh[KVE * NE],   g_wkl[KVE * NE];
__device__ __nv_bfloat16 g_wvh[KVE * NE],   g_wvl[KVE * NE];
__device__ __nv_bfloat16 g_woh[NE * NE],    g_wol[NE * NE];
__device__ __nv_bfloat16 g_yh[MROWS * NE],  g_yl[MROWS * NE];

// ---------------------------------------------------------------------------
// Split fp32 -> bf16 hi + bf16 lo   (4 elements / thread, vectorized)
// ---------------------------------------------------------------------------
__global__ __launch_bounds__(256) void split_bf16(const float* __restrict__ x,
                                                  __nv_bfloat16* __restrict__ hi,
                                                  __nv_bfloat16* __restrict__ lo,
                                                  int n4) {
    int i = blockIdx.x * blockDim.x + threadIdx.x;
    if (i >= n4) return;
    float4 v = ((const float4*)x)[i];
    union { __nv_bfloat16 b[4]; uint2 u; } H, L;
    float vv[4] = {v.x, v.y, v.z, v.w};
#pragma unroll
    for (int j = 0; j < 4; j++) {
        __nv_bfloat16 h = __float2bfloat16(vv[j]);
        H.b[j] = h;
        L.b[j] = __float2bfloat16(vv[j] - __bfloat162float(h));
    }
    ((uint2*)hi)[i] = H.u;
    ((uint2*)lo)[i] = L.u;
}

// ---------------------------------------------------------------------------
// Tensor-core NT GEMM with bf16x3 split:
//   C[m,n] = sum_k (Ah+Al)[m,k] * (Bh+Bl)[n,k]  ~=  AhBh + AhBl + AlBh
// Block tile 128x128, K-step 32, 256 threads (8 warps: 2x4), warp tile 64x32.
// ---------------------------------------------------------------------------
#define TBM 128
#define TBN 128
#define TBK 32
#define TLD (TBK + 8)   // smem stride (elements), 80 bytes: multiple of 16B

__global__ __launch_bounds__(256) void gemm_nt_bf16x3(
    const __nv_bfloat16* __restrict__ Ah, const __nv_bfloat16* __restrict__ Al,
    const __nv_bfloat16* __restrict__ Bh, const __nv_bfloat16* __restrict__ Bl,
    float* __restrict__ C, int M, int N, int K)
{
    __shared__ __align__(256) __nv_bfloat16 sAh[TBM][TLD];
    __shared__ __align__(256) __nv_bfloat16 sAl[TBM][TLD];
    __shared__ __align__(256) __nv_bfloat16 sBh[TBN][TLD];
    __shared__ __align__(256) __nv_bfloat16 sBl[TBN][TLD];

    const int t  = threadIdx.x;
    const int w  = t >> 5;
    const int wm = w & 1;        // 0..1
    const int wn = w >> 1;       // 0..3
    const int row0 = blockIdx.y * TBM;
    const int col0 = blockIdx.x * TBN;

    wmma::fragment<wmma::accumulator, 16, 16, 16, float> acc[4][2];
#pragma unroll
    for (int i = 0; i < 4; i++)
#pragma unroll
        for (int j = 0; j < 2; j++) wmma::fill_fragment(acc[i][j], 0.0f);

    for (int kb = 0; kb < K; kb += TBK) {
        // Load tiles: each tile is 128 rows x 32 bf16 = 512 uint4; 2 per thread.
#pragma unroll
        for (int i = 0; i < 2; i++) {
            int p = t + i * 256;
            int r = p >> 2, q = p & 3;
            size_t ga = (size_t)(row0 + r) * K + kb + q * 8;
            size_t gb = (size_t)(col0 + r) * K + kb + q * 8;
            *(uint4*)&sAh[r][q * 8] = *(const uint4*)(Ah + ga);
            *(uint4*)&sAl[r][q * 8] = *(const uint4*)(Al + ga);
            *(uint4*)&sBh[r][q * 8] = *(const uint4*)(Bh + gb);
            *(uint4*)&sBl[r][q * 8] = *(const uint4*)(Bl + gb);
        }
        __syncthreads();

#pragma unroll
        for (int kk = 0; kk < TBK; kk += 16) {
            wmma::fragment<wmma::matrix_a, 16, 16, 16, __nv_bfloat16, wmma::row_major> ah[4], al[4];
            wmma::fragment<wmma::matrix_b, 16, 16, 16, __nv_bfloat16, wmma::col_major> bh[2], bl[2];
#pragma unroll
            for (int i = 0; i < 4; i++) {
                wmma::load_matrix_sync(ah[i], &sAh[wm * 64 + i * 16][kk], TLD);
                wmma::load_matrix_sync(al[i], &sAl[wm * 64 + i * 16][kk], TLD);
            }
#pragma unroll
            for (int j = 0; j < 2; j++) {
                wmma::load_matrix_sync(bh[j], &sBh[wn * 32 + j * 16][kk], TLD);
                wmma::load_matrix_sync(bl[j], &sBl[wn * 32 + j * 16][kk], TLD);
            }
#pragma unroll
            for (int i = 0; i < 4; i++)
#pragma unroll
                for (int j = 0; j < 2; j++) {
                    wmma::mma_sync(acc[i][j], ah[i], bh[j], acc[i][j]);
                    wmma::mma_sync(acc[i][j], ah[i], bl[j], acc[i][j]);
                    wmma::mma_sync(acc[i][j], al[i], bh[j], acc[i][j]);
                }
        }
        __syncthreads();
    }

#pragma unroll
    for (int i = 0; i < 4; i++)
#pragma unroll
        for (int j = 0; j < 2; j++)
            wmma::store_matrix_sync(
                &C[(size_t)(row0 + wm * 64 + i * 16) * N + col0 + wn * 32 + j * 16],
                acc[i][j], N, wmma::mem_row_major);
}

// ---------------------------------------------------------------------------
// Causal GQA flash attention, fp32, online softmax (unchanged from R1).
// ---------------------------------------------------------------------------
#define AQ 64
#define AKV 64
#define SM_QS 0
#define SM_KT (64 * 128)
#define SM_VS (SM_KT + 128 * 65)
#define SM_PS (SM_VS + 64 * 128)
#define SM_TOT (SM_PS + 64 * 65)

__global__ __launch_bounds__(256) void attn_kernel(const float* __restrict__ q,
                                                   const float* __restrict__ k,
                                                   const float* __restrict__ v,
                                                   float* __restrict__ y) {
    extern __shared__ float sm[];
    float* Qs = sm + SM_QS;
    float* Kt = sm + SM_KT;
    float* Vs = sm + SM_VS;
    float* Ps = sm + SM_PS;

    const int t  = threadIdx.x;
    const int tx = t & 15;
    const int ty = t >> 4;
    const int qb = blockIdx.x;
    const int bh = blockIdx.y;
    const int b  = bh >> 4;
    const int h  = bh & 15;
    const int hk = h / GRP;
    const int q0 = qb * AQ;

#pragma unroll
    for (int i = 0; i < 8; i++) {
        int f4 = t + i * 256;
        int r = f4 >> 5, d4 = f4 & 31;
        float4 vq = *(const float4*)(q + ((size_t)(b * TT + q0 + r) * NH + h) * HD + d4 * 4);
        *(float4*)(&Qs[r * 128 + d4 * 4]) = vq;
    }

    float mrow[4], lrow[4], acc[4][8];
#pragma unroll
    for (int i = 0; i < 4; i++) {
        mrow[i] = -CUDART_INF_F;
        lrow[i] = 0.0f;
#pragma unroll
        for (int j = 0; j < 8; j++) acc[i][j] = 0.0f;
    }

    for (int kb = 0; kb <= qb; kb++) {
        const int k0 = kb * AKV;
#pragma unroll
        for (int i = 0; i < 8; i++) {
            int f4 = t + i * 256;
            int c = f4 >> 5, d4 = f4 & 31;
            size_t gidx = ((size_t)(b * TT + k0 + c) * NKV + hk) * HD + d4 * 4;
            float4 vk = *(const float4*)(k + gidx);
            Kt[(d4 * 4 + 0) * 65 + c] = vk.x;
            Kt[(d4 * 4 + 1) * 65 + c] = vk.y;
            Kt[(d4 * 4 + 2) * 65 + c] = vk.z;
            Kt[(d4 * 4 + 3) * 65 + c] = vk.w;
            float4 vv = *(const float4*)(v + gidx);
            *(float4*)(&Vs[c * 128 + d4 * 4]) = vv;
        }
        __syncthreads();

        float S[4][4];
#pragma unroll
        for (int i = 0; i < 4; i++)
#pragma unroll
            for (int j = 0; j < 4; j++) S[i][j] = 0.0f;

#pragma unroll 8
        for (int d = 0; d < HD; d++) {
            float a[4], bb[4];
#pragma unroll
            for (int i = 0; i < 4; i++) a[i] = Qs[(ty * 4 + i) * 128 + d];
#pragma unroll
            for (int j = 0; j < 4; j++) bb[j] = Kt[d * 65 + tx + 16 * j];
#pragma unroll
            for (int i = 0; i < 4; i++)
#pragma unroll
                for (int j = 0; j < 4; j++) S[i][j] += a[i] * bb[j];
        }

        const bool diag = (kb == qb);
#pragma unroll
        for (int i = 0; i < 4; i++) {
            const int r = ty * 4 + i;
            float rmax = -CUDART_INF_F;
#pragma unroll
            for (int j = 0; j < 4; j++) {
                int c = tx + 16 * j;
                float s = S[i][j] * ATT_SCALE;
                if (diag && c > r) s = -CUDART_INF_F;
                S[i][j] = s;
                rmax = fmaxf(rmax, s);
            }
#pragma unroll
            for (int off = 1; off < 16; off <<= 1)
                rmax = fmaxf(rmax, __shfl_xor_sync(0xffffffffu, rmax, off));

            float mnew = fmaxf(mrow[i], rmax);
            float alpha = __expf(mrow[i] - mnew);
            float rsum = 0.0f;
#pragma unroll
            for (int j = 0; j < 4; j++) {
                float p = __expf(S[i][j] - mnew);
                S[i][j] = p;
                rsum += p;
            }
#pragma unroll
            for (int off = 1; off < 16; off <<= 1)
                rsum += __shfl_xor_sync(0xffffffffu, rsum, off);

            lrow[i] = lrow[i] * alpha + rsum;
            mrow[i] = mnew;
#pragma unroll
            for (int j = 0; j < 8; j++) acc[i][j] *= alpha;
#pragma unroll
            for (int j = 0; j < 4; j++) Ps[r * 65 + tx + 16 * j] = S[i][j];
        }
        __syncthreads();

#pragma unroll 4
        for (int c = 0; c < AKV; c++) {
            float pv[4];
#pragma unroll
            for (int i = 0; i < 4; i++) pv[i] = Ps[(ty * 4 + i) * 65 + c];
            float vv[8];
#pragma unroll
            for (int j = 0; j < 8; j++) vv[j] = Vs[c * 128 + tx + 16 * j];
#pragma unroll
            for (int i = 0; i < 4; i++)
#pragma unroll
                for (int j = 0; j < 8; j++) acc[i][j] += pv[i] * vv[j];
        }
        __syncthreads();
    }

#pragma unroll
    for (int i = 0; i < 4; i++) {
        float inv = 1.0f / lrow[i];
        size_t base = ((size_t)(b * TT + q0 + ty * 4 + i) * NH + h) * HD;
#pragma unroll
        for (int j = 0; j < 8; j++)
            y[base + tx + 16 * j] = acc[i][j] * inv;
    }
}

// ---------------------------------------------------------------------------
extern "C" void kernel_launch(void* const* d_in, const int* in_sizes, int n_in,
                              void* d_out, int out_size) {
    const float* x  = (const float*)d_in[0];
    const float* wq = (const float*)d_in[1];
    const float* wk = (const float*)d_in[2];
    const float* wv = (const float*)d_in[3];
    const float* wo = (const float*)d_in[4];
    float* out = (float*)d_out;

    float *qp, *kp, *vp, *yp;
    cudaGetSymbolAddress((void**)&qp, g_q);
    cudaGetSymbolAddress((void**)&kp, g_k);
    cudaGetSymbolAddress((void**)&vp, g_v);
    cudaGetSymbolAddress((void**)&yp, g_y);

    __nv_bfloat16 *xh, *xl, *wqh, *wql, *wkh, *wkl, *wvh, *wvl, *woh, *wol, *yh, *yl;
    cudaGetSymbolAddress((void**)&xh,  g_xh);  cudaGetSymbolAddress((void**)&xl,  g_xl);
    cudaGetSymbolAddress((void**)&wqh, g_wqh); cudaGetSymbolAddress((void**)&wql, g_wql);
    cudaGetSymbolAddress((void**)&wkh, g_wkh); cudaGetSymbolAddress((void**)&wkl, g_wkl);
    cudaGetSymbolAddress((void**)&wvh, g_wvh); cudaGetSymbolAddress((void**)&wvl, g_wvl);
    cudaGetSymbolAddress((void**)&woh, g_woh); cudaGetSymbolAddress((void**)&wol, g_wol);
    cudaGetSymbolAddress((void**)&yh,  g_yh);  cudaGetSymbolAddress((void**)&yl,  g_yl);

    // Splits
    int nx  = MROWS * NE / 4;
    int nw  = NE * NE / 4;
    int nwk = KVE * NE / 4;
    split_bf16<<<(nx  + 255) / 256, 256>>>(x,  xh,  xl,  nx);
    split_bf16<<<(nw  + 255) / 256, 256>>>(wq, wqh, wql, nw);
    split_bf16<<<(nwk + 255) / 256, 256>>>(wk, wkh, wkl, nwk);
    split_bf16<<<(nwk + 255) / 256, 256>>>(wv, wvh, wvl, nwk);
    split_bf16<<<(nw  + 255) / 256, 256>>>(wo, woh, wol, nw);

    // Projections on tensor cores
    dim3 blk(256);
    dim3 grdQ(NE / TBN, MROWS / TBM);   // (16, 32)
    dim3 grdKV(KVE / TBN, MROWS / TBM); // (4, 32)
    gemm_nt_bf16x3<<<grdQ, blk>>>(xh, xl, wqh, wql, qp, MROWS, NE, NE);
    gemm_nt_bf16x3<<<grdKV, blk>>>(xh, xl, wkh, wkl, kp, MROWS, KVE, NE);
    gemm_nt_bf16x3<<<grdKV, blk>>>(xh, xl, wvh, wvl, vp, MROWS, KVE, NE);

    // Attention (fp32)
    size_t smem = SM_TOT * sizeof(float);
    cudaFuncSetAttribute(attn_kernel, cudaFuncAttributeMaxDynamicSharedMemorySize, (int)smem);
    dim3 agrd(TT / AQ, BB * NH);
    attn_kernel<<<agrd, blk, smem>>>(qp, kp, vp, yp);

    // Output projection
    split_bf16<<<(nx + 255) / 256, 256>>>(yp, yh, yl, nx);
    gemm_nt_bf16x3<<<grdQ, blk>>>(yh, yl, woh, wol, out, MROWS, NE, NE);
}

// round 4
// speedup vs baseline: 1.7880x; 1.2723x over previous
#include <cuda_runtime.h>
#include <cuda_bf16.h>
#include <math_constants.h>
#include <mma.h>
#include <cstdint>

using namespace nvcuda;

#define BB 2
#define TT 2048
#define NE 2048
#define NH 16
#define NKV 4
#define HD 128
#define GRP (NH / NKV)
#define MROWS (BB * TT)
#define KVE (NKV * HD)

// fp32 scratch
__device__ float g_q[MROWS * NE];
__device__ float g_k[MROWS * KVE];
__device__ float g_v[MROWS * KVE];

// bf16 split scratch
__device__ __nv_bfloat16 g_xh[MROWS * NE],  g_xl[MROWS * NE];
__device__ __nv_bfloat16 g_wqh[NE * NE],    g_wql[NE * NE];
__device__ __nv_bfloat16 g_wkh[KVE * NE],   g_wkl[KVE * NE];
__device__ __nv_bfloat16 g_wvh[KVE * NE],   g_wvl[KVE * NE];
__device__ __nv_bfloat16 g_woh[NE * NE],    g_wol[NE * NE];
__device__ __nv_bfloat16 g_yh[MROWS * NE],  g_yl[MROWS * NE];

__device__ __forceinline__ uint32_t pack_bf16(float x, float y) {
    __nv_bfloat162 r = __floats2bfloat162_rn(x, y);
    return *(uint32_t*)&r;
}
__device__ __forceinline__ float fast_exp2(float x) {
    float y; asm("ex2.approx.f32 %0, %1;" : "=f"(y) : "f"(x)); return y;
}
__device__ __forceinline__ void mma16816(float* c, const uint32_t* a, uint32_t b0, uint32_t b1) {
    asm volatile("mma.sync.aligned.m16n8k16.row.col.f32.bf16.bf16.f32 "
                 "{%0,%1,%2,%3}, {%4,%5,%6,%7}, {%8,%9}, {%0,%1,%2,%3};\n"
                 : "+f"(c[0]), "+f"(c[1]), "+f"(c[2]), "+f"(c[3])
                 : "r"(a[0]), "r"(a[1]), "r"(a[2]), "r"(a[3]), "r"(b0), "r"(b1));
}

// ---------------------------------------------------------------------------
// split fp32 -> bf16 hi + lo
// ---------------------------------------------------------------------------
__global__ __launch_bounds__(256) void split_bf16(const float* __restrict__ x,
                                                  __nv_bfloat16* __restrict__ hi,
                                                  __nv_bfloat16* __restrict__ lo,
                                                  int n4) {
    int i = blockIdx.x * blockDim.x + threadIdx.x;
    if (i >= n4) return;
    float4 v = ((const float4*)x)[i];
    union { __nv_bfloat16 b[4]; uint2 u; } H, L;
    float vv[4] = {v.x, v.y, v.z, v.w};
#pragma unroll
    for (int j = 0; j < 4; j++) {
        __nv_bfloat16 h = __float2bfloat16(vv[j]);
        H.b[j] = h;
        L.b[j] = __float2bfloat16(vv[j] - __bfloat162float(h));
    }
    ((uint2*)hi)[i] = H.u;
    ((uint2*)lo)[i] = L.u;
}

// ---------------------------------------------------------------------------
// wmma NT GEMM, bf16x3
// ---------------------------------------------------------------------------
#define TBM 128
#define TBN 128
#define TBK 32
#define TLD (TBK + 8)

__global__ __launch_bounds__(256) void gemm_nt_bf16x3(
    const __nv_bfloat16* __restrict__ Ah, const __nv_bfloat16* __restrict__ Al,
    const __nv_bfloat16* __restrict__ Bh, const __nv_bfloat16* __restrict__ Bl,
    float* __restrict__ C, int M, int N, int K)
{
    __shared__ __align__(256) __nv_bfloat16 sAh[TBM][TLD];
    __shared__ __align__(256) __nv_bfloat16 sAl[TBM][TLD];
    __shared__ __align__(256) __nv_bfloat16 sBh[TBN][TLD];
    __shared__ __align__(256) __nv_bfloat16 sBl[TBN][TLD];

    const int t  = threadIdx.x;
    const int w  = t >> 5;
    const int wm = w & 1;
    const int wn = w >> 1;
    const int row0 = blockIdx.y * TBM;
    const int col0 = blockIdx.x * TBN;

    wmma::fragment<wmma::accumulator, 16, 16, 16, float> acc[4][2];
#pragma unroll
    for (int i = 0; i < 4; i++)
#pragma unroll
        for (int j = 0; j < 2; j++) wmma::fill_fragment(acc[i][j], 0.0f);

    for (int kb = 0; kb < K; kb += TBK) {
#pragma unroll
        for (int i = 0; i < 2; i++) {
            int p = t + i * 256;
            int r = p >> 2, qq = p & 3;
            size_t ga = (size_t)(row0 + r) * K + kb + qq * 8;
            size_t gb = (size_t)(col0 + r) * K + kb + qq * 8;
            *(uint4*)&sAh[r][qq * 8] = *(const uint4*)(Ah + ga);
            *(uint4*)&sAl[r][qq * 8] = *(const uint4*)(Al + ga);
            *(uint4*)&sBh[r][qq * 8] = *(const uint4*)(Bh + gb);
            *(uint4*)&sBl[r][qq * 8] = *(const uint4*)(Bl + gb);
        }
        __syncthreads();
#pragma unroll
        for (int kk = 0; kk < TBK; kk += 16) {
            wmma::fragment<wmma::matrix_a, 16, 16, 16, __nv_bfloat16, wmma::row_major> ah[4], al[4];
            wmma::fragment<wmma::matrix_b, 16, 16, 16, __nv_bfloat16, wmma::col_major> bh[2], bl[2];
#pragma unroll
            for (int i = 0; i < 4; i++) {
                wmma::load_matrix_sync(ah[i], &sAh[wm * 64 + i * 16][kk], TLD);
                wmma::load_matrix_sync(al[i], &sAl[wm * 64 + i * 16][kk], TLD);
            }
#pragma unroll
            for (int j = 0; j < 2; j++) {
                wmma::load_matrix_sync(bh[j], &sBh[wn * 32 + j * 16][kk], TLD);
                wmma::load_matrix_sync(bl[j], &sBl[wn * 32 + j * 16][kk], TLD);
            }
#pragma unroll
            for (int i = 0; i < 4; i++)
#pragma unroll
                for (int j = 0; j < 2; j++) {
                    wmma::mma_sync(acc[i][j], ah[i], bh[j], acc[i][j]);
                    wmma::mma_sync(acc[i][j], ah[i], bl[j], acc[i][j]);
                    wmma::mma_sync(acc[i][j], al[i], bh[j], acc[i][j]);
                }
        }
        __syncthreads();
    }
#pragma unroll
    for (int i = 0; i < 4; i++)
#pragma unroll
        for (int j = 0; j < 2; j++)
            wmma::store_matrix_sync(
                &C[(size_t)(row0 + wm * 64 + i * 16) * N + col0 + wn * 32 + j * 16],
                acc[i][j], N, wmma::mem_row_major);
}

// ---------------------------------------------------------------------------
// FA2-style tensor-core causal GQA attention.
// CTA: 128 Q rows, 8 warps (16 rows each). KV tile 64, D=128.
// ---------------------------------------------------------------------------
#define BQ 128
#define BKV 64
#define KSTR 136   // K smem row stride (bf16 units)
#define VSTR 72    // V^T smem row stride
#define SM_ATT_BYTES ((2 * BKV * KSTR + 2 * HD * VSTR) * 2)

__global__ __launch_bounds__(256, 1) void attn_mma(const float* __restrict__ q,
                                                   const float* __restrict__ k,
                                                   const float* __restrict__ v,
                                                   __nv_bfloat16* __restrict__ yh,
                                                   __nv_bfloat16* __restrict__ yl) {
    extern __shared__ __nv_bfloat16 smA[];
    __nv_bfloat16* Ksh = smA;
    __nv_bfloat16* Ksl = Ksh + BKV * KSTR;
    __nv_bfloat16* Vth = Ksl + BKV * KSTR;
    __nv_bfloat16* Vtl = Vth + HD * VSTR;

    const int t    = threadIdx.x;
    const int w    = t >> 5;
    const int lane = t & 31;
    const int qb   = (gridDim.x - 1) - blockIdx.x;   // heavy CTAs first
    const int bh   = blockIdx.y;
    const int b    = bh >> 4;
    const int h    = bh & 15;
    const int hk   = h / GRP;
    const int q0   = qb * BQ;
    const int rg0  = q0 + w * 16 + (lane >> 2);
    const int rg1  = rg0 + 8;
    const int qpair = (lane & 3) * 2;

    // ---- Load Q fragments (scaled), bf16 hi/lo ----
    const float qscale = 0.08838834764831845f * 1.4426950408889634f;
    uint32_t Qh[8][4], Ql[8][4];
#pragma unroll
    for (int kt = 0; kt < 8; kt++) {
#pragma unroll
        for (int half = 0; half < 2; half++) {
#pragma unroll
            for (int ri = 0; ri < 2; ri++) {
                int row = ri ? rg1 : rg0;
                int d = kt * 16 + half * 8 + qpair;
                float2 f = *(const float2*)(q + ((size_t)(b * TT + row) * NH + h) * HD + d);
                f.x *= qscale; f.y *= qscale;
                float hx = __bfloat162float(__float2bfloat16(f.x));
                float hy = __bfloat162float(__float2bfloat16(f.y));
                Qh[kt][half * 2 + ri] = pack_bf16(hx, hy);
                Ql[kt][half * 2 + ri] = pack_bf16(f.x - hx, f.y - hy);
            }
        }
    }

    float O[16][4];
#pragma unroll
    for (int nt = 0; nt < 16; nt++)
#pragma unroll
        for (int e = 0; e < 4; e++) O[nt][e] = 0.0f;
    float m0 = -CUDART_INF_F, m1 = -CUDART_INF_F, l0 = 0.0f, l1 = 0.0f;

    const int kb_end = 2 * qb + 2;
    for (int kb = 0; kb < kb_end; kb++) {
        const int k0 = kb * BKV;
        __syncthreads();
        // ---- load K (split) and V (split+transpose) ----
#pragma unroll
        for (int i = 0; i < 8; i++) {
            int f4 = t + i * 256;
            int c  = f4 >> 5;
            int d4 = f4 & 31;
            size_t g = ((size_t)(b * TT + k0 + c) * NKV + hk) * HD + d4 * 4;
            float4 kk = *(const float4*)(k + g);
            float kf[4] = {kk.x, kk.y, kk.z, kk.w};
            float khf[4];
#pragma unroll
            for (int j = 0; j < 4; j++) khf[j] = __bfloat162float(__float2bfloat16(kf[j]));
            *(__nv_bfloat162*)&Ksh[c * KSTR + d4 * 4]     = __floats2bfloat162_rn(khf[0], khf[1]);
            *(__nv_bfloat162*)&Ksh[c * KSTR + d4 * 4 + 2] = __floats2bfloat162_rn(khf[2], khf[3]);
            *(__nv_bfloat162*)&Ksl[c * KSTR + d4 * 4]     = __floats2bfloat162_rn(kf[0] - khf[0], kf[1] - khf[1]);
            *(__nv_bfloat162*)&Ksl[c * KSTR + d4 * 4 + 2] = __floats2bfloat162_rn(kf[2] - khf[2], kf[3] - khf[3]);

            float4 vv = *(const float4*)(v + g);
            float vf[4] = {vv.x, vv.y, vv.z, vv.w};
#pragma unroll
            for (int j = 0; j < 4; j++) {
                float vh = __bfloat162float(__float2bfloat16(vf[j]));
                Vth[(d4 * 4 + j) * VSTR + c] = __float2bfloat16(vh);
                Vtl[(d4 * 4 + j) * VSTR + c] = __float2bfloat16(vf[j] - vh);
            }
        }
        __syncthreads();

        // ---- S = Q K^T ----
        float S[8][4];
#pragma unroll
        for (int jt = 0; jt < 8; jt++)
#pragma unroll
            for (int e = 0; e < 4; e++) S[jt][e] = 0.0f;

#pragma unroll
        for (int kt = 0; kt < 8; kt++) {
#pragma unroll
            for (int jt = 0; jt < 8; jt++) {
                int base = (jt * 8 + (lane >> 2)) * KSTR + kt * 16 + qpair;
                uint32_t bh0 = *(const uint32_t*)&Ksh[base];
                uint32_t bh1 = *(const uint32_t*)&Ksh[base + 8];
                uint32_t bl0 = *(const uint32_t*)&Ksl[base];
                uint32_t bl1 = *(const uint32_t*)&Ksl[base + 8];
                mma16816(S[jt], Qh[kt], bh0, bh1);
                mma16816(S[jt], Qh[kt], bl0, bl1);
                mma16816(S[jt], Ql[kt], bh0, bh1);
            }
        }

        // ---- causal mask ----
        if (kb >= 2 * qb) {
#pragma unroll
            for (int jt = 0; jt < 8; jt++) {
                int c0 = k0 + jt * 8 + qpair;
                if (c0 > rg0)     S[jt][0] = -CUDART_INF_F;
                if (c0 + 1 > rg0) S[jt][1] = -CUDART_INF_F;
                if (c0 > rg1)     S[jt][2] = -CUDART_INF_F;
                if (c0 + 1 > rg1) S[jt][3] = -CUDART_INF_F;
            }
        }

        // ---- online softmax (base-2 domain) ----
        float mx0 = -CUDART_INF_F, mx1 = -CUDART_INF_F;
#pragma unroll
        for (int jt = 0; jt < 8; jt++) {
            mx0 = fmaxf(mx0, fmaxf(S[jt][0], S[jt][1]));
            mx1 = fmaxf(mx1, fmaxf(S[jt][2], S[jt][3]));
        }
#pragma unroll
        for (int off = 1; off <= 2; off <<= 1) {
            mx0 = fmaxf(mx0, __shfl_xor_sync(0xffffffffu, mx0, off));
            mx1 = fmaxf(mx1, __shfl_xor_sync(0xffffffffu, mx1, off));
        }
        float mn0 = fmaxf(m0, mx0), mn1 = fmaxf(m1, mx1);
        float al0 = fast_exp2(m0 - mn0), al1 = fast_exp2(m1 - mn1);
        float s0 = 0.0f, s1 = 0.0f;
#pragma unroll
        for (int jt = 0; jt < 8; jt++) {
            S[jt][0] = fast_exp2(S[jt][0] - mn0); s0 += S[jt][0];
            S[jt][1] = fast_exp2(S[jt][1] - mn0); s0 += S[jt][1];
            S[jt][2] = fast_exp2(S[jt][2] - mn1); s1 += S[jt][2];
            S[jt][3] = fast_exp2(S[jt][3] - mn1); s1 += S[jt][3];
        }
#pragma unroll
        for (int off = 1; off <= 2; off <<= 1) {
            s0 += __shfl_xor_sync(0xffffffffu, s0, off);
            s1 += __shfl_xor_sync(0xffffffffu, s1, off);
        }
        l0 = l0 * al0 + s0; l1 = l1 * al1 + s1;
        m0 = mn0; m1 = mn1;
#pragma unroll
        for (int nt = 0; nt < 16; nt++) {
            O[nt][0] *= al0; O[nt][1] *= al0;
            O[nt][2] *= al1; O[nt][3] *= al1;
        }

        // ---- O += P V ----
#pragma unroll
        for (int kt = 0; kt < 4; kt++) {
            uint32_t Ph[4], Pl[4];
            {
                float p00 = S[2 * kt][0],     p01 = S[2 * kt][1];
                float p10 = S[2 * kt][2],     p11 = S[2 * kt][3];
                float p20 = S[2 * kt + 1][0], p21 = S[2 * kt + 1][1];
                float p30 = S[2 * kt + 1][2], p31 = S[2 * kt + 1][3];
                float h00 = __bfloat162float(__float2bfloat16(p00));
                float h01 = __bfloat162float(__float2bfloat16(p01));
                float h10 = __bfloat162float(__float2bfloat16(p10));
                float h11 = __bfloat162float(__float2bfloat16(p11));
                float h20 = __bfloat162float(__float2bfloat16(p20));
                float h21 = __bfloat162float(__float2bfloat16(p21));
                float h30 = __bfloat162float(__float2bfloat16(p30));
                float h31 = __bfloat162float(__float2bfloat16(p31));
                Ph[0] = pack_bf16(h00, h01); Ph[1] = pack_bf16(h10, h11);
                Ph[2] = pack_bf16(h20, h21); Ph[3] = pack_bf16(h30, h31);
                Pl[0] = pack_bf16(p00 - h00, p01 - h01);
                Pl[1] = pack_bf16(p10 - h10, p11 - h11);
                Pl[2] = pack_bf16(p20 - h20, p21 - h21);
                Pl[3] = pack_bf16(p30 - h30, p31 - h31);
            }
#pragma unroll
            for (int nt = 0; nt < 16; nt++) {
                int base = (nt * 8 + (lane >> 2)) * VSTR + kt * 16 + qpair;
                uint32_t bh0 = *(const uint32_t*)&Vth[base];
                uint32_t bh1 = *(const uint32_t*)&Vth[base + 8];
                uint32_t bl0 = *(const uint32_t*)&Vtl[base];
                uint32_t bl1 = *(const uint32_t*)&Vtl[base + 8];
                mma16816(O[nt], Ph, bh0, bh1);
                mma16816(O[nt], Ph, bl0, bl1);
                mma16816(O[nt], Pl, bh0, bh1);
            }
        }
    }

    // ---- epilogue: O/l -> yh/yl bf16 split ----
    float il0 = 1.0f / l0, il1 = 1.0f / l1;
#pragma unroll
    for (int nt = 0; nt < 16; nt++) {
        int d = nt * 8 + qpair;
        size_t base0 = (size_t)(b * TT + rg0) * NE + h * HD + d;
        size_t base1 = (size_t)(b * TT + rg1) * NE + h * HD + d;
        float o00 = O[nt][0] * il0, o01 = O[nt][1] * il0;
        float o10 = O[nt][2] * il1, o11 = O[nt][3] * il1;
        float h00 = __bfloat162float(__float2bfloat16(o00));
        float h01 = __bfloat162float(__float2bfloat16(o01));
        float h10 = __bfloat162float(__float2bfloat16(o10));
        float h11 = __bfloat162float(__float2bfloat16(o11));
        *(uint32_t*)&yh[base0] = pack_bf16(h00, h01);
        *(uint32_t*)&yl[base0] = pack_bf16(o00 - h00, o01 - h01);
        *(uint32_t*)&yh[base1] = pack_bf16(h10, h11);
        *(uint32_t*)&yl[base1] = pack_bf16(o10 - h10, o11 - h11);
    }
}

// ---------------------------------------------------------------------------
extern "C" void kernel_launch(void* const* d_in, const int* in_sizes, int n_in,
                              void* d_out, int out_size) {
    const float* x  = (const float*)d_in[0];
    const float* wq = (const float*)d_in[1];
    const float* wk = (const float*)d_in[2];
    const float* wv = (const float*)d_in[3];
    const float* wo = (const float*)d_in[4];
    float* out = (float*)d_out;

    float *qp, *kp, *vp;
    cudaGetSymbolAddress((void**)&qp, g_q);
    cudaGetSymbolAddress((void**)&kp, g_k);
    cudaGetSymbolAddress((void**)&vp, g_v);

    __nv_bfloat16 *xh, *xl, *wqh, *wql, *wkh, *wkl, *wvh, *wvl, *woh, *wol, *yh, *yl;
    cudaGetSymbolAddress((void**)&xh,  g_xh);  cudaGetSymbolAddress((void**)&xl,  g_xl);
    cudaGetSymbolAddress((void**)&wqh, g_wqh); cudaGetSymbolAddress((void**)&wql, g_wql);
    cudaGetSymbolAddress((void**)&wkh, g_wkh); cudaGetSymbolAddress((void**)&wkl, g_wkl);
    cudaGetSymbolAddress((void**)&wvh, g_wvh); cudaGetSymbolAddress((void**)&wvl, g_wvl);
    cudaGetSymbolAddress((void**)&woh, g_woh); cudaGetSymbolAddress((void**)&wol, g_wol);
    cudaGetSymbolAddress((void**)&yh,  g_yh);  cudaGetSymbolAddress((void**)&yl,  g_yl);

    int nx  = MROWS * NE / 4;
    int nw  = NE * NE / 4;
    int nwk = KVE * NE / 4;
    split_bf16<<<(nx  + 255) / 256, 256>>>(x,  xh,  xl,  nx);
    split_bf16<<<(nw  + 255) / 256, 256>>>(wq, wqh, wql, nw);
    split_bf16<<<(nwk + 255) / 256, 256>>>(wk, wkh, wkl, nwk);
    split_bf16<<<(nwk + 255) / 256, 256>>>(wv, wvh, wvl, nwk);
    split_bf16<<<(nw  + 255) / 256, 256>>>(wo, woh, wol, nw);

    dim3 blk(256);
    dim3 grdQ(NE / TBN, MROWS / TBM);
    dim3 grdKV(KVE / TBN, MROWS / TBM);
    gemm_nt_bf16x3<<<grdQ, blk>>>(xh, xl, wqh, wql, qp, MROWS, NE, NE);
    gemm_nt_bf16x3<<<grdKV, blk>>>(xh, xl, wkh, wkl, kp, MROWS, KVE, NE);
    gemm_nt_bf16x3<<<grdKV, blk>>>(xh, xl, wvh, wvl, vp, MROWS, KVE, NE);

    cudaFuncSetAttribute(attn_mma, cudaFuncAttributeMaxDynamicSharedMemorySize, SM_ATT_BYTES);
    dim3 agrd(TT / BQ, BB * NH);   // (16, 32)
    attn_mma<<<agrd, blk, SM_ATT_BYTES>>>(qp, kp, vp, yh, yl);

    gemm_nt_bf16x3<<<grdQ, blk>>>(yh, yl, woh, wol, out, MROWS, NE, NE);
}

// round 5
// speedup vs baseline: 1.9767x; 1.1055x over previous
#include <cuda_runtime.h>
#include <cuda_bf16.h>
#include <math_constants.h>
#include <mma.h>
#include <cstdint>

using namespace nvcuda;

#define BB 2
#define TT 2048
#define NE 2048
#define NH 16
#define NKV 4
#define HD 128
#define GRP (NH / NKV)
#define MROWS (BB * TT)
#define KVE (NKV * HD)

// fp32 scratch
__device__ float g_q[MROWS * NE];
__device__ float g_k[MROWS * KVE];
__device__ float g_v[MROWS * KVE];

// bf16 split scratch
__device__ __nv_bfloat16 g_xh[MROWS * NE],  g_xl[MROWS * NE];
__device__ __nv_bfloat16 g_wqh[NE * NE],    g_wql[NE * NE];
__device__ __nv_bfloat16 g_wkh[KVE * NE],   g_wkl[KVE * NE];
__device__ __nv_bfloat16 g_wvh[KVE * NE],   g_wvl[KVE * NE];
__device__ __nv_bfloat16 g_woh[NE * NE],    g_wol[NE * NE];
__device__ __nv_bfloat16 g_yh[MROWS * NE],  g_yl[MROWS * NE];

__device__ __forceinline__ uint32_t pack_bf16(float x, float y) {
    __nv_bfloat162 r = __floats2bfloat162_rn(x, y);
    return *(uint32_t*)&r;
}
__device__ __forceinline__ float fast_exp2(float x) {
    float y; asm("ex2.approx.f32 %0, %1;" : "=f"(y) : "f"(x)); return y;
}
__device__ __forceinline__ void mma16816(float* c, const uint32_t* a, uint32_t b0, uint32_t b1) {
    asm volatile("mma.sync.aligned.m16n8k16.row.col.f32.bf16.bf16.f32 "
                 "{%0,%1,%2,%3}, {%4,%5,%6,%7}, {%8,%9}, {%0,%1,%2,%3};\n"
                 : "+f"(c[0]), "+f"(c[1]), "+f"(c[2]), "+f"(c[3])
                 : "r"(a[0]), "r"(a[1]), "r"(a[2]), "r"(a[3]), "r"(b0), "r"(b1));
}
__device__ __forceinline__ void cp16(__nv_bfloat16* s, const __nv_bfloat16* g) {
    uint32_t sa = (uint32_t)__cvta_generic_to_shared(s);
    asm volatile("cp.async.cg.shared.global [%0], [%1], 16;" :: "r"(sa), "l"(g));
}

// ---------------------------------------------------------------------------
// split fp32 -> bf16 hi + lo
// ---------------------------------------------------------------------------
__global__ __launch_bounds__(256) void split_bf16(const float* __restrict__ x,
                                                  __nv_bfloat16* __restrict__ hi,
                                                  __nv_bfloat16* __restrict__ lo,
                                                  int n4) {
    int i = blockIdx.x * blockDim.x + threadIdx.x;
    if (i >= n4) return;
    float4 v = ((const float4*)x)[i];
    union { __nv_bfloat16 b[4]; uint2 u; } H, L;
    float vv[4] = {v.x, v.y, v.z, v.w};
#pragma unroll
    for (int j = 0; j < 4; j++) {
        __nv_bfloat16 h = __float2bfloat16(vv[j]);
        H.b[j] = h;
        L.b[j] = __float2bfloat16(vv[j] - __bfloat162float(h));
    }
    ((uint2*)hi)[i] = H.u;
    ((uint2*)lo)[i] = L.u;
}

// ---------------------------------------------------------------------------
// cp.async double-buffered wmma NT GEMM, bf16x3.
// Block tile 128x128, K-step 32, 256 threads (8 warps 2x4), warp tile 64x32.
// blockIdx.z selects (B,C) pair -> K and V projections fuse into one launch.
// ---------------------------------------------------------------------------
#define TBM 128
#define TBN 128
#define TBK 32
#define TLD 40
#define TILE_ELEMS (TBM * TLD)   // 5120

__global__ __launch_bounds__(256) void gemm_nt_pipe(
    const __nv_bfloat16* __restrict__ Ah, const __nv_bfloat16* __restrict__ Al,
    const __nv_bfloat16* __restrict__ Bh0, const __nv_bfloat16* __restrict__ Bl0,
    float* __restrict__ C0,
    const __nv_bfloat16* __restrict__ Bh1, const __nv_bfloat16* __restrict__ Bl1,
    float* __restrict__ C1,
    int M, int N, int K)
{
    const __nv_bfloat16* Bh = blockIdx.z ? Bh1 : Bh0;
    const __nv_bfloat16* Bl = blockIdx.z ? Bl1 : Bl0;
    float* C = blockIdx.z ? C1 : C0;

    extern __shared__ __nv_bfloat16 gsm[];
    // layout: [stage][tile: Ah,Al,Bh,Bl][TILE_ELEMS]
    auto tilep = [&](int st, int which) { return gsm + (st * 4 + which) * TILE_ELEMS; };

    const int t  = threadIdx.x;
    const int w  = t >> 5;
    const int wm = w & 1;
    const int wn = w >> 1;
    const int row0 = blockIdx.y * TBM;
    const int col0 = blockIdx.x * TBN;

    wmma::fragment<wmma::accumulator, 16, 16, 16, float> acc[4][2];
#pragma unroll
    for (int i = 0; i < 4; i++)
#pragma unroll
        for (int j = 0; j < 2; j++) wmma::fill_fragment(acc[i][j], 0.0f);

    const int nk = K / TBK;

    auto load_stage = [&](int st, int kb) {
        __nv_bfloat16* tAh = tilep(st, 0);
        __nv_bfloat16* tAl = tilep(st, 1);
        __nv_bfloat16* tBh = tilep(st, 2);
        __nv_bfloat16* tBl = tilep(st, 3);
#pragma unroll
        for (int i = 0; i < 2; i++) {
            int p = t + i * 256;
            int r = p >> 2, qq = p & 3;
            size_t ga = (size_t)(row0 + r) * K + kb * TBK + qq * 8;
            size_t gb = (size_t)(col0 + r) * K + kb * TBK + qq * 8;
            int so = r * TLD + qq * 8;
            cp16(tAh + so, Ah + ga);
            cp16(tAl + so, Al + ga);
            cp16(tBh + so, Bh + gb);
            cp16(tBl + so, Bl + gb);
        }
        asm volatile("cp.async.commit_group;" ::: "memory");
    };

    load_stage(0, 0);

    for (int kb = 0; kb < nk; kb++) {
        const int cur = kb & 1;
        if (kb + 1 < nk) {
            load_stage(cur ^ 1, kb + 1);
            asm volatile("cp.async.wait_group 1;" ::: "memory");
        } else {
            asm volatile("cp.async.wait_group 0;" ::: "memory");
        }
        __syncthreads();

        const __nv_bfloat16* tAh = tilep(cur, 0);
        const __nv_bfloat16* tAl = tilep(cur, 1);
        const __nv_bfloat16* tBh = tilep(cur, 2);
        const __nv_bfloat16* tBl = tilep(cur, 3);

#pragma unroll
        for (int kk = 0; kk < TBK; kk += 16) {
            wmma::fragment<wmma::matrix_a, 16, 16, 16, __nv_bfloat16, wmma::row_major> ah[4], al[4];
            wmma::fragment<wmma::matrix_b, 16, 16, 16, __nv_bfloat16, wmma::col_major> bh[2], bl[2];
#pragma unroll
            for (int i = 0; i < 4; i++) {
                wmma::load_matrix_sync(ah[i], tAh + (wm * 64 + i * 16) * TLD + kk, TLD);
                wmma::load_matrix_sync(al[i], tAl + (wm * 64 + i * 16) * TLD + kk, TLD);
            }
#pragma unroll
            for (int j = 0; j < 2; j++) {
                wmma::load_matrix_sync(bh[j], tBh + (wn * 32 + j * 16) * TLD + kk, TLD);
                wmma::load_matrix_sync(bl[j], tBl + (wn * 32 + j * 16) * TLD + kk, TLD);
            }
#pragma unroll
            for (int i = 0; i < 4; i++)
#pragma unroll
                for (int j = 0; j < 2; j++) {
                    wmma::mma_sync(acc[i][j], ah[i], bh[j], acc[i][j]);
                    wmma::mma_sync(acc[i][j], ah[i], bl[j], acc[i][j]);
                    wmma::mma_sync(acc[i][j], al[i], bh[j], acc[i][j]);
                }
        }
        __syncthreads();
    }

#pragma unroll
    for (int i = 0; i < 4; i++)
#pragma unroll
        for (int j = 0; j < 2; j++)
            wmma::store_matrix_sync(
                &C[(size_t)(row0 + wm * 64 + i * 16) * N + col0 + wn * 32 + j * 16],
                acc[i][j], N, wmma::mem_row_major);
}

#define GEMM_SMEM (8 * TILE_ELEMS * 2)  // 81920 bytes

// ---------------------------------------------------------------------------
// FA2-style tensor-core causal GQA attention (unchanged from R4).
// ---------------------------------------------------------------------------
#define BQ 128
#define BKV 64
#define KSTR 136
#define VSTR 72
#define SM_ATT_BYTES ((2 * BKV * KSTR + 2 * HD * VSTR) * 2)

__global__ __launch_bounds__(256, 1) void attn_mma(const float* __restrict__ q,
                                                   const float* __restrict__ k,
                                                   const float* __restrict__ v,
                                                   __nv_bfloat16* __restrict__ yh,
                                                   __nv_bfloat16* __restrict__ yl) {
    extern __shared__ __nv_bfloat16 smA[];
    __nv_bfloat16* Ksh = smA;
    __nv_bfloat16* Ksl = Ksh + BKV * KSTR;
    __nv_bfloat16* Vth = Ksl + BKV * KSTR;
    __nv_bfloat16* Vtl = Vth + HD * VSTR;

    const int t    = threadIdx.x;
    const int w    = t >> 5;
    const int lane = t & 31;
    const int qb   = (gridDim.x - 1) - blockIdx.x;
    const int bh   = blockIdx.y;
    const int b    = bh >> 4;
    const int h    = bh & 15;
    const int hk   = h / GRP;
    const int q0   = qb * BQ;
    const int rg0  = q0 + w * 16 + (lane >> 2);
    const int rg1  = rg0 + 8;
    const int qpair = (lane & 3) * 2;

    const float qscale = 0.08838834764831845f * 1.4426950408889634f;
    uint32_t Qh[8][4], Ql[8][4];
#pragma unroll
    for (int kt = 0; kt < 8; kt++) {
#pragma unroll
        for (int half = 0; half < 2; half++) {
#pragma unroll
            for (int ri = 0; ri < 2; ri++) {
                int row = ri ? rg1 : rg0;
                int d = kt * 16 + half * 8 + qpair;
                float2 f = *(const float2*)(q + ((size_t)(b * TT + row) * NH + h) * HD + d);
                f.x *= qscale; f.y *= qscale;
                float hx = __bfloat162float(__float2bfloat16(f.x));
                float hy = __bfloat162float(__float2bfloat16(f.y));
                Qh[kt][half * 2 + ri] = pack_bf16(hx, hy);
                Ql[kt][half * 2 + ri] = pack_bf16(f.x - hx, f.y - hy);
            }
        }
    }

    float O[16][4];
#pragma unroll
    for (int nt = 0; nt < 16; nt++)
#pragma unroll
        for (int e = 0; e < 4; e++) O[nt][e] = 0.0f;
    float m0 = -CUDART_INF_F, m1 = -CUDART_INF_F, l0 = 0.0f, l1 = 0.0f;

    const int kb_end = 2 * qb + 2;
    for (int kb = 0; kb < kb_end; kb++) {
        const int k0 = kb * BKV;
        __syncthreads();
#pragma unroll
        for (int i = 0; i < 8; i++) {
            int f4 = t + i * 256;
            int c  = f4 >> 5;
            int d4 = f4 & 31;
            size_t g = ((size_t)(b * TT + k0 + c) * NKV + hk) * HD + d4 * 4;
            float4 kk = *(const float4*)(k + g);
            float kf[4] = {kk.x, kk.y, kk.z, kk.w};
            float khf[4];
#pragma unroll
            for (int j = 0; j < 4; j++) khf[j] = __bfloat162float(__float2bfloat16(kf[j]));
            *(__nv_bfloat162*)&Ksh[c * KSTR + d4 * 4]     = __floats2bfloat162_rn(khf[0], khf[1]);
            *(__nv_bfloat162*)&Ksh[c * KSTR + d4 * 4 + 2] = __floats2bfloat162_rn(khf[2], khf[3]);
            *(__nv_bfloat162*)&Ksl[c * KSTR + d4 * 4]     = __floats2bfloat162_rn(kf[0] - khf[0], kf[1] - khf[1]);
            *(__nv_bfloat162*)&Ksl[c * KSTR + d4 * 4 + 2] = __floats2bfloat162_rn(kf[2] - khf[2], kf[3] - khf[3]);

            float4 vv = *(const float4*)(v + g);
            float vf[4] = {vv.x, vv.y, vv.z, vv.w};
#pragma unroll
            for (int j = 0; j < 4; j++) {
                float vh = __bfloat162float(__float2bfloat16(vf[j]));
                Vth[(d4 * 4 + j) * VSTR + c] = __float2bfloat16(vh);
                Vtl[(d4 * 4 + j) * VSTR + c] = __float2bfloat16(vf[j] - vh);
            }
        }
        __syncthreads();

        float S[8][4];
#pragma unroll
        for (int jt = 0; jt < 8; jt++)
#pragma unroll
            for (int e = 0; e < 4; e++) S[jt][e] = 0.0f;

#pragma unroll
        for (int kt = 0; kt < 8; kt++) {
#pragma unroll
            for (int jt = 0; jt < 8; jt++) {
                int base = (jt * 8 + (lane >> 2)) * KSTR + kt * 16 + qpair;
                uint32_t bh0 = *(const uint32_t*)&Ksh[base];
                uint32_t bh1 = *(const uint32_t*)&Ksh[base + 8];
                uint32_t bl0 = *(const uint32_t*)&Ksl[base];
                uint32_t bl1 = *(const uint32_t*)&Ksl[base + 8];
                mma16816(S[jt], Qh[kt], bh0, bh1);
                mma16816(S[jt], Qh[kt], bl0, bl1);
                mma16816(S[jt], Ql[kt], bh0, bh1);
            }
        }

        if (kb >= 2 * qb) {
#pragma unroll
            for (int jt = 0; jt < 8; jt++) {
                int c0 = k0 + jt * 8 + qpair;
                if (c0 > rg0)     S[jt][0] = -CUDART_INF_F;
                if (c0 + 1 > rg0) S[jt][1] = -CUDART_INF_F;
                if (c0 > rg1)     S[jt][2] = -CUDART_INF_F;
                if (c0 + 1 > rg1) S[jt][3] = -CUDART_INF_F;
            }
        }

        float mx0 = -CUDART_INF_F, mx1 = -CUDART_INF_F;
#pragma unroll
        for (int jt = 0; jt < 8; jt++) {
            mx0 = fmaxf(mx0, fmaxf(S[jt][0], S[jt][1]));
            mx1 = fmaxf(mx1, fmaxf(S[jt][2], S[jt][3]));
        }
#pragma unroll
        for (int off = 1; off <= 2; off <<= 1) {
            mx0 = fmaxf(mx0, __shfl_xor_sync(0xffffffffu, mx0, off));
            mx1 = fmaxf(mx1, __shfl_xor_sync(0xffffffffu, mx1, off));
        }
        float mn0 = fmaxf(m0, mx0), mn1 = fmaxf(m1, mx1);
        float al0 = fast_exp2(m0 - mn0), al1 = fast_exp2(m1 - mn1);
        float s0 = 0.0f, s1 = 0.0f;
#pragma unroll
        for (int jt = 0; jt < 8; jt++) {
            S[jt][0] = fast_exp2(S[jt][0] - mn0); s0 += S[jt][0];
            S[jt][1] = fast_exp2(S[jt][1] - mn0); s0 += S[jt][1];
            S[jt][2] = fast_exp2(S[jt][2] - mn1); s1 += S[jt][2];
            S[jt][3] = fast_exp2(S[jt][3] - mn1); s1 += S[jt][3];
        }
#pragma unroll
        for (int off = 1; off <= 2; off <<= 1) {
            s0 += __shfl_xor_sync(0xffffffffu, s0, off);
            s1 += __shfl_xor_sync(0xffffffffu, s1, off);
        }
        l0 = l0 * al0 + s0; l1 = l1 * al1 + s1;
        m0 = mn0; m1 = mn1;
#pragma unroll
        for (int nt = 0; nt < 16; nt++) {
            O[nt][0] *= al0; O[nt][1] *= al0;
            O[nt][2] *= al1; O[nt][3] *= al1;
        }

#pragma unroll
        for (int kt = 0; kt < 4; kt++) {
            uint32_t Ph[4], Pl[4];
            {
                float p00 = S[2 * kt][0],     p01 = S[2 * kt][1];
                float p10 = S[2 * kt][2],     p11 = S[2 * kt][3];
                float p20 = S[2 * kt + 1][0], p21 = S[2 * kt + 1][1];
                float p30 = S[2 * kt + 1][2], p31 = S[2 * kt + 1][3];
                float h00 = __bfloat162float(__float2bfloat16(p00));
                float h01 = __bfloat162float(__float2bfloat16(p01));
                float h10 = __bfloat162float(__float2bfloat16(p10));
                float h11 = __bfloat162float(__float2bfloat16(p11));
                float h20 = __bfloat162float(__float2bfloat16(p20));
                float h21 = __bfloat162float(__float2bfloat16(p21));
                float h30 = __bfloat162float(__float2bfloat16(p30));
                float h31 = __bfloat162float(__float2bfloat16(p31));
                Ph[0] = pack_bf16(h00, h01); Ph[1] = pack_bf16(h10, h11);
                Ph[2] = pack_bf16(h20, h21); Ph[3] = pack_bf16(h30, h31);
                Pl[0] = pack_bf16(p00 - h00, p01 - h01);
                Pl[1] = pack_bf16(p10 - h10, p11 - h11);
                Pl[2] = pack_bf16(p20 - h20, p21 - h21);
                Pl[3] = pack_bf16(p30 - h30, p31 - h31);
            }
#pragma unroll
            for (int nt = 0; nt < 16; nt++) {
                int base = (nt * 8 + (lane >> 2)) * VSTR + kt * 16 + qpair;
                uint32_t bh0 = *(const uint32_t*)&Vth[base];
                uint32_t bh1 = *(const uint32_t*)&Vth[base + 8];
                uint32_t bl0 = *(const uint32_t*)&Vtl[base];
                uint32_t bl1 = *(const uint32_t*)&Vtl[base + 8];
                mma16816(O[nt], Ph, bh0, bh1);
                mma16816(O[nt], Ph, bl0, bl1);
                mma16816(O[nt], Pl, bh0, bh1);
            }
        }
    }

    float il0 = 1.0f / l0, il1 = 1.0f / l1;
#pragma unroll
    for (int nt = 0; nt < 16; nt++) {
        int d = nt * 8 + qpair;
        size_t base0 = (size_t)(b * TT + rg0) * NE + h * HD + d;
        size_t base1 = (size_t)(b * TT + rg1) * NE + h * HD + d;
        float o00 = O[nt][0] * il0, o01 = O[nt][1] * il0;
        float o10 = O[nt][2] * il1, o11 = O[nt][3] * il1;
        float h00 = __bfloat162float(__float2bfloat16(o00));
        float h01 = __bfloat162float(__float2bfloat16(o01));
        float h10 = __bfloat162float(__float2bfloat16(o10));
        float h11 = __bfloat162float(__float2bfloat16(o11));
        *(uint32_t*)&yh[base0] = pack_bf16(h00, h01);
        *(uint32_t*)&yl[base0] = pack_bf16(o00 - h00, o01 - h01);
        *(uint32_t*)&yh[base1] = pack_bf16(h10, h11);
        *(uint32_t*)&yl[base1] = pack_bf16(o10 - h10, o11 - h11);
    }
}

// ---------------------------------------------------------------------------
extern "C" void kernel_launch(void* const* d_in, const int* in_sizes, int n_in,
                              void* d_out, int out_size) {
    const float* x  = (const float*)d_in[0];
    const float* wq = (const float*)d_in[1];
    const float* wk = (const float*)d_in[2];
    const float* wv = (const float*)d_in[3];
    const float* wo = (const float*)d_in[4];
    float* out = (float*)d_out;

    float *qp, *kp, *vp;
    cudaGetSymbolAddress((void**)&qp, g_q);
    cudaGetSymbolAddress((void**)&kp, g_k);
    cudaGetSymbolAddress((void**)&vp, g_v);

    __nv_bfloat16 *xh, *xl, *wqh, *wql, *wkh, *wkl, *wvh, *wvl, *woh, *wol, *yh, *yl;
    cudaGetSymbolAddress((void**)&xh,  g_xh);  cudaGetSymbolAddress((void**)&xl,  g_xl);
    cudaGetSymbolAddress((void**)&wqh, g_wqh); cudaGetSymbolAddress((void**)&wql, g_wql);
    cudaGetSymbolAddress((void**)&wkh, g_wkh); cudaGetSymbolAddress((void**)&wkl, g_wkl);
    cudaGetSymbolAddress((void**)&wvh, g_wvh); cudaGetSymbolAddress((void**)&wvl, g_wvl);
    cudaGetSymbolAddress((void**)&woh, g_woh); cudaGetSymbolAddress((void**)&wol, g_wol);
    cudaGetSymbolAddress((void**)&yh,  g_yh);  cudaGetSymbolAddress((void**)&yl,  g_yl);

    int nx  = MROWS * NE / 4;
    int nw  = NE * NE / 4;
    int nwk = KVE * NE / 4;
    split_bf16<<<(nx  + 255) / 256, 256>>>(x,  xh,  xl,  nx);
    split_bf16<<<(nw  + 255) / 256, 256>>>(wq, wqh, wql, nw);
    split_bf16<<<(nwk + 255) / 256, 256>>>(wk, wkh, wkl, nwk);
    split_bf16<<<(nwk + 255) / 256, 256>>>(wv, wvh, wvl, nwk);
    split_bf16<<<(nw  + 255) / 256, 256>>>(wo, woh, wol, nw);

    cudaFuncSetAttribute(gemm_nt_pipe, cudaFuncAttributeMaxDynamicSharedMemorySize, GEMM_SMEM);

    dim3 blk(256);
    dim3 grdQ(NE / TBN, MROWS / TBM, 1);    // (16, 32, 1)
    dim3 grdKV(KVE / TBN, MROWS / TBM, 2);  // (4, 32, 2) fused K+V

    gemm_nt_pipe<<<grdQ, blk, GEMM_SMEM>>>(xh, xl, wqh, wql, qp, wqh, wql, qp, MROWS, NE, NE);
    gemm_nt_pipe<<<grdKV, blk, GEMM_SMEM>>>(xh, xl, wkh, wkl, kp, wvh, wvl, vp, MROWS, KVE, NE);

    cudaFuncSetAttribute(attn_mma, cudaFuncAttributeMaxDynamicSharedMemorySize, SM_ATT_BYTES);
    dim3 agrd(TT / BQ, BB * NH);
    attn_mma<<<agrd, blk, SM_ATT_BYTES>>>(qp, kp, vp, yh, yl);

    gemm_nt_pipe<<<grdQ, blk, GEMM_SMEM>>>(yh, yl, woh, wol, out, woh, wol, out, MROWS, NE, NE);
}

// round 7
// speedup vs baseline: 2.2824x; 1.1547x over previous
#include <cuda_runtime.h>
#include <cuda_bf16.h>
#include <math_constants.h>
#include <mma.h>
#include <cstdint>

using namespace nvcuda;

#define BB 2
#define TT 2048
#define NE 2048
#define NH 16
#define NKV 4
#define HD 128
#define GRP (NH / NKV)
#define MROWS (BB * TT)
#define KVE (NKV * HD)

// bf16 split scratch
__device__ __nv_bfloat16 g_xh[MROWS * NE],  g_xl[MROWS * NE];
__device__ __nv_bfloat16 g_wqh[NE * NE],    g_wql[NE * NE];
__device__ __nv_bfloat16 g_wkh[KVE * NE],   g_wkl[KVE * NE];
__device__ __nv_bfloat16 g_wvh[KVE * NE],   g_wvl[KVE * NE];
__device__ __nv_bfloat16 g_woh[NE * NE],    g_wol[NE * NE];
__device__ __nv_bfloat16 g_yh[MROWS * NE],  g_yl[MROWS * NE];
// pre-split activations
__device__ __nv_bfloat16 g_qh[MROWS * NE],  g_ql[MROWS * NE];     // (B,T,H,D)
__device__ __nv_bfloat16 g_kh[MROWS * KVE], g_kl[MROWS * KVE];    // (B,T,Hkv,D)
__device__ __nv_bfloat16 g_vth[MROWS * KVE], g_vtl[MROWS * KVE];  // (B,Hkv,D,T)

__device__ __forceinline__ uint32_t pack_bf16(float x, float y) {
    __nv_bfloat162 r = __floats2bfloat162_rn(x, y);
    return *(uint32_t*)&r;
}
__device__ __forceinline__ float fast_exp2(float x) {
    float y; asm("ex2.approx.f32 %0, %1;" : "=f"(y) : "f"(x)); return y;
}
__device__ __forceinline__ void mma16816(float* c, const uint32_t* a, uint32_t b0, uint32_t b1) {
    asm volatile("mma.sync.aligned.m16n8k16.row.col.f32.bf16.bf16.f32 "
                 "{%0,%1,%2,%3}, {%4,%5,%6,%7}, {%8,%9}, {%0,%1,%2,%3};\n"
                 : "+f"(c[0]), "+f"(c[1]), "+f"(c[2]), "+f"(c[3])
                 : "r"(a[0]), "r"(a[1]), "r"(a[2]), "r"(a[3]), "r"(b0), "r"(b1));
}
__device__ __forceinline__ void cp16(__nv_bfloat16* s, const __nv_bfloat16* g) {
    uint32_t sa = (uint32_t)__cvta_generic_to_shared(s);
    asm volatile("cp.async.cg.shared.global [%0], [%1], 16;" :: "r"(sa), "l"(g));
}

// ---------------------------------------------------------------------------
// split fp32 -> bf16 hi + lo
// ---------------------------------------------------------------------------
__global__ __launch_bounds__(256) void split_bf16(const float* __restrict__ x,
                                                  __nv_bfloat16* __restrict__ hi,
                                                  __nv_bfloat16* __restrict__ lo,
                                                  int n4) {
    int i = blockIdx.x * blockDim.x + threadIdx.x;
    if (i >= n4) return;
    float4 v = ((const float4*)x)[i];
    union { __nv_bfloat16 b[4]; uint2 u; } H, L;
    float vv[4] = {v.x, v.y, v.z, v.w};
#pragma unroll
    for (int j = 0; j < 4; j++) {
        __nv_bfloat16 h = __float2bfloat16(vv[j]);
        H.b[j] = h;
        L.b[j] = __float2bfloat16(vv[j] - __bfloat162float(h));
    }
    ((uint2*)hi)[i] = H.u;
    ((uint2*)lo)[i] = L.u;
}

// ---------------------------------------------------------------------------
// 3-stage cp.async wmma NT GEMM, bf16x3.
// Block tile 128x128, K-step 32, 256 threads (8 warps 2x4), warp tile 64x32.
// blockIdx.z selects per-output mode:
//   mode 0: fp32 C (row-major M x N)
//   mode 1: bf16 hi/lo split C (row-major)
//   mode 2: bf16 hi/lo split, transposed V layout (B,Hkv,D,T)
// ---------------------------------------------------------------------------
#define TBM 128
#define TBN 128
#define TBK 32
#define TLD 40
#define TILE_ELEMS (TBM * TLD)   // 5120 bf16
#define NSTAGE 3
#define SEPI 132                 // fp32 epilogue smem stride
#define GEMM_SMEM (NSTAGE * 4 * TILE_ELEMS * 2)  // 122880 B? (3*4*5120*2=122880)

__global__ __launch_bounds__(256, 1) void gemm_nt_pipe(
    const __nv_bfloat16* __restrict__ Ah, const __nv_bfloat16* __restrict__ Al,
    const __nv_bfloat16* __restrict__ Bh0, const __nv_bfloat16* __restrict__ Bl0,
    int mode0, float* __restrict__ Cf0,
    __nv_bfloat16* __restrict__ Ch0, __nv_bfloat16* __restrict__ Cl0,
    const __nv_bfloat16* __restrict__ Bh1, const __nv_bfloat16* __restrict__ Bl1,
    int mode1, float* __restrict__ Cf1,
    __nv_bfloat16* __restrict__ Ch1, __nv_bfloat16* __restrict__ Cl1,
    int M, int N, int K)
{
    const __nv_bfloat16* Bh = blockIdx.z ? Bh1 : Bh0;
    const __nv_bfloat16* Bl = blockIdx.z ? Bl1 : Bl0;
    const int mode = blockIdx.z ? mode1 : mode0;
    float* Cf = blockIdx.z ? Cf1 : Cf0;
    __nv_bfloat16* Ch = blockIdx.z ? Ch1 : Ch0;
    __nv_bfloat16* Cl = blockIdx.z ? Cl1 : Cl0;

    extern __shared__ __nv_bfloat16 gsm[];
    auto tilep = [&](int st, int which) { return gsm + (st * 4 + which) * TILE_ELEMS; };

    const int t  = threadIdx.x;
    const int w  = t >> 5;
    const int wm = w & 1;
    const int wn = w >> 1;
    const int row0 = blockIdx.y * TBM;
    const int col0 = blockIdx.x * TBN;

    wmma::fragment<wmma::accumulator, 16, 16, 16, float> acc[4][2];
#pragma unroll
    for (int i = 0; i < 4; i++)
#pragma unroll
        for (int j = 0; j < 2; j++) wmma::fill_fragment(acc[i][j], 0.0f);

    const int nk = K / TBK;

    auto load_stage = [&](int st, int kb) {
        __nv_bfloat16* tAh = tilep(st, 0);
        __nv_bfloat16* tAl = tilep(st, 1);
        __nv_bfloat16* tBh = tilep(st, 2);
        __nv_bfloat16* tBl = tilep(st, 3);
#pragma unroll
        for (int i = 0; i < 2; i++) {
            int p = t + i * 256;
            int r = p >> 2, qq = p & 3;
            size_t ga = (size_t)(row0 + r) * K + kb * TBK + qq * 8;
            size_t gb = (size_t)(col0 + r) * K + kb * TBK + qq * 8;
            int so = r * TLD + qq * 8;
            cp16(tAh + so, Ah + ga);
            cp16(tAl + so, Al + ga);
            cp16(tBh + so, Bh + gb);
            cp16(tBl + so, Bl + gb);
        }
        asm volatile("cp.async.commit_group;" ::: "memory");
    };

    load_stage(0, 0);
    load_stage(1, 1);

    for (int kb = 0; kb < nk; kb++) {
        const int cur = kb % NSTAGE;
        if (kb + 2 < nk) {
            load_stage((kb + 2) % NSTAGE, kb + 2);
            asm volatile("cp.async.wait_group 2;" ::: "memory");
        } else if (kb + 1 < nk) {
            asm volatile("cp.async.wait_group 1;" ::: "memory");
        } else {
            asm volatile("cp.async.wait_group 0;" ::: "memory");
        }
        __syncthreads();

        const __nv_bfloat16* tAh = tilep(cur, 0);
        const __nv_bfloat16* tAl = tilep(cur, 1);
        const __nv_bfloat16* tBh = tilep(cur, 2);
        const __nv_bfloat16* tBl = tilep(cur, 3);

#pragma unroll
        for (int kk = 0; kk < TBK; kk += 16) {
            wmma::fragment<wmma::matrix_a, 16, 16, 16, __nv_bfloat16, wmma::row_major> ah[4], al[4];
            wmma::fragment<wmma::matrix_b, 16, 16, 16, __nv_bfloat16, wmma::col_major> bh[2], bl[2];
#pragma unroll
            for (int i = 0; i < 4; i++) {
                wmma::load_matrix_sync(ah[i], tAh + (wm * 64 + i * 16) * TLD + kk, TLD);
                wmma::load_matrix_sync(al[i], tAl + (wm * 64 + i * 16) * TLD + kk, TLD);
            }
#pragma unroll
            for (int j = 0; j < 2; j++) {
                wmma::load_matrix_sync(bh[j], tBh + (wn * 32 + j * 16) * TLD + kk, TLD);
                wmma::load_matrix_sync(bl[j], tBl + (wn * 32 + j * 16) * TLD + kk, TLD);
            }
#pragma unroll
            for (int i = 0; i < 4; i++)
#pragma unroll
                for (int j = 0; j < 2; j++) {
                    wmma::mma_sync(acc[i][j], ah[i], bh[j], acc[i][j]);
                    wmma::mma_sync(acc[i][j], ah[i], bl[j], acc[i][j]);
                    wmma::mma_sync(acc[i][j], al[i], bh[j], acc[i][j]);
                }
        }
        __syncthreads();
    }

    // Epilogue: stage through smem fp32, then write per mode
    float* smf = (float*)gsm;
#pragma unroll
    for (int i = 0; i < 4; i++)
#pragma unroll
        for (int j = 0; j < 2; j++)
            wmma::store_matrix_sync(&smf[(wm * 64 + i * 16) * SEPI + wn * 32 + j * 16],
                                    acc[i][j], SEPI, wmma::mem_row_major);
    __syncthreads();

    if (mode == 0) {
#pragma unroll
        for (int i = 0; i < 32; i++) {
            int p = t + i * 256;          // 8192 float2
            int r = p >> 6, c2 = (p & 63) * 2;
            float2 v = *(float2*)&smf[r * SEPI + c2];
            *(float2*)&Cf[(size_t)(row0 + r) * N + col0 + c2] = v;
        }
    } else if (mode == 1) {
#pragma unroll
        for (int i = 0; i < 32; i++) {
            int p = t + i * 256;
            int r = p >> 6, c2 = (p & 63) * 2;
            float x0 = smf[r * SEPI + c2], x1 = smf[r * SEPI + c2 + 1];
            float h0 = __bfloat162float(__float2bfloat16(x0));
            float h1 = __bfloat162float(__float2bfloat16(x1));
            size_t gidx = (size_t)(row0 + r) * N + col0 + c2;
            *(uint32_t*)&Ch[gidx] = pack_bf16(h0, h1);
            *(uint32_t*)&Cl[gidx] = pack_bf16(x0 - h0, x1 - h1);
        }
    } else {
        // mode 2: V transposed (B,Hkv,D,T). col0 block -> hk, c -> d; row -> (b,t)
        const int b  = row0 >> 11;           // row0 / 2048
        const int t0 = row0 & 2047;
        const int hk = col0 >> 7;
#pragma unroll
        for (int i = 0; i < 32; i++) {
            int p = t + i * 256;             // 8192 r-pairs
            int c = p >> 6, rp = (p & 63) * 2;
            float x0 = smf[rp * SEPI + c], x1 = smf[(rp + 1) * SEPI + c];
            float h0 = __bfloat162float(__float2bfloat16(x0));
            float h1 = __bfloat162float(__float2bfloat16(x1));
            size_t gidx = ((size_t)(b * NKV + hk) * HD + c) * TT + t0 + rp;
            *(uint32_t*)&Ch[gidx] = pack_bf16(h0, h1);
            *(uint32_t*)&Cl[gidx] = pack_bf16(x0 - h0, x1 - h1);
        }
    }
}

// ---------------------------------------------------------------------------
// FA2-style mma.sync causal GQA attention, pre-split bf16 inputs,
// double-buffered cp.async K/V tile loads.
// CTA: 128 Q rows, 8 warps. KV tile 64, D=128.
// ---------------------------------------------------------------------------
#define BQ 128
#define BKV 64
#define KSTR 136
#define VSTR 72
#define KTILE (BKV * KSTR)     // 8704
#define VTILE (HD * VSTR)      // 9216
#define ASTAGE (2 * KTILE + 2 * VTILE)  // 35840 bf16
#define SM_ATT_BYTES (2 * ASTAGE * 2)   // 143360 B

__global__ __launch_bounds__(256, 1) void attn_mma(
    const __nv_bfloat16* __restrict__ qh, const __nv_bfloat16* __restrict__ ql,
    const __nv_bfloat16* __restrict__ kh, const __nv_bfloat16* __restrict__ kl,
    const __nv_bfloat16* __restrict__ vth, const __nv_bfloat16* __restrict__ vtl,
    __nv_bfloat16* __restrict__ yh, __nv_bfloat16* __restrict__ yl) {
    extern __shared__ __nv_bfloat16 smA[];

    const int t    = threadIdx.x;
    const int w    = t >> 5;
    const int lane = t & 31;
    const int qb   = (gridDim.x - 1) - blockIdx.x;   // heavy CTAs first
    const int bh   = blockIdx.y;
    const int b    = bh >> 4;
    const int h    = bh & 15;
    const int hk   = h / GRP;
    const int q0   = qb * BQ;
    const int rg0  = q0 + w * 16 + (lane >> 2);
    const int rg1  = rg0 + 8;
    const int qpair = (lane & 3) * 2;

    // ---- Q fragments from pre-split qh/ql ----
    uint32_t Qh[8][4], Ql[8][4];
#pragma unroll
    for (int kt = 0; kt < 8; kt++) {
#pragma unroll
        for (int half = 0; half < 2; half++) {
#pragma unroll
            for (int ri = 0; ri < 2; ri++) {
                int row = ri ? rg1 : rg0;
                size_t gi = ((size_t)(b * TT + row) * NH + h) * HD + kt * 16 + half * 8 + qpair;
                Qh[kt][half * 2 + ri] = *(const uint32_t*)&qh[gi];
                Ql[kt][half * 2 + ri] = *(const uint32_t*)&ql[gi];
            }
        }
    }

    float O[16][4];
#pragma unroll
    for (int nt = 0; nt < 16; nt++)
#pragma unroll
        for (int e = 0; e < 4; e++) O[nt][e] = 0.0f;
    float m0 = -CUDART_INF_F, m1 = -CUDART_INF_F, l0 = 0.0f, l1 = 0.0f;

    const float SCL = 0.08838834764831845f * 1.4426950408889634f;
    const int kb_end = 2 * qb + 2;

    auto fill = [&](int st, int kb) {
        __nv_bfloat16* Ksh = smA + st * ASTAGE;
        __nv_bfloat16* Ksl = Ksh + KTILE;
        __nv_bfloat16* Vsh = Ksl + KTILE;
        __nv_bfloat16* Vsl = Vsh + VTILE;
        const int k0 = kb * BKV;
        // K: 64 rows x 128 d, 16 chunks/row -> 1024 chunks
#pragma unroll
        for (int i = 0; i < 4; i++) {
            int p = t + i * 256;
            int c = p >> 4, ch = p & 15;
            size_t g = ((size_t)(b * TT + k0 + c) * NKV + hk) * HD + ch * 8;
            cp16(Ksh + c * KSTR + ch * 8, kh + g);
            cp16(Ksl + c * KSTR + ch * 8, kl + g);
        }
        // V^T: 128 rows (d) x 64 t, 8 chunks/row -> 1024 chunks
#pragma unroll
        for (int i = 0; i < 4; i++) {
            int p = t + i * 256;
            int d = p >> 3, ch = p & 7;
            size_t g = ((size_t)(b * NKV + hk) * HD + d) * TT + k0 + ch * 8;
            cp16(Vsh + d * VSTR + ch * 8, vth + g);
            cp16(Vsl + d * VSTR + ch * 8, vtl + g);
        }
        asm volatile("cp.async.commit_group;" ::: "memory");
    };

    fill(0, 0);

    for (int kb = 0; kb < kb_end; kb++) {
        const int cur = kb & 1;
        const int k0 = kb * BKV;
        if (kb + 1 < kb_end) {
            fill(cur ^ 1, kb + 1);
            asm volatile("cp.async.wait_group 1;" ::: "memory");
        } else {
            asm volatile("cp.async.wait_group 0;" ::: "memory");
        }
        __syncthreads();

        const __nv_bfloat16* Ksh = smA + cur * ASTAGE;
        const __nv_bfloat16* Ksl = Ksh + KTILE;
        const __nv_bfloat16* Vsh = Ksl + KTILE;
        const __nv_bfloat16* Vsl = Vsh + VTILE;

        // ---- S = Q K^T ----
        float S[8][4];
#pragma unroll
        for (int jt = 0; jt < 8; jt++)
#pragma unroll
            for (int e = 0; e < 4; e++) S[jt][e] = 0.0f;

#pragma unroll
        for (int kt = 0; kt < 8; kt++) {
#pragma unroll
            for (int jt = 0; jt < 8; jt++) {
                int base = (jt * 8 + (lane >> 2)) * KSTR + kt * 16 + qpair;
                uint32_t bh0 = *(const uint32_t*)&Ksh[base];
                uint32_t bh1 = *(const uint32_t*)&Ksh[base + 8];
                uint32_t bl0 = *(const uint32_t*)&Ksl[base];
                uint32_t bl1 = *(const uint32_t*)&Ksl[base + 8];
                mma16816(S[jt], Qh[kt], bh0, bh1);
                mma16816(S[jt], Qh[kt], bl0, bl1);
                mma16816(S[jt], Ql[kt], bh0, bh1);
            }
        }

        // ---- scale + causal mask ----
        const bool diag = (kb >= 2 * qb);
#pragma unroll
        for (int jt = 0; jt < 8; jt++) {
            int c0 = k0 + jt * 8 + qpair;
            S[jt][0] *= SCL; S[jt][1] *= SCL; S[jt][2] *= SCL; S[jt][3] *= SCL;
            if (diag) {
                if (c0 > rg0)     S[jt][0] = -CUDART_INF_F;
                if (c0 + 1 > rg0) S[jt][1] = -CUDART_INF_F;
                if (c0 > rg1)     S[jt][2] = -CUDART_INF_F;
                if (c0 + 1 > rg1) S[jt][3] = -CUDART_INF_F;
            }
        }

        // ---- online softmax (base-2) ----
        float mx0 = -CUDART_INF_F, mx1 = -CUDART_INF_F;
#pragma unroll
        for (int jt = 0; jt < 8; jt++) {
            mx0 = fmaxf(mx0, fmaxf(S[jt][0], S[jt][1]));
            mx1 = fmaxf(mx1, fmaxf(S[jt][2], S[jt][3]));
        }
#pragma unroll
        for (int off = 1; off <= 2; off <<= 1) {
            mx0 = fmaxf(mx0, __shfl_xor_sync(0xffffffffu, mx0, off));
            mx1 = fmaxf(mx1, __shfl_xor_sync(0xffffffffu, mx1, off));
        }
        float mn0 = fmaxf(m0, mx0), mn1 = fmaxf(m1, mx1);
        float al0 = fast_exp2(m0 - mn0), al1 = fast_exp2(m1 - mn1);
        float s0 = 0.0f, s1 = 0.0f;
#pragma unroll
        for (int jt = 0; jt < 8; jt++) {
            S[jt][0] = fast_exp2(S[jt][0] - mn0); s0 += S[jt][0];
            S[jt][1] = fast_exp2(S[jt][1] - mn0); s0 += S[jt][1];
            S[jt][2] = fast_exp2(S[jt][2] - mn1); s1 += S[jt][2];
            S[jt][3] = fast_exp2(S[jt][3] - mn1); s1 += S[jt][3];
        }
#pragma unroll
        for (int off = 1; off <= 2; off <<= 1) {
            s0 += __shfl_xor_sync(0xffffffffu, s0, off);
            s1 += __shfl_xor_sync(0xffffffffu, s1, off);
        }
        l0 = l0 * al0 + s0; l1 = l1 * al1 + s1;
        m0 = mn0; m1 = mn1;
#pragma unroll
        for (int nt = 0; nt < 16; nt++) {
            O[nt][0] *= al0; O[nt][1] *= al0;
            O[nt][2] *= al1; O[nt][3] *= al1;
        }

        // ---- O += P V ----
#pragma unroll
        for (int kt = 0; kt < 4; kt++) {
            uint32_t Ph[4], Pl[4];
            {
                float p00 = S[2 * kt][0],     p01 = S[2 * kt][1];
                float p10 = S[2 * kt][2],     p11 = S[2 * kt][3];
                float p20 = S[2 * kt + 1][0], p21 = S[2 * kt + 1][1];
                float p30 = S[2 * kt + 1][2], p31 = S[2 * kt + 1][3];
                float h00 = __bfloat162float(__float2bfloat16(p00));
                float h01 = __bfloat162float(__float2bfloat16(p01));
                float h10 = __bfloat162float(__float2bfloat16(p10));
                float h11 = __bfloat162float(__float2bfloat16(p11));
                float h20 = __bfloat162float(__float2bfloat16(p20));
                float h21 = __bfloat162float(__float2bfloat16(p21));
                float h30 = __bfloat162float(__float2bfloat16(p30));
                float h31 = __bfloat162float(__float2bfloat16(p31));
                Ph[0] = pack_bf16(h00, h01); Ph[1] = pack_bf16(h10, h11);
                Ph[2] = pack_bf16(h20, h21); Ph[3] = pack_bf16(h30, h31);
                Pl[0] = pack_bf16(p00 - h00, p01 - h01);
                Pl[1] = pack_bf16(p10 - h10, p11 - h11);
                Pl[2] = pack_bf16(p20 - h20, p21 - h21);
                Pl[3] = pack_bf16(p30 - h30, p31 - h31);
            }
#pragma unroll
            for (int nt = 0; nt < 16; nt++) {
                int base = (nt * 8 + (lane >> 2)) * VSTR + kt * 16 + qpair;
                uint32_t bh0 = *(const uint32_t*)&Vsh[base];
                uint32_t bh1 = *(const uint32_t*)&Vsh[base + 8];
                uint32_t bl0 = *(const uint32_t*)&Vsl[base];
                uint32_t bl1 = *(const uint32_t*)&Vsl[base + 8];
                mma16816(O[nt], Ph, bh0, bh1);
                mma16816(O[nt], Ph, bl0, bl1);
                mma16816(O[nt], Pl, bh0, bh1);
            }
        }
        __syncthreads();
    }

    float il0 = 1.0f / l0, il1 = 1.0f / l1;
#pragma unroll
    for (int nt = 0; nt < 16; nt++) {
        int d = nt * 8 + qpair;
        size_t base0 = (size_t)(b * TT + rg0) * NE + h * HD + d;
        size_t base1 = (size_t)(b * TT + rg1) * NE + h * HD + d;
        float o00 = O[nt][0] * il0, o01 = O[nt][1] * il0;
        float o10 = O[nt][2] * il1, o11 = O[nt][3] * il1;
        float h00 = __bfloat162float(__float2bfloat16(o00));
        float h01 = __bfloat162float(__float2bfloat16(o01));
        float h10 = __bfloat162float(__float2bfloat16(o10));
        float h11 = __bfloat162float(__float2bfloat16(o11));
        *(uint32_t*)&yh[base0] = pack_bf16(h00, h01);
        *(uint32_t*)&yl[base0] = pack_bf16(o00 - h00, o01 - h01);
        *(uint32_t*)&yh[base1] = pack_bf16(h10, h11);
        *(uint32_t*)&yl[base1] = pack_bf16(o10 - h10, o11 - h11);
    }
}

// ---------------------------------------------------------------------------
extern "C" void kernel_launch(void* const* d_in, const int* in_sizes, int n_in,
                              void* d_out, int out_size) {
    const float* x  = (const float*)d_in[0];
    const float* wq = (const float*)d_in[1];
    const float* wk = (const float*)d_in[2];
    const float* wv = (const float*)d_in[3];
    const float* wo = (const float*)d_in[4];
    float* out = (float*)d_out;

    __nv_bfloat16 *xh, *xl, *wqh, *wql, *wkh, *wkl, *wvh, *wvl, *woh, *wol, *yh, *yl;
    __nv_bfloat16 *qh, *ql, *kh, *kl, *vth, *vtl;
    cudaGetSymbolAddress((void**)&xh,  g_xh);  cudaGetSymbolAddress((void**)&xl,  g_xl);
    cudaGetSymbolAddress((void**)&wqh, g_wqh); cudaGetSymbolAddress((void**)&wql, g_wql);
    cudaGetSymbolAddress((void**)&wkh, g_wkh); cudaGetSymbolAddress((void**)&wkl, g_wkl);
    cudaGetSymbolAddress((void**)&wvh, g_wvh); cudaGetSymbolAddress((void**)&wvl, g_wvl);
    cudaGetSymbolAddress((void**)&woh, g_woh); cudaGetSymbolAddress((void**)&wol, g_wol);
    cudaGetSymbolAddress((void**)&yh,  g_yh);  cudaGetSymbolAddress((void**)&yl,  g_yl);
    cudaGetSymbolAddress((void**)&qh,  g_qh);  cudaGetSymbolAddress((void**)&ql,  g_ql);
    cudaGetSymbolAddress((void**)&kh,  g_kh);  cudaGetSymbolAddress((void**)&kl,  g_kl);
    cudaGetSymbolAddress((void**)&vth, g_vth); cudaGetSymbolAddress((void**)&vtl, g_vtl);

    int nx  = MROWS * NE / 4;
    int nw  = NE * NE / 4;
    int nwk = KVE * NE / 4;
    split_bf16<<<(nx  + 255) / 256, 256>>>(x,  xh,  xl,  nx);
    split_bf16<<<(nw  + 255) / 256, 256>>>(wq, wqh, wql, nw);
    split_bf16<<<(nwk + 255) / 256, 256>>>(wk, wkh, wkl, nwk);
    split_bf16<<<(nwk + 255) / 256, 256>>>(wv, wvh, wvl, nwk);
    split_bf16<<<(nw  + 255) / 256, 256>>>(wo, woh, wol, nw);

    cudaFuncSetAttribute(gemm_nt_pipe, cudaFuncAttributeMaxDynamicSharedMemorySize, GEMM_SMEM);

    dim3 blk(256);
    dim3 grdQ(NE / TBN, MROWS / TBM, 1);    // (16, 32, 1)
    dim3 grdKV(KVE / TBN, MROWS / TBM, 2);  // (4, 32, 2) fused K+V

    // Q projection -> split (B,T,H,D)
    gemm_nt_pipe<<<grdQ, blk, GEMM_SMEM>>>(xh, xl,
        wqh, wql, 1, nullptr, qh, ql,
        wqh, wql, 1, nullptr, qh, ql,
        MROWS, NE, NE);
    // K (mode 1) + V (mode 2, transposed) fused
    gemm_nt_pipe<<<grdKV, blk, GEMM_SMEM>>>(xh, xl,
        wkh, wkl, 1, nullptr, kh, kl,
        wvh, wvl, 2, nullptr, vth, vtl,
        MROWS, KVE, NE);

    cudaFuncSetAttribute(attn_mma, cudaFuncAttributeMaxDynamicSharedMemorySize, SM_ATT_BYTES);
    dim3 agrd(TT / BQ, BB * NH);
    attn_mma<<<agrd, blk, SM_ATT_BYTES>>>(qh, ql, kh, kl, vth, vtl, yh, yl);

    // Output projection -> fp32 out
    gemm_nt_pipe<<<grdQ, blk, GEMM_SMEM>>>(yh, yl,
        woh, wol, 0, out, nullptr, nullptr,
        woh, wol, 0, out, nullptr, nullptr,
        MROWS, NE, NE);
}

// round 8
// speedup vs baseline: 3.6642x; 1.6054x over previous
#include <cuda_runtime.h>
#include <cuda_fp16.h>
#include <math_constants.h>
#include <mma.h>
#include <cstdint>

using namespace nvcuda;

#define BB 2
#define TT 2048
#define NE 2048
#define NH 16
#define NKV 4
#define HD 128
#define GRP (NH / NKV)
#define MROWS (BB * TT)
#define KVE (NKV * NE / NH * 1)   // placeholder guard
#undef KVE
#define KVE (NKV * HD)

// fp16 scratch
__device__ __half g_xh[MROWS * NE], g_xl[MROWS * NE];
__device__ __half g_wq[NE * NE];
__device__ __half g_wk[KVE * NE];
__device__ __half g_wv[KVE * NE];
__device__ __half g_wo[NE * NE];
__device__ __half g_qh[MROWS * NE], g_ql[MROWS * NE];   // (B,T,H,D) split
__device__ __half g_k[MROWS * KVE];                     // (B,T,Hkv,D) single
__device__ __half g_vt[MROWS * KVE];                    // (B,Hkv,D,T) single
__device__ __half g_yh[MROWS * NE], g_yl[MROWS * NE];   // attention out split

__device__ __forceinline__ uint32_t pack_h(float x, float y) {
    __half2 r = __floats2half2_rn(x, y);
    return *(uint32_t*)&r;
}
__device__ __forceinline__ float fast_exp2(float x) {
    float y; asm("ex2.approx.f32 %0, %1;" : "=f"(y) : "f"(x)); return y;
}
__device__ __forceinline__ void mma16816(float* c, const uint32_t* a, uint32_t b0, uint32_t b1) {
    asm volatile("mma.sync.aligned.m16n8k16.row.col.f32.f16.f16.f32 "
                 "{%0,%1,%2,%3}, {%4,%5,%6,%7}, {%8,%9}, {%0,%1,%2,%3};\n"
                 : "+f"(c[0]), "+f"(c[1]), "+f"(c[2]), "+f"(c[3])
                 : "r"(a[0]), "r"(a[1]), "r"(a[2]), "r"(a[3]), "r"(b0), "r"(b1));
}
__device__ __forceinline__ void cp16(__half* s, const __half* g) {
    uint32_t sa = (uint32_t)__cvta_generic_to_shared(s);
    asm volatile("cp.async.cg.shared.global [%0], [%1], 16;" :: "r"(sa), "l"(g));
}

// ---------------------------------------------------------------------------
// fp32 -> fp16 hi + lo split (activations)
// ---------------------------------------------------------------------------
__global__ __launch_bounds__(256) void split_fp16(const float* __restrict__ x,
                                                  __half* __restrict__ hi,
                                                  __half* __restrict__ lo,
                                                  int n4) {
    int i = blockIdx.x * blockDim.x + threadIdx.x;
    if (i >= n4) return;
    float4 v = ((const float4*)x)[i];
    union { __half b[4]; uint2 u; } H, L;
    float vv[4] = {v.x, v.y, v.z, v.w};
#pragma unroll
    for (int j = 0; j < 4; j++) {
        __half h = __float2half_rn(vv[j]);
        H.b[j] = h;
        L.b[j] = __float2half_rn(vv[j] - __half2float(h));
    }
    ((uint2*)hi)[i] = H.u;
    ((uint2*)lo)[i] = L.u;
}

// fp32 -> fp16 single (weights)
__global__ __launch_bounds__(256) void conv_fp16(const float* __restrict__ x,
                                                 __half* __restrict__ o, int n4) {
    int i = blockIdx.x * blockDim.x + threadIdx.x;
    if (i >= n4) return;
    float4 v = ((const float4*)x)[i];
    union { __half b[4]; uint2 u; } H;
    H.b[0] = __float2half_rn(v.x); H.b[1] = __float2half_rn(v.y);
    H.b[2] = __float2half_rn(v.z); H.b[3] = __float2half_rn(v.w);
    ((uint2*)o)[i] = H.u;
}

// ---------------------------------------------------------------------------
// 4-stage cp.async wmma NT GEMM, fp16 2-term (A split, B single).
// Block tile 128x128, K-step 32, 256 threads (8 warps 2x4), warp tile 64x32.
// Output modes: 0 fp32 row-major; 1 fp16 hi/lo split row-major;
//               2 fp16 single row-major; 3 fp16 single transposed (B,Hkv,D,T).
// ---------------------------------------------------------------------------
#define TBM 128
#define TBN 128
#define TBK 32
#define TLD 40
#define TILE_ELEMS (TBM * TLD)   // 5120 halves
#define NSTAGE 4
#define SEPI 132
#define GEMM_SMEM (NSTAGE * 3 * TILE_ELEMS * 2)  // 122880 B

__global__ __launch_bounds__(256, 1) void gemm_nt_pipe(
    const __half* __restrict__ Ah, const __half* __restrict__ Al,
    const __half* __restrict__ B0, int mode0, float* __restrict__ Cf0,
    __half* __restrict__ Ch0, __half* __restrict__ Cl0,
    const __half* __restrict__ B1, int mode1, float* __restrict__ Cf1,
    __half* __restrict__ Ch1, __half* __restrict__ Cl1,
    int M, int N, int K)
{
    const __half* B = blockIdx.z ? B1 : B0;
    const int mode = blockIdx.z ? mode1 : mode0;
    float*  Cf = blockIdx.z ? Cf1 : Cf0;
    __half* Ch = blockIdx.z ? Ch1 : Ch0;
    __half* Cl = blockIdx.z ? Cl1 : Cl0;

    extern __shared__ __half gsm[];
    auto tilep = [&](int st, int which) { return gsm + (st * 3 + which) * TILE_ELEMS; };

    const int t  = threadIdx.x;
    const int w  = t >> 5;
    const int wm = w & 1;
    const int wn = w >> 1;
    const int row0 = blockIdx.y * TBM;
    const int col0 = blockIdx.x * TBN;

    wmma::fragment<wmma::accumulator, 16, 16, 16, float> acc[4][2];
#pragma unroll
    for (int i = 0; i < 4; i++)
#pragma unroll
        for (int j = 0; j < 2; j++) wmma::fill_fragment(acc[i][j], 0.0f);

    const int nk = K / TBK;

    auto load_stage = [&](int st, int kb) {
        __half* tAh = tilep(st, 0);
        __half* tAl = tilep(st, 1);
        __half* tB  = tilep(st, 2);
#pragma unroll
        for (int i = 0; i < 2; i++) {
            int p = t + i * 256;
            int r = p >> 2, qq = p & 3;
            size_t ga = (size_t)(row0 + r) * K + kb * TBK + qq * 8;
            size_t gb = (size_t)(col0 + r) * K + kb * TBK + qq * 8;
            int so = r * TLD + qq * 8;
            cp16(tAh + so, Ah + ga);
            cp16(tAl + so, Al + ga);
            cp16(tB  + so, B  + gb);
        }
        asm volatile("cp.async.commit_group;" ::: "memory");
    };

    load_stage(0, 0);
    load_stage(1, 1);
    load_stage(2, 2);

    for (int kb = 0; kb < nk; kb++) {
        const int cur = kb % NSTAGE;
        if (kb + 3 < nk) {
            load_stage((kb + 3) % NSTAGE, kb + 3);
            asm volatile("cp.async.wait_group 3;" ::: "memory");
        } else if (kb + 2 < nk) {
            asm volatile("cp.async.wait_group 2;" ::: "memory");
        } else if (kb + 1 < nk) {
            asm volatile("cp.async.wait_group 1;" ::: "memory");
        } else {
            asm volatile("cp.async.wait_group 0;" ::: "memory");
        }
        __syncthreads();

        const __half* tAh = tilep(cur, 0);
        const __half* tAl = tilep(cur, 1);
        const __half* tB  = tilep(cur, 2);

#pragma unroll
        for (int kk = 0; kk < TBK; kk += 16) {
            wmma::fragment<wmma::matrix_a, 16, 16, 16, __half, wmma::row_major> ah[4], al[4];
            wmma::fragment<wmma::matrix_b, 16, 16, 16, __half, wmma::col_major> bf[2];
#pragma unroll
            for (int i = 0; i < 4; i++) {
                wmma::load_matrix_sync(ah[i], tAh + (wm * 64 + i * 16) * TLD + kk, TLD);
                wmma::load_matrix_sync(al[i], tAl + (wm * 64 + i * 16) * TLD + kk, TLD);
            }
#pragma unroll
            for (int j = 0; j < 2; j++)
                wmma::load_matrix_sync(bf[j], tB + (wn * 32 + j * 16) * TLD + kk, TLD);
#pragma unroll
            for (int i = 0; i < 4; i++)
#pragma unroll
                for (int j = 0; j < 2; j++) {
                    wmma::mma_sync(acc[i][j], ah[i], bf[j], acc[i][j]);
                    wmma::mma_sync(acc[i][j], al[i], bf[j], acc[i][j]);
                }
        }
        __syncthreads();
    }

    // Epilogue via smem fp32 staging
    float* smf = (float*)gsm;
#pragma unroll
    for (int i = 0; i < 4; i++)
#pragma unroll
        for (int j = 0; j < 2; j++)
            wmma::store_matrix_sync(&smf[(wm * 64 + i * 16) * SEPI + wn * 32 + j * 16],
                                    acc[i][j], SEPI, wmma::mem_row_major);
    __syncthreads();

    if (mode == 0) {
#pragma unroll
        for (int i = 0; i < 32; i++) {
            int p = t + i * 256;
            int r = p >> 6, c2 = (p & 63) * 2;
            float2 v = *(float2*)&smf[r * SEPI + c2];
            *(float2*)&Cf[(size_t)(row0 + r) * N + col0 + c2] = v;
        }
    } else if (mode == 1) {
#pragma unroll
        for (int i = 0; i < 32; i++) {
            int p = t + i * 256;
            int r = p >> 6, c2 = (p & 63) * 2;
            float x0 = smf[r * SEPI + c2], x1 = smf[r * SEPI + c2 + 1];
            float h0 = __half2float(__float2half_rn(x0));
            float h1 = __half2float(__float2half_rn(x1));
            size_t gidx = (size_t)(row0 + r) * N + col0 + c2;
            *(uint32_t*)&Ch[gidx] = pack_h(h0, h1);
            *(uint32_t*)&Cl[gidx] = pack_h(x0 - h0, x1 - h1);
        }
    } else if (mode == 2) {
#pragma unroll
        for (int i = 0; i < 32; i++) {
            int p = t + i * 256;
            int r = p >> 6, c2 = (p & 63) * 2;
            float x0 = smf[r * SEPI + c2], x1 = smf[r * SEPI + c2 + 1];
            size_t gidx = (size_t)(row0 + r) * N + col0 + c2;
            *(uint32_t*)&Ch[gidx] = pack_h(x0, x1);
        }
    } else {
        // mode 3: transposed single fp16 (B,Hkv,D,T)
        const int b  = row0 >> 11;
        const int t0 = row0 & 2047;
        const int hk = col0 >> 7;
#pragma unroll
        for (int i = 0; i < 32; i++) {
            int p = t + i * 256;
            int c = p >> 6, rp = (p & 63) * 2;
            float x0 = smf[rp * SEPI + c], x1 = smf[(rp + 1) * SEPI + c];
            size_t gidx = ((size_t)(b * NKV + hk) * HD + c) * TT + t0 + rp;
            *(uint32_t*)&Ch[gidx] = pack_h(x0, x1);
        }
    }
}

// ---------------------------------------------------------------------------
// FA2 mma.sync causal GQA attention, fp16 2-term:
//   S = (Qh + Ql) K   (Q split in regs, K single in smem)
//   O += (Ph + Pl) V  (P split in regs, V single in smem)
// Double-buffered cp.async tile loads. CTA: 128 Q rows, 8 warps, KV tile 64.
// ---------------------------------------------------------------------------
#define BQ 128
#define BKV 64
#define KSTR 136
#define VSTR 72
#define KTILE (BKV * KSTR)     // 8704 halves
#define VTILE (HD * VSTR)      // 9216 halves
#define ASTAGE (KTILE + VTILE)           // 17920 halves
#define SM_ATT_BYTES (2 * ASTAGE * 2)    // 71680 B

__global__ __launch_bounds__(256, 1) void attn_mma(
    const __half* __restrict__ qh, const __half* __restrict__ ql,
    const __half* __restrict__ kf, const __half* __restrict__ vtf,
    __half* __restrict__ yh, __half* __restrict__ yl) {
    extern __shared__ __half smA[];

    const int t    = threadIdx.x;
    const int w    = t >> 5;
    const int lane = t & 31;
    const int qb   = (gridDim.x - 1) - blockIdx.x;   // heavy CTAs first
    const int bh   = blockIdx.y;
    const int b    = bh >> 4;
    const int h    = bh & 15;
    const int hk   = h / GRP;
    const int q0   = qb * BQ;
    const int rg0  = q0 + w * 16 + (lane >> 2);
    const int rg1  = rg0 + 8;
    const int qpair = (lane & 3) * 2;

    // ---- Q fragments (pre-split fp16) ----
    uint32_t Qh[8][4], Ql[8][4];
#pragma unroll
    for (int kt = 0; kt < 8; kt++) {
#pragma unroll
        for (int half = 0; half < 2; half++) {
#pragma unroll
            for (int ri = 0; ri < 2; ri++) {
                int row = ri ? rg1 : rg0;
                size_t gi = ((size_t)(b * TT + row) * NH + h) * HD + kt * 16 + half * 8 + qpair;
                Qh[kt][half * 2 + ri] = *(const uint32_t*)&qh[gi];
                Ql[kt][half * 2 + ri] = *(const uint32_t*)&ql[gi];
            }
        }
    }

    float O[16][4];
#pragma unroll
    for (int nt = 0; nt < 16; nt++)
#pragma unroll
        for (int e = 0; e < 4; e++) O[nt][e] = 0.0f;
    float m0 = -CUDART_INF_F, m1 = -CUDART_INF_F, l0 = 0.0f, l1 = 0.0f;

    const float SCL = 0.08838834764831845f * 1.4426950408889634f;
    const int kb_end = 2 * qb + 2;

    auto fill = [&](int st, int kb) {
        __half* Ksh = smA + st * ASTAGE;
        __half* Vsh = Ksh + KTILE;
        const int k0 = kb * BKV;
#pragma unroll
        for (int i = 0; i < 4; i++) {
            int p = t + i * 256;
            int c = p >> 4, ch = p & 15;
            size_t g = ((size_t)(b * TT + k0 + c) * NKV + hk) * HD + ch * 8;
            cp16(Ksh + c * KSTR + ch * 8, kf + g);
        }
#pragma unroll
        for (int i = 0; i < 4; i++) {
            int p = t + i * 256;
            int d = p >> 3, ch = p & 7;
            size_t g = ((size_t)(b * NKV + hk) * HD + d) * TT + k0 + ch * 8;
            cp16(Vsh + d * VSTR + ch * 8, vtf + g);
        }
        asm volatile("cp.async.commit_group;" ::: "memory");
    };

    fill(0, 0);

    for (int kb = 0; kb < kb_end; kb++) {
        const int cur = kb & 1;
        const int k0 = kb * BKV;
        if (kb + 1 < kb_end) {
            fill(cur ^ 1, kb + 1);
            asm volatile("cp.async.wait_group 1;" ::: "memory");
        } else {
            asm volatile("cp.async.wait_group 0;" ::: "memory");
        }
        __syncthreads();

        const __half* Ksh = smA + cur * ASTAGE;
        const __half* Vsh = Ksh + KTILE;

        // ---- S = Q K^T ----
        float S[8][4];
#pragma unroll
        for (int jt = 0; jt < 8; jt++)
#pragma unroll
            for (int e = 0; e < 4; e++) S[jt][e] = 0.0f;

#pragma unroll
        for (int kt = 0; kt < 8; kt++) {
#pragma unroll
            for (int jt = 0; jt < 8; jt++) {
                int base = (jt * 8 + (lane >> 2)) * KSTR + kt * 16 + qpair;
                uint32_t b0 = *(const uint32_t*)&Ksh[base];
                uint32_t b1 = *(const uint32_t*)&Ksh[base + 8];
                mma16816(S[jt], Qh[kt], b0, b1);
                mma16816(S[jt], Ql[kt], b0, b1);
            }
        }

        // ---- scale + causal mask ----
        const bool diag = (kb >= 2 * qb);
#pragma unroll
        for (int jt = 0; jt < 8; jt++) {
            int c0 = k0 + jt * 8 + qpair;
            S[jt][0] *= SCL; S[jt][1] *= SCL; S[jt][2] *= SCL; S[jt][3] *= SCL;
            if (diag) {
                if (c0 > rg0)     S[jt][0] = -CUDART_INF_F;
                if (c0 + 1 > rg0) S[jt][1] = -CUDART_INF_F;
                if (c0 > rg1)     S[jt][2] = -CUDART_INF_F;
                if (c0 + 1 > rg1) S[jt][3] = -CUDART_INF_F;
            }
        }

        // ---- online softmax (base-2) ----
        float mx0 = -CUDART_INF_F, mx1 = -CUDART_INF_F;
#pragma unroll
        for (int jt = 0; jt < 8; jt++) {
            mx0 = fmaxf(mx0, fmaxf(S[jt][0], S[jt][1]));
            mx1 = fmaxf(mx1, fmaxf(S[jt][2], S[jt][3]));
        }
#pragma unroll
        for (int off = 1; off <= 2; off <<= 1) {
            mx0 = fmaxf(mx0, __shfl_xor_sync(0xffffffffu, mx0, off));
            mx1 = fmaxf(mx1, __shfl_xor_sync(0xffffffffu, mx1, off));
        }
        float mn0 = fmaxf(m0, mx0), mn1 = fmaxf(m1, mx1);
        float al0 = fast_exp2(m0 - mn0), al1 = fast_exp2(m1 - mn1);
        float s0 = 0.0f, s1 = 0.0f;
#pragma unroll
        for (int jt = 0; jt < 8; jt++) {
            S[jt][0] = fast_exp2(S[jt][0] - mn0); s0 += S[jt][0];
            S[jt][1] = fast_exp2(S[jt][1] - mn0); s0 += S[jt][1];
            S[jt][2] = fast_exp2(S[jt][2] - mn1); s1 += S[jt][2];
            S[jt][3] = fast_exp2(S[jt][3] - mn1); s1 += S[jt][3];
        }
#pragma unroll
        for (int off = 1; off <= 2; off <<= 1) {
            s0 += __shfl_xor_sync(0xffffffffu, s0, off);
            s1 += __shfl_xor_sync(0xffffffffu, s1, off);
        }
        l0 = l0 * al0 + s0; l1 = l1 * al1 + s1;
        m0 = mn0; m1 = mn1;
#pragma unroll
        for (int nt = 0; nt < 16; nt++) {
            O[nt][0] *= al0; O[nt][1] *= al0;
            O[nt][2] *= al1; O[nt][3] *= al1;
        }

        // ---- O += P V (P split fp16) ----
#pragma unroll
        for (int kt = 0; kt < 4; kt++) {
            uint32_t Ph[4], Pl[4];
            {
                float p00 = S[2 * kt][0],     p01 = S[2 * kt][1];
                float p10 = S[2 * kt][2],     p11 = S[2 * kt][3];
                float p20 = S[2 * kt + 1][0], p21 = S[2 * kt + 1][1];
                float p30 = S[2 * kt + 1][2], p31 = S[2 * kt + 1][3];
                float h00 = __half2float(__float2half_rn(p00));
                float h01 = __half2float(__float2half_rn(p01));
                float h10 = __half2float(__float2half_rn(p10));
                float h11 = __half2float(__float2half_rn(p11));
                float h20 = __half2float(__float2half_rn(p20));
                float h21 = __half2float(__float2half_rn(p21));
                float h30 = __half2float(__float2half_rn(p30));
                float h31 = __half2float(__float2half_rn(p31));
                Ph[0] = pack_h(h00, h01); Ph[1] = pack_h(h10, h11);
                Ph[2] = pack_h(h20, h21); Ph[3] = pack_h(h30, h31);
                Pl[0] = pack_h(p00 - h00, p01 - h01);
                Pl[1] = pack_h(p10 - h10, p11 - h11);
                Pl[2] = pack_h(p20 - h20, p21 - h21);
                Pl[3] = pack_h(p30 - h30, p31 - h31);
            }
#pragma unroll
            for (int nt = 0; nt < 16; nt++) {
                int base = (nt * 8 + (lane >> 2)) * VSTR + kt * 16 + qpair;
                uint32_t b0 = *(const uint32_t*)&Vsh[base];
                uint32_t b1 = *(const uint32_t*)&Vsh[base + 8];
                mma16816(O[nt], Ph, b0, b1);
                mma16816(O[nt], Pl, b0, b1);
            }
        }
        __syncthreads();
    }

    float il0 = 1.0f / l0, il1 = 1.0f / l1;
#pragma unroll
    for (int nt = 0; nt < 16; nt++) {
        int d = nt * 8 + qpair;
        size_t base0 = (size_t)(b * TT + rg0) * NE + h * HD + d;
        size_t base1 = (size_t)(b * TT + rg1) * NE + h * HD + d;
        float o00 = O[nt][0] * il0, o01 = O[nt][1] * il0;
        float o10 = O[nt][2] * il1, o11 = O[nt][3] * il1;
        float h00 = __half2float(__float2half_rn(o00));
        float h01 = __half2float(__float2half_rn(o01));
        float h10 = __half2float(__float2half_rn(o10));
        float h11 = __half2float(__float2half_rn(o11));
        *(uint32_t*)&yh[base0] = pack_h(h00, h01);
        *(uint32_t*)&yl[base0] = pack_h(o00 - h00, o01 - h01);
        *(uint32_t*)&yh[base1] = pack_h(h10, h11);
        *(uint32_t*)&yl[base1] = pack_h(o10 - h10, o11 - h11);
    }
}

// ---------------------------------------------------------------------------
extern "C" void kernel_launch(void* const* d_in, const int* in_sizes, int n_in,
                              void* d_out, int out_size) {
    const float* x  = (const float*)d_in[0];
    const float* wq = (const float*)d_in[1];
    const float* wk = (const float*)d_in[2];
    const float* wv = (const float*)d_in[3];
    const float* wo = (const float*)d_in[4];
    float* out = (float*)d_out;

    __half *xh, *xl, *wqp, *wkp, *wvp, *wop, *qh, *ql, *kp, *vtp, *yh, *yl;
    cudaGetSymbolAddress((void**)&xh,  g_xh);  cudaGetSymbolAddress((void**)&xl, g_xl);
    cudaGetSymbolAddress((void**)&wqp, g_wq);  cudaGetSymbolAddress((void**)&wkp, g_wk);
    cudaGetSymbolAddress((void**)&wvp, g_wv);  cudaGetSymbolAddress((void**)&wop, g_wo);
    cudaGetSymbolAddress((void**)&qh,  g_qh);  cudaGetSymbolAddress((void**)&ql,  g_ql);
    cudaGetSymbolAddress((void**)&kp,  g_k);   cudaGetSymbolAddress((void**)&vtp, g_vt);
    cudaGetSymbolAddress((void**)&yh,  g_yh);  cudaGetSymbolAddress((void**)&yl,  g_yl);

    int nx  = MROWS * NE / 4;
    int nw  = NE * NE / 4;
    int nwk = KVE * NE / 4;
    split_fp16<<<(nx  + 255) / 256, 256>>>(x,  xh, xl, nx);
    conv_fp16<<<(nw  + 255) / 256, 256>>>(wq, wqp, nw);
    conv_fp16<<<(nwk + 255) / 256, 256>>>(wk, wkp, nwk);
    conv_fp16<<<(nwk + 255) / 256, 256>>>(wv, wvp, nwk);
    conv_fp16<<<(nw  + 255) / 256, 256>>>(wo, wop, nw);

    cudaFuncSetAttribute(gemm_nt_pipe, cudaFuncAttributeMaxDynamicSharedMemorySize, GEMM_SMEM);

    dim3 blk(256);
    dim3 grdQ(NE / TBN, MROWS / TBM, 1);    // (16, 32, 1)
    dim3 grdKV(KVE / TBN, MROWS / TBM, 2);  // (4, 32, 2) fused K+V

    // Q projection -> fp16 split (B,T,H,D)
    gemm_nt_pipe<<<grdQ, blk, GEMM_SMEM>>>(xh, xl,
        wqp, 1, nullptr, qh, ql,
        wqp, 1, nullptr, qh, ql,
        MROWS, NE, NE);
    // K (mode 2 single) + V (mode 3 transposed single) fused
    gemm_nt_pipe<<<grdKV, blk, GEMM_SMEM>>>(xh, xl,
        wkp, 2, nullptr, kp,  nullptr,
        wvp, 3, nullptr, vtp, nullptr,
        MROWS, KVE, NE);

    cudaFuncSetAttribute(attn_mma, cudaFuncAttributeMaxDynamicSharedMemorySize, SM_ATT_BYTES);
    dim3 agrd(TT / BQ, BB * NH);
    attn_mma<<<agrd, blk, SM_ATT_BYTES>>>(qh, ql, kp, vtp, yh, yl);

    // Output projection -> fp32 out
    gemm_nt_pipe<<<grdQ, blk, GEMM_SMEM>>>(yh, yl,
        wop, 0, out, nullptr, nullptr,
        wop, 0, out, nullptr, nullptr,
        MROWS, NE, NE);
}

// round 9
// speedup vs baseline: 4.0008x; 1.0919x over previous
#include <cuda_runtime.h>
#include <cuda_fp16.h>
#include <math_constants.h>
#include <mma.h>
#include <cstdint>

using namespace nvcuda;

#define BB 2
#define TT 2048
#define NE 2048
#define NH 16
#define NKV 4
#define HD 128
#define GRP (NH / NKV)
#define MROWS (BB * TT)
#define KVE (NKV * HD)

// fp16 scratch
__device__ __half g_xh[MROWS * NE], g_xl[MROWS * NE];
__device__ __half g_wq[NE * NE];
__device__ __half g_wk[KVE * NE];
__device__ __half g_wv[KVE * NE];
__device__ __half g_wo[NE * NE];
__device__ __half g_qh[MROWS * NE], g_ql[MROWS * NE];   // (B,T,H,D) split
__device__ __half g_k[MROWS * KVE];                     // (B,T,Hkv,D)
__device__ __half g_vt[MROWS * KVE];                    // (B,Hkv,D,T)
__device__ __half g_yh[MROWS * NE], g_yl[MROWS * NE];

__device__ __forceinline__ uint32_t pack_h(float x, float y) {
    __half2 r = __floats2half2_rn(x, y);
    return *(uint32_t*)&r;
}
__device__ __forceinline__ float fast_exp2(float x) {
    float y; asm("ex2.approx.f32 %0, %1;" : "=f"(y) : "f"(x)); return y;
}
__device__ __forceinline__ void mma16816(float* c, const uint32_t* a, uint32_t b0, uint32_t b1) {
    asm volatile("mma.sync.aligned.m16n8k16.row.col.f32.f16.f16.f32 "
                 "{%0,%1,%2,%3}, {%4,%5,%6,%7}, {%8,%9}, {%0,%1,%2,%3};\n"
                 : "+f"(c[0]), "+f"(c[1]), "+f"(c[2]), "+f"(c[3])
                 : "r"(a[0]), "r"(a[1]), "r"(a[2]), "r"(a[3]), "r"(b0), "r"(b1));
}
__device__ __forceinline__ void cp16(__half* s, const __half* g) {
    uint32_t sa = (uint32_t)__cvta_generic_to_shared(s);
    asm volatile("cp.async.cg.shared.global [%0], [%1], 16;" :: "r"(sa), "l"(g));
}

// ---------------------------------------------------------------------------
// Fused prep: split x -> (xh,xl); convert wq/wk/wv/wo -> fp16
// ---------------------------------------------------------------------------
#define NX4  (MROWS * NE / 4)   // 2097152
#define NW4  (NE * NE / 4)      // 1048576
#define NWK4 (KVE * NE / 4)     // 262144
#define PREP_TOTAL (NX4 + NW4 + 2 * NWK4 + NW4)

__global__ __launch_bounds__(256) void prep_all(
    const float* __restrict__ x,  const float* __restrict__ wq,
    const float* __restrict__ wk, const float* __restrict__ wv,
    const float* __restrict__ wo,
    __half* __restrict__ xh, __half* __restrict__ xl,
    __half* __restrict__ wqp, __half* __restrict__ wkp,
    __half* __restrict__ wvp, __half* __restrict__ wop)
{
    int i = blockIdx.x * blockDim.x + threadIdx.x;
    if (i >= PREP_TOTAL) return;
    if (i < NX4) {
        float4 v = ((const float4*)x)[i];
        union { __half b[4]; uint2 u; } H, L;
        float vv[4] = {v.x, v.y, v.z, v.w};
#pragma unroll
        for (int j = 0; j < 4; j++) {
            __half h = __float2half_rn(vv[j]);
            H.b[j] = h;
            L.b[j] = __float2half_rn(vv[j] - __half2float(h));
        }
        ((uint2*)xh)[i] = H.u;
        ((uint2*)xl)[i] = L.u;
        return;
    }
    const float* src; __half* dst; int j;
    i -= NX4;
    if (i < NW4)                { src = wq; dst = wqp; j = i; }
    else if (i < NW4 + NWK4)    { src = wk; dst = wkp; j = i - NW4; }
    else if (i < NW4 + 2*NWK4)  { src = wv; dst = wvp; j = i - NW4 - NWK4; }
    else                        { src = wo; dst = wop; j = i - NW4 - 2*NWK4; }
    float4 v = ((const float4*)src)[j];
    union { __half b[4]; uint2 u; } H;
    H.b[0] = __float2half_rn(v.x); H.b[1] = __float2half_rn(v.y);
    H.b[2] = __float2half_rn(v.z); H.b[3] = __float2half_rn(v.w);
    ((uint2*)dst)[j] = H.u;
}

// ---------------------------------------------------------------------------
// GEMM core: 3-stage cp.async, K-step 64, fp16 2-term (A split, B single).
// Block tile 128x128, 256 threads (8 warps 2x4), warp tile 64x32.
// ---------------------------------------------------------------------------
#define TBM 128
#define TBN 128
#define TBK 64
#define TLD 72
#define TILE_ELEMS (TBM * TLD)     // 9216 halves
#define NSTAGE 3
#define SEPI 132
#define GEMM_SMEM (NSTAGE * 3 * TILE_ELEMS * 2)   // 165888 B

// Loads one k-stage (A hi, A lo, B) into stage st.
__device__ __forceinline__ void g_load_stage(
    __half* gsm, int st, int kb, int t,
    const __half* Ah, const __half* Al, const __half* B,
    int row0, int col0, int K)
{
    __half* tAh = gsm + (st * 3 + 0) * TILE_ELEMS;
    __half* tAl = gsm + (st * 3 + 1) * TILE_ELEMS;
    __half* tB  = gsm + (st * 3 + 2) * TILE_ELEMS;
#pragma unroll
    for (int i = 0; i < 4; i++) {
        int p = t + i * 256;              // 0..1023
        int r = p >> 3, ch = p & 7;       // row, 16B chunk
        size_t ga = (size_t)(row0 + r) * K + kb * TBK + ch * 8;
        size_t gb = (size_t)(col0 + r) * K + kb * TBK + ch * 8;
        int so = r * TLD + ch * 8;
        cp16(tAh + so, Ah + ga);
        cp16(tAl + so, Al + ga);
        cp16(tB  + so, B  + gb);
    }
    asm volatile("cp.async.commit_group;" ::: "memory");
}

// Computes full accumulation into smem fp32 staging buffer (SEPI stride).
__device__ __forceinline__ void g_core(
    __half* gsm, int t,
    const __half* Ah, const __half* Al, const __half* B,
    int row0, int col0, int K)
{
    const int w  = t >> 5;
    const int wm = w & 1;
    const int wn = w >> 1;

    wmma::fragment<wmma::accumulator, 16, 16, 16, float> acc[4][2];
#pragma unroll
    for (int i = 0; i < 4; i++)
#pragma unroll
        for (int j = 0; j < 2; j++) wmma::fill_fragment(acc[i][j], 0.0f);

    const int nk = K / TBK;
    g_load_stage(gsm, 0, 0, t, Ah, Al, B, row0, col0, K);
    g_load_stage(gsm, 1, 1, t, Ah, Al, B, row0, col0, K);

    for (int kb = 0; kb < nk; kb++) {
        const int cur = kb % NSTAGE;
        if (kb + 2 < nk) {
            g_load_stage(gsm, (kb + 2) % NSTAGE, kb + 2, t, Ah, Al, B, row0, col0, K);
            asm volatile("cp.async.wait_group 2;" ::: "memory");
        } else if (kb + 1 < nk) {
            asm volatile("cp.async.wait_group 1;" ::: "memory");
        } else {
            asm volatile("cp.async.wait_group 0;" ::: "memory");
        }
        __syncthreads();

        const __half* tAh = gsm + (cur * 3 + 0) * TILE_ELEMS;
        const __half* tAl = gsm + (cur * 3 + 1) * TILE_ELEMS;
        const __half* tB  = gsm + (cur * 3 + 2) * TILE_ELEMS;

#pragma unroll
        for (int kk = 0; kk < TBK; kk += 16) {
            wmma::fragment<wmma::matrix_a, 16, 16, 16, __half, wmma::row_major> ah[4], al[4];
            wmma::fragment<wmma::matrix_b, 16, 16, 16, __half, wmma::col_major> bf[2];
#pragma unroll
            for (int i = 0; i < 4; i++) {
                wmma::load_matrix_sync(ah[i], tAh + (wm * 64 + i * 16) * TLD + kk, TLD);
                wmma::load_matrix_sync(al[i], tAl + (wm * 64 + i * 16) * TLD + kk, TLD);
            }
#pragma unroll
            for (int j = 0; j < 2; j++)
                wmma::load_matrix_sync(bf[j], tB + (wn * 32 + j * 16) * TLD + kk, TLD);
#pragma unroll
            for (int i = 0; i < 4; i++)
#pragma unroll
                for (int j = 0; j < 2; j++) {
                    wmma::mma_sync(acc[i][j], ah[i], bf[j], acc[i][j]);
                    wmma::mma_sync(acc[i][j], al[i], bf[j], acc[i][j]);
                }
        }
        __syncthreads();
    }

    float* smf = (float*)gsm;
#pragma unroll
    for (int i = 0; i < 4; i++)
#pragma unroll
        for (int j = 0; j < 2; j++)
            wmma::store_matrix_sync(&smf[(wm * 64 + i * 16) * SEPI + wn * 32 + j * 16],
                                    acc[i][j], SEPI, wmma::mem_row_major);
    __syncthreads();
}

// Fused Q/K/V projection launch. grid = (24, 32).
// bx 0..15: Q (mode split), bx 16..19: K (single), bx 20..23: V^T (single).
__global__ __launch_bounds__(256, 1) void gemm_qkv(
    const __half* __restrict__ xh, const __half* __restrict__ xl,
    const __half* __restrict__ wq, const __half* __restrict__ wk,
    const __half* __restrict__ wv,
    __half* __restrict__ qh, __half* __restrict__ ql,
    __half* __restrict__ kp, __half* __restrict__ vtp)
{
    extern __shared__ __half gsm[];
    const int t  = threadIdx.x;
    const int bx = blockIdx.x;
    const int row0 = blockIdx.y * TBM;

    const __half* B; int mode, N, cb;
    if (bx < 16)      { B = wq; mode = 1; N = NE;  cb = bx; }
    else if (bx < 20) { B = wk; mode = 2; N = KVE; cb = bx - 16; }
    else              { B = wv; mode = 3; N = KVE; cb = bx - 20; }
    const int col0 = cb * TBN;

    g_core(gsm, t, xh, xl, B, row0, col0, NE);
    float* smf = (float*)gsm;

    if (mode == 1) {
#pragma unroll
        for (int i = 0; i < 32; i++) {
            int p = t + i * 256;
            int r = p >> 6, c2 = (p & 63) * 2;
            float x0 = smf[r * SEPI + c2], x1 = smf[r * SEPI + c2 + 1];
            float h0 = __half2float(__float2half_rn(x0));
            float h1 = __half2float(__float2half_rn(x1));
            size_t gidx = (size_t)(row0 + r) * N + col0 + c2;
            *(uint32_t*)&qh[gidx] = pack_h(h0, h1);
            *(uint32_t*)&ql[gidx] = pack_h(x0 - h0, x1 - h1);
        }
    } else if (mode == 2) {
#pragma unroll
        for (int i = 0; i < 32; i++) {
            int p = t + i * 256;
            int r = p >> 6, c2 = (p & 63) * 2;
            float x0 = smf[r * SEPI + c2], x1 = smf[r * SEPI + c2 + 1];
            size_t gidx = (size_t)(row0 + r) * N + col0 + c2;
            *(uint32_t*)&kp[gidx] = pack_h(x0, x1);
        }
    } else {
        const int b  = row0 >> 11;
        const int t0 = row0 & 2047;
        const int hk = col0 >> 7;
#pragma unroll
        for (int i = 0; i < 32; i++) {
            int p = t + i * 256;
            int c = p >> 6, rp = (p & 63) * 2;
            float x0 = smf[rp * SEPI + c], x1 = smf[(rp + 1) * SEPI + c];
            size_t gidx = ((size_t)(b * NKV + hk) * HD + c) * TT + t0 + rp;
            *(uint32_t*)&vtp[gidx] = pack_h(x0, x1);
        }
    }
}

// Output projection: fp32 out. grid = (16, 32).
__global__ __launch_bounds__(256, 1) void gemm_wo(
    const __half* __restrict__ yh, const __half* __restrict__ yl,
    const __half* __restrict__ wo, float* __restrict__ out)
{
    extern __shared__ __half gsm[];
    const int t = threadIdx.x;
    const int row0 = blockIdx.y * TBM;
    const int col0 = blockIdx.x * TBN;

    g_core(gsm, t, yh, yl, wo, row0, col0, NE);
    float* smf = (float*)gsm;
#pragma unroll
    for (int i = 0; i < 32; i++) {
        int p = t + i * 256;
        int r = p >> 6, c2 = (p & 63) * 2;
        float2 v = *(float2*)&smf[r * SEPI + c2];
        *(float2*)&out[(size_t)(row0 + r) * NE + col0 + c2] = v;
    }
}

// ---------------------------------------------------------------------------
// FA2 mma.sync causal GQA attention (unchanged from R8).
// ---------------------------------------------------------------------------
#define BQ 128
#define BKV 64
#define KSTR 136
#define VSTR 72
#define KTILE (BKV * KSTR)
#define VTILE (HD * VSTR)
#define ASTAGE (KTILE + VTILE)
#define SM_ATT_BYTES (2 * ASTAGE * 2)

__global__ __launch_bounds__(256, 1) void attn_mma(
    const __half* __restrict__ qh, const __half* __restrict__ ql,
    const __half* __restrict__ kf, const __half* __restrict__ vtf,
    __half* __restrict__ yh, __half* __restrict__ yl) {
    extern __shared__ __half smA[];

    const int t    = threadIdx.x;
    const int w    = t >> 5;
    const int lane = t & 31;
    const int qb   = (gridDim.x - 1) - blockIdx.x;
    const int bh   = blockIdx.y;
    const int b    = bh >> 4;
    const int h    = bh & 15;
    const int hk   = h / GRP;
    const int q0   = qb * BQ;
    const int rg0  = q0 + w * 16 + (lane >> 2);
    const int rg1  = rg0 + 8;
    const int qpair = (lane & 3) * 2;

    uint32_t Qh[8][4], Ql[8][4];
#pragma unroll
    for (int kt = 0; kt < 8; kt++) {
#pragma unroll
        for (int half = 0; half < 2; half++) {
#pragma unroll
            for (int ri = 0; ri < 2; ri++) {
                int row = ri ? rg1 : rg0;
                size_t gi = ((size_t)(b * TT + row) * NH + h) * HD + kt * 16 + half * 8 + qpair;
                Qh[kt][half * 2 + ri] = *(const uint32_t*)&qh[gi];
                Ql[kt][half * 2 + ri] = *(const uint32_t*)&ql[gi];
            }
        }
    }

    float O[16][4];
#pragma unroll
    for (int nt = 0; nt < 16; nt++)
#pragma unroll
        for (int e = 0; e < 4; e++) O[nt][e] = 0.0f;
    float m0 = -CUDART_INF_F, m1 = -CUDART_INF_F, l0 = 0.0f, l1 = 0.0f;

    const float SCL = 0.08838834764831845f * 1.4426950408889634f;
    const int kb_end = 2 * qb + 2;

    auto fill = [&](int st, int kb) {
        __half* Ksh = smA + st * ASTAGE;
        __half* Vsh = Ksh + KTILE;
        const int k0 = kb * BKV;
#pragma unroll
        for (int i = 0; i < 4; i++) {
            int p = t + i * 256;
            int c = p >> 4, ch = p & 15;
            size_t g = ((size_t)(b * TT + k0 + c) * NKV + hk) * HD + ch * 8;
            cp16(Ksh + c * KSTR + ch * 8, kf + g);
        }
#pragma unroll
        for (int i = 0; i < 4; i++) {
            int p = t + i * 256;
            int d = p >> 3, ch = p & 7;
            size_t g = ((size_t)(b * NKV + hk) * HD + d) * TT + k0 + ch * 8;
            cp16(Vsh + d * VSTR + ch * 8, vtf + g);
        }
        asm volatile("cp.async.commit_group;" ::: "memory");
    };

    fill(0, 0);

    for (int kb = 0; kb < kb_end; kb++) {
        const int cur = kb & 1;
        const int k0 = kb * BKV;
        if (kb + 1 < kb_end) {
            fill(cur ^ 1, kb + 1);
            asm volatile("cp.async.wait_group 1;" ::: "memory");
        } else {
            asm volatile("cp.async.wait_group 0;" ::: "memory");
        }
        __syncthreads();

        const __half* Ksh = smA + cur * ASTAGE;
        const __half* Vsh = Ksh + KTILE;

        float S[8][4];
#pragma unroll
        for (int jt = 0; jt < 8; jt++)
#pragma unroll
            for (int e = 0; e < 4; e++) S[jt][e] = 0.0f;

#pragma unroll
        for (int kt = 0; kt < 8; kt++) {
#pragma unroll
            for (int jt = 0; jt < 8; jt++) {
                int base = (jt * 8 + (lane >> 2)) * KSTR + kt * 16 + qpair;
                uint32_t b0 = *(const uint32_t*)&Ksh[base];
                uint32_t b1 = *(const uint32_t*)&Ksh[base + 8];
                mma16816(S[jt], Qh[kt], b0, b1);
                mma16816(S[jt], Ql[kt], b0, b1);
            }
        }

        const bool diag = (kb >= 2 * qb);
#pragma unroll
        for (int jt = 0; jt < 8; jt++) {
            int c0 = k0 + jt * 8 + qpair;
            S[jt][0] *= SCL; S[jt][1] *= SCL; S[jt][2] *= SCL; S[jt][3] *= SCL;
            if (diag) {
                if (c0 > rg0)     S[jt][0] = -CUDART_INF_F;
                if (c0 + 1 > rg0) S[jt][1] = -CUDART_INF_F;
                if (c0 > rg1)     S[jt][2] = -CUDART_INF_F;
                if (c0 + 1 > rg1) S[jt][3] = -CUDART_INF_F;
            }
        }

        float mx0 = -CUDART_INF_F, mx1 = -CUDART_INF_F;
#pragma unroll
        for (int jt = 0; jt < 8; jt++) {
            mx0 = fmaxf(mx0, fmaxf(S[jt][0], S[jt][1]));
            mx1 = fmaxf(mx1, fmaxf(S[jt][2], S[jt][3]));
        }
#pragma unroll
        for (int off = 1; off <= 2; off <<= 1) {
            mx0 = fmaxf(mx0, __shfl_xor_sync(0xffffffffu, mx0, off));
            mx1 = fmaxf(mx1, __shfl_xor_sync(0xffffffffu, mx1, off));
        }
        float mn0 = fmaxf(m0, mx0), mn1 = fmaxf(m1, mx1);
        float al0 = fast_exp2(m0 - mn0), al1 = fast_exp2(m1 - mn1);
        float s0 = 0.0f, s1 = 0.0f;
#pragma unroll
        for (int jt = 0; jt < 8; jt++) {
            S[jt][0] = fast_exp2(S[jt][0] - mn0); s0 += S[jt][0];
            S[jt][1] = fast_exp2(S[jt][1] - mn0); s0 += S[jt][1];
            S[jt][2] = fast_exp2(S[jt][2] - mn1); s1 += S[jt][2];
            S[jt][3] = fast_exp2(S[jt][3] - mn1); s1 += S[jt][3];
        }
#pragma unroll
        for (int off = 1; off <= 2; off <<= 1) {
            s0 += __shfl_xor_sync(0xffffffffu, s0, off);
            s1 += __shfl_xor_sync(0xffffffffu, s1, off);
        }
        l0 = l0 * al0 + s0; l1 = l1 * al1 + s1;
        m0 = mn0; m1 = mn1;
#pragma unroll
        for (int nt = 0; nt < 16; nt++) {
            O[nt][0] *= al0; O[nt][1] *= al0;
            O[nt][2] *= al1; O[nt][3] *= al1;
        }

#pragma unroll
        for (int kt = 0; kt < 4; kt++) {
            uint32_t Ph[4], Pl[4];
            {
                float p00 = S[2 * kt][0],     p01 = S[2 * kt][1];
                float p10 = S[2 * kt][2],     p11 = S[2 * kt][3];
                float p20 = S[2 * kt + 1][0], p21 = S[2 * kt + 1][1];
                float p30 = S[2 * kt + 1][2], p31 = S[2 * kt + 1][3];
                float h00 = __half2float(__float2half_rn(p00));
                float h01 = __half2float(__float2half_rn(p01));
                float h10 = __half2float(__float2half_rn(p10));
                float h11 = __half2float(__float2half_rn(p11));
                float h20 = __half2float(__float2half_rn(p20));
                float h21 = __half2float(__float2half_rn(p21));
                float h30 = __half2float(__float2half_rn(p30));
                float h31 = __half2float(__float2half_rn(p31));
                Ph[0] = pack_h(h00, h01); Ph[1] = pack_h(h10, h11);
                Ph[2] = pack_h(h20, h21); Ph[3] = pack_h(h30, h31);
                Pl[0] = pack_h(p00 - h00, p01 - h01);
                Pl[1] = pack_h(p10 - h10, p11 - h11);
                Pl[2] = pack_h(p20 - h20, p21 - h21);
                Pl[3] = pack_h(p30 - h30, p31 - h31);
            }
#pragma unroll
            for (int nt = 0; nt < 16; nt++) {
                int base = (nt * 8 + (lane >> 2)) * VSTR + kt * 16 + qpair;
                uint32_t b0 = *(const uint32_t*)&Vsh[base];
                uint32_t b1 = *(const uint32_t*)&Vsh[base + 8];
                mma16816(O[nt], Ph, b0, b1);
                mma16816(O[nt], Pl, b0, b1);
            }
        }
        __syncthreads();
    }

    float il0 = 1.0f / l0, il1 = 1.0f / l1;
#pragma unroll
    for (int nt = 0; nt < 16; nt++) {
        int d = nt * 8 + qpair;
        size_t base0 = (size_t)(b * TT + rg0) * NE + h * HD + d;
        size_t base1 = (size_t)(b * TT + rg1) * NE + h * HD + d;
        float o00 = O[nt][0] * il0, o01 = O[nt][1] * il0;
        float o10 = O[nt][2] * il1, o11 = O[nt][3] * il1;
        float h00 = __half2float(__float2half_rn(o00));
        float h01 = __half2float(__float2half_rn(o01));
        float h10 = __half2float(__float2half_rn(o10));
        float h11 = __half2float(__float2half_rn(o11));
        *(uint32_t*)&yh[base0] = pack_h(h00, h01);
        *(uint32_t*)&yl[base0] = pack_h(o00 - h00, o01 - h01);
        *(uint32_t*)&yh[base1] = pack_h(h10, h11);
        *(uint32_t*)&yl[base1] = pack_h(o10 - h10, o11 - h11);
    }
}

// ---------------------------------------------------------------------------
extern "C" void kernel_launch(void* const* d_in, const int* in_sizes, int n_in,
                              void* d_out, int out_size) {
    const float* x  = (const float*)d_in[0];
    const float* wq = (const float*)d_in[1];
    const float* wk = (const float*)d_in[2];
    const float* wv = (const float*)d_in[3];
    const float* wo = (const float*)d_in[4];
    float* out = (float*)d_out;

    __half *xh, *xl, *wqp, *wkp, *wvp, *wop, *qh, *ql, *kp, *vtp, *yh, *yl;
    cudaGetSymbolAddress((void**)&xh,  g_xh);  cudaGetSymbolAddress((void**)&xl, g_xl);
    cudaGetSymbolAddress((void**)&wqp, g_wq);  cudaGetSymbolAddress((void**)&wkp, g_wk);
    cudaGetSymbolAddress((void**)&wvp, g_wv);  cudaGetSymbolAddress((void**)&wop, g_wo);
    cudaGetSymbolAddress((void**)&qh,  g_qh);  cudaGetSymbolAddress((void**)&ql,  g_ql);
    cudaGetSymbolAddress((void**)&kp,  g_k);   cudaGetSymbolAddress((void**)&vtp, g_vt);
    cudaGetSymbolAddress((void**)&yh,  g_yh);  cudaGetSymbolAddress((void**)&yl,  g_yl);

    prep_all<<<(PREP_TOTAL + 255) / 256, 256>>>(x, wq, wk, wv, wo,
                                                xh, xl, wqp, wkp, wvp, wop);

    cudaFuncSetAttribute(gemm_qkv, cudaFuncAttributeMaxDynamicSharedMemorySize, GEMM_SMEM);
    cudaFuncSetAttribute(gemm_wo,  cudaFuncAttributeMaxDynamicSharedMemorySize, GEMM_SMEM);

    dim3 blk(256);
    gemm_qkv<<<dim3(24, 32), blk, GEMM_SMEM>>>(xh, xl, wqp, wkp, wvp,
                                               qh, ql, kp, vtp);

    cudaFuncSetAttribute(attn_mma, cudaFuncAttributeMaxDynamicSharedMemorySize, SM_ATT_BYTES);
    attn_mma<<<dim3(TT / BQ, BB * NH), blk, SM_ATT_BYTES>>>(qh, ql, kp, vtp, yh, yl);

    gemm_wo<<<dim3(16, 32), blk, GEMM_SMEM>>>(yh, yl, wop, out);
}

// round 10
// speedup vs baseline: 4.1736x; 1.0432x over previous
#include <cuda_runtime.h>
#include <cuda_fp16.h>
#include <math_constants.h>
#include <mma.h>
#include <cstdint>

using namespace nvcuda;

#define BB 2
#define TT 2048
#define NE 2048
#define NH 16
#define NKV 4
#define HD 128
#define GRP (NH / NKV)
#define MROWS (BB * TT)
#define KVE (NKV * HD)

// fp16 scratch
__device__ __half g_xh[MROWS * NE], g_xl[MROWS * NE];
__device__ __half g_wq[NE * NE];
__device__ __half g_wk[KVE * NE];
__device__ __half g_wv[KVE * NE];
__device__ __half g_wo[NE * NE];
__device__ __half g_qh[MROWS * NE], g_ql[MROWS * NE];   // (B,T,H,D) split
__device__ __half g_k[MROWS * KVE];                     // (B,T,Hkv,D)
__device__ __half g_vt[MROWS * KVE];                    // (B,Hkv,D,T)
__device__ __half g_yh[MROWS * NE], g_yl[MROWS * NE];

__device__ __forceinline__ uint32_t pack_h(float x, float y) {
    __half2 r = __floats2half2_rn(x, y);
    return *(uint32_t*)&r;
}
__device__ __forceinline__ float fast_exp2(float x) {
    float y; asm("ex2.approx.f32 %0, %1;" : "=f"(y) : "f"(x)); return y;
}
__device__ __forceinline__ void mma16816(float* c, const uint32_t* a, uint32_t b0, uint32_t b1) {
    asm volatile("mma.sync.aligned.m16n8k16.row.col.f32.f16.f16.f32 "
                 "{%0,%1,%2,%3}, {%4,%5,%6,%7}, {%8,%9}, {%0,%1,%2,%3};\n"
                 : "+f"(c[0]), "+f"(c[1]), "+f"(c[2]), "+f"(c[3])
                 : "r"(a[0]), "r"(a[1]), "r"(a[2]), "r"(a[3]), "r"(b0), "r"(b1));
}
__device__ __forceinline__ void cp16(__half* s, const __half* g) {
    uint32_t sa = (uint32_t)__cvta_generic_to_shared(s);
    asm volatile("cp.async.cg.shared.global [%0], [%1], 16;" :: "r"(sa), "l"(g));
}

// ---------------------------------------------------------------------------
// Fused prep: split x -> (xh,xl); convert wq/wk/wv/wo -> fp16
// ---------------------------------------------------------------------------
#define NX4  (MROWS * NE / 4)
#define NW4  (NE * NE / 4)
#define NWK4 (KVE * NE / 4)
#define PREP_TOTAL (NX4 + NW4 + 2 * NWK4 + NW4)

__global__ __launch_bounds__(256) void prep_all(
    const float* __restrict__ x,  const float* __restrict__ wq,
    const float* __restrict__ wk, const float* __restrict__ wv,
    const float* __restrict__ wo,
    __half* __restrict__ xh, __half* __restrict__ xl,
    __half* __restrict__ wqp, __half* __restrict__ wkp,
    __half* __restrict__ wvp, __half* __restrict__ wop)
{
    int i = blockIdx.x * blockDim.x + threadIdx.x;
    if (i >= PREP_TOTAL) return;
    if (i < NX4) {
        float4 v = ((const float4*)x)[i];
        union { __half b[4]; uint2 u; } H, L;
        float vv[4] = {v.x, v.y, v.z, v.w};
#pragma unroll
        for (int j = 0; j < 4; j++) {
            __half h = __float2half_rn(vv[j]);
            H.b[j] = h;
            L.b[j] = __float2half_rn(vv[j] - __half2float(h));
        }
        ((uint2*)xh)[i] = H.u;
        ((uint2*)xl)[i] = L.u;
        return;
    }
    const float* src; __half* dst; int j;
    i -= NX4;
    if (i < NW4)                { src = wq; dst = wqp; j = i; }
    else if (i < NW4 + NWK4)    { src = wk; dst = wkp; j = i - NW4; }
    else if (i < NW4 + 2*NWK4)  { src = wv; dst = wvp; j = i - NW4 - NWK4; }
    else                        { src = wo; dst = wop; j = i - NW4 - 2*NWK4; }
    float4 v = ((const float4*)src)[j];
    union { __half b[4]; uint2 u; } H;
    H.b[0] = __float2half_rn(v.x); H.b[1] = __float2half_rn(v.y);
    H.b[2] = __float2half_rn(v.z); H.b[3] = __float2half_rn(v.w);
    ((uint2*)dst)[j] = H.u;
}

// ---------------------------------------------------------------------------
// GEMM core: 3-stage cp.async, K-step 32, fp16 2-term (A split, B single).
// Block tile 128x128, 256 threads (8 warps 2x4), warp tile 64x32.
// Sized for 2 CTAs/SM: 92,160 B smem/CTA, <=128 regs (a-frags loaded per-i).
// ---------------------------------------------------------------------------
#define TBM 128
#define TBN 128
#define TBK 32
#define TLD 40
#define TILE_ELEMS (TBM * TLD)     // 5120 halves
#define NSTAGE 3
#define SEPI 132
#define GEMM_SMEM (NSTAGE * 3 * TILE_ELEMS * 2)   // 92,160 B

__device__ __forceinline__ void g_load_stage(
    __half* gsm, int st, int kb, int t,
    const __half* Ah, const __half* Al, const __half* B,
    int row0, int col0, int K)
{
    __half* tAh = gsm + (st * 3 + 0) * TILE_ELEMS;
    __half* tAl = gsm + (st * 3 + 1) * TILE_ELEMS;
    __half* tB  = gsm + (st * 3 + 2) * TILE_ELEMS;
#pragma unroll
    for (int i = 0; i < 2; i++) {
        int p = t + i * 256;              // 0..511
        int r = p >> 2, ch = p & 3;       // row, 16B chunk
        size_t ga = (size_t)(row0 + r) * K + kb * TBK + ch * 8;
        size_t gb = (size_t)(col0 + r) * K + kb * TBK + ch * 8;
        int so = r * TLD + ch * 8;
        cp16(tAh + so, Ah + ga);
        cp16(tAl + so, Al + ga);
        cp16(tB  + so, B  + gb);
    }
    asm volatile("cp.async.commit_group;" ::: "memory");
}

__device__ __forceinline__ void g_core(
    __half* gsm, int t,
    const __half* Ah, const __half* Al, const __half* B,
    int row0, int col0, int K)
{
    const int w  = t >> 5;
    const int wm = w & 1;
    const int wn = w >> 1;

    wmma::fragment<wmma::accumulator, 16, 16, 16, float> acc[4][2];
#pragma unroll
    for (int i = 0; i < 4; i++)
#pragma unroll
        for (int j = 0; j < 2; j++) wmma::fill_fragment(acc[i][j], 0.0f);

    const int nk = K / TBK;
    g_load_stage(gsm, 0, 0, t, Ah, Al, B, row0, col0, K);
    g_load_stage(gsm, 1, 1, t, Ah, Al, B, row0, col0, K);

    for (int kb = 0; kb < nk; kb++) {
        const int cur = kb % NSTAGE;
        if (kb + 2 < nk) {
            g_load_stage(gsm, (kb + 2) % NSTAGE, kb + 2, t, Ah, Al, B, row0, col0, K);
            asm volatile("cp.async.wait_group 2;" ::: "memory");
        } else if (kb + 1 < nk) {
            asm volatile("cp.async.wait_group 1;" ::: "memory");
        } else {
            asm volatile("cp.async.wait_group 0;" ::: "memory");
        }
        __syncthreads();

        const __half* tAh = gsm + (cur * 3 + 0) * TILE_ELEMS;
        const __half* tAl = gsm + (cur * 3 + 1) * TILE_ELEMS;
        const __half* tB  = gsm + (cur * 3 + 2) * TILE_ELEMS;

#pragma unroll
        for (int kk = 0; kk < TBK; kk += 16) {
            wmma::fragment<wmma::matrix_b, 16, 16, 16, __half, wmma::col_major> bf[2];
#pragma unroll
            for (int j = 0; j < 2; j++)
                wmma::load_matrix_sync(bf[j], tB + (wn * 32 + j * 16) * TLD + kk, TLD);
            // Load a-frags per-i to keep live registers <=128 (2 CTAs/SM).
#pragma unroll
            for (int i = 0; i < 4; i++) {
                wmma::fragment<wmma::matrix_a, 16, 16, 16, __half, wmma::row_major> ah, al;
                wmma::load_matrix_sync(ah, tAh + (wm * 64 + i * 16) * TLD + kk, TLD);
                wmma::load_matrix_sync(al, tAl + (wm * 64 + i * 16) * TLD + kk, TLD);
#pragma unroll
                for (int j = 0; j < 2; j++) {
                    wmma::mma_sync(acc[i][j], ah, bf[j], acc[i][j]);
                    wmma::mma_sync(acc[i][j], al, bf[j], acc[i][j]);
                }
            }
        }
        __syncthreads();
    }

    float* smf = (float*)gsm;
#pragma unroll
    for (int i = 0; i < 4; i++)
#pragma unroll
        for (int j = 0; j < 2; j++)
            wmma::store_matrix_sync(&smf[(wm * 64 + i * 16) * SEPI + wn * 32 + j * 16],
                                    acc[i][j], SEPI, wmma::mem_row_major);
    __syncthreads();
}

// Fused Q/K/V projection. grid = (24, 32). 2 CTAs/SM.
__global__ __launch_bounds__(256, 2) void gemm_qkv(
    const __half* __restrict__ xh, const __half* __restrict__ xl,
    const __half* __restrict__ wq, const __half* __restrict__ wk,
    const __half* __restrict__ wv,
    __half* __restrict__ qh, __half* __restrict__ ql,
    __half* __restrict__ kp, __half* __restrict__ vtp)
{
    extern __shared__ __half gsm[];
    const int t  = threadIdx.x;
    const int bx = blockIdx.x;
    const int row0 = blockIdx.y * TBM;

    const __half* B; int mode, N, cb;
    if (bx < 16)      { B = wq; mode = 1; N = NE;  cb = bx; }
    else if (bx < 20) { B = wk; mode = 2; N = KVE; cb = bx - 16; }
    else              { B = wv; mode = 3; N = KVE; cb = bx - 20; }
    const int col0 = cb * TBN;

    g_core(gsm, t, xh, xl, B, row0, col0, NE);
    float* smf = (float*)gsm;

    if (mode == 1) {
#pragma unroll
        for (int i = 0; i < 32; i++) {
            int p = t + i * 256;
            int r = p >> 6, c2 = (p & 63) * 2;
            float x0 = smf[r * SEPI + c2], x1 = smf[r * SEPI + c2 + 1];
            float h0 = __half2float(__float2half_rn(x0));
            float h1 = __half2float(__float2half_rn(x1));
            size_t gidx = (size_t)(row0 + r) * N + col0 + c2;
            *(uint32_t*)&qh[gidx] = pack_h(h0, h1);
            *(uint32_t*)&ql[gidx] = pack_h(x0 - h0, x1 - h1);
        }
    } else if (mode == 2) {
#pragma unroll
        for (int i = 0; i < 32; i++) {
            int p = t + i * 256;
            int r = p >> 6, c2 = (p & 63) * 2;
            float x0 = smf[r * SEPI + c2], x1 = smf[r * SEPI + c2 + 1];
            size_t gidx = (size_t)(row0 + r) * N + col0 + c2;
            *(uint32_t*)&kp[gidx] = pack_h(x0, x1);
        }
    } else {
        const int b  = row0 >> 11;
        const int t0 = row0 & 2047;
        const int hk = col0 >> 7;
#pragma unroll
        for (int i = 0; i < 32; i++) {
            int p = t + i * 256;
            int c = p >> 6, rp = (p & 63) * 2;
            float x0 = smf[rp * SEPI + c], x1 = smf[(rp + 1) * SEPI + c];
            size_t gidx = ((size_t)(b * NKV + hk) * HD + c) * TT + t0 + rp;
            *(uint32_t*)&vtp[gidx] = pack_h(x0, x1);
        }
    }
}

// Output projection: fp32 out. grid = (16, 32). 2 CTAs/SM.
__global__ __launch_bounds__(256, 2) void gemm_wo(
    const __half* __restrict__ yh, const __half* __restrict__ yl,
    const __half* __restrict__ wo, float* __restrict__ out)
{
    extern __shared__ __half gsm[];
    const int t = threadIdx.x;
    const int row0 = blockIdx.y * TBM;
    const int col0 = blockIdx.x * TBN;

    g_core(gsm, t, yh, yl, wo, row0, col0, NE);
    float* smf = (float*)gsm;
#pragma unroll
    for (int i = 0; i < 32; i++) {
        int p = t + i * 256;
        int r = p >> 6, c2 = (p & 63) * 2;
        float2 v = *(float2*)&smf[r * SEPI + c2];
        *(float2*)&out[(size_t)(row0 + r) * NE + col0 + c2] = v;
    }
}

// ---------------------------------------------------------------------------
// FA2 mma.sync causal GQA attention (unchanged from R8/R9).
// ---------------------------------------------------------------------------
#define BQ 128
#define BKV 64
#define KSTR 136
#define VSTR 72
#define KTILE (BKV * KSTR)
#define VTILE (HD * VSTR)
#define ASTAGE (KTILE + VTILE)
#define SM_ATT_BYTES (2 * ASTAGE * 2)

__global__ __launch_bounds__(256, 1) void attn_mma(
    const __half* __restrict__ qh, const __half* __restrict__ ql,
    const __half* __restrict__ kf, const __half* __restrict__ vtf,
    __half* __restrict__ yh, __half* __restrict__ yl) {
    extern __shared__ __half smA[];

    const int t    = threadIdx.x;
    const int w    = t >> 5;
    const int lane = t & 31;
    const int qb   = (gridDim.x - 1) - blockIdx.x;
    const int bh   = blockIdx.y;
    const int b    = bh >> 4;
    const int h    = bh & 15;
    const int hk   = h / GRP;
    const int q0   = qb * BQ;
    const int rg0  = q0 + w * 16 + (lane >> 2);
    const int rg1  = rg0 + 8;
    const int qpair = (lane & 3) * 2;

    uint32_t Qh[8][4], Ql[8][4];
#pragma unroll
    for (int kt = 0; kt < 8; kt++) {
#pragma unroll
        for (int half = 0; half < 2; half++) {
#pragma unroll
            for (int ri = 0; ri < 2; ri++) {
                int row = ri ? rg1 : rg0;
                size_t gi = ((size_t)(b * TT + row) * NH + h) * HD + kt * 16 + half * 8 + qpair;
                Qh[kt][half * 2 + ri] = *(const uint32_t*)&qh[gi];
                Ql[kt][half * 2 + ri] = *(const uint32_t*)&ql[gi];
            }
        }
    }

    float O[16][4];
#pragma unroll
    for (int nt = 0; nt < 16; nt++)
#pragma unroll
        for (int e = 0; e < 4; e++) O[nt][e] = 0.0f;
    float m0 = -CUDART_INF_F, m1 = -CUDART_INF_F, l0 = 0.0f, l1 = 0.0f;

    const float SCL = 0.08838834764831845f * 1.4426950408889634f;
    const int kb_end = 2 * qb + 2;

    auto fill = [&](int st, int kb) {
        __half* Ksh = smA + st * ASTAGE;
        __half* Vsh = Ksh + KTILE;
        const int k0 = kb * BKV;
#pragma unroll
        for (int i = 0; i < 4; i++) {
            int p = t + i * 256;
            int c = p >> 4, ch = p & 15;
            size_t g = ((size_t)(b * TT + k0 + c) * NKV + hk) * HD + ch * 8;
            cp16(Ksh + c * KSTR + ch * 8, kf + g);
        }
#pragma unroll
        for (int i = 0; i < 4; i++) {
            int p = t + i * 256;
            int d = p >> 3, ch = p & 7;
            size_t g = ((size_t)(b * NKV + hk) * HD + d) * TT + k0 + ch * 8;
            cp16(Vsh + d * VSTR + ch * 8, vtf + g);
        }
        asm volatile("cp.async.commit_group;" ::: "memory");
    };

    fill(0, 0);

    for (int kb = 0; kb < kb_end; kb++) {
        const int cur = kb & 1;
        const int k0 = kb * BKV;
        if (kb + 1 < kb_end) {
            fill(cur ^ 1, kb + 1);
            asm volatile("cp.async.wait_group 1;" ::: "memory");
        } else {
            asm volatile("cp.async.wait_group 0;" ::: "memory");
        }
        __syncthreads();

        const __half* Ksh = smA + cur * ASTAGE;
        const __half* Vsh = Ksh + KTILE;

        float S[8][4];
#pragma unroll
        for (int jt = 0; jt < 8; jt++)
#pragma unroll
            for (int e = 0; e < 4; e++) S[jt][e] = 0.0f;

#pragma unroll
        for (int kt = 0; kt < 8; kt++) {
#pragma unroll
            for (int jt = 0; jt < 8; jt++) {
                int base = (jt * 8 + (lane >> 2)) * KSTR + kt * 16 + qpair;
                uint32_t b0 = *(const uint32_t*)&Ksh[base];
                uint32_t b1 = *(const uint32_t*)&Ksh[base + 8];
                mma16816(S[jt], Qh[kt], b0, b1);
                mma16816(S[jt], Ql[kt], b0, b1);
            }
        }

        const bool diag = (kb >= 2 * qb);
#pragma unroll
        for (int jt = 0; jt < 8; jt++) {
            int c0 = k0 + jt * 8 + qpair;
            S[jt][0] *= SCL; S[jt][1] *= SCL; S[jt][2] *= SCL; S[jt][3] *= SCL;
            if (diag) {
                if (c0 > rg0)     S[jt][0] = -CUDART_INF_F;
                if (c0 + 1 > rg0) S[jt][1] = -CUDART_INF_F;
                if (c0 > rg1)     S[jt][2] = -CUDART_INF_F;
                if (c0 + 1 > rg1) S[jt][3] = -CUDART_INF_F;
            }
        }

        float mx0 = -CUDART_INF_F, mx1 = -CUDART_INF_F;
#pragma unroll
        for (int jt = 0; jt < 8; jt++) {
            mx0 = fmaxf(mx0, fmaxf(S[jt][0], S[jt][1]));
            mx1 = fmaxf(mx1, fmaxf(S[jt][2], S[jt][3]));
        }
#pragma unroll
        for (int off = 1; off <= 2; off <<= 1) {
            mx0 = fmaxf(mx0, __shfl_xor_sync(0xffffffffu, mx0, off));
            mx1 = fmaxf(mx1, __shfl_xor_sync(0xffffffffu, mx1, off));
        }
        float mn0 = fmaxf(m0, mx0), mn1 = fmaxf(m1, mx1);
        float al0 = fast_exp2(m0 - mn0), al1 = fast_exp2(m1 - mn1);
        float s0 = 0.0f, s1 = 0.0f;
#pragma unroll
        for (int jt = 0; jt < 8; jt++) {
            S[jt][0] = fast_exp2(S[jt][0] - mn0); s0 += S[jt][0];
            S[jt][1] = fast_exp2(S[jt][1] - mn0); s0 += S[jt][1];
            S[jt][2] = fast_exp2(S[jt][2] - mn1); s1 += S[jt][2];
            S[jt][3] = fast_exp2(S[jt][3] - mn1); s1 += S[jt][3];
        }
#pragma unroll
        for (int off = 1; off <= 2; off <<= 1) {
            s0 += __shfl_xor_sync(0xffffffffu, s0, off);
            s1 += __shfl_xor_sync(0xffffffffu, s1, off);
        }
        l0 = l0 * al0 + s0; l1 = l1 * al1 + s1;
        m0 = mn0; m1 = mn1;
#pragma unroll
        for (int nt = 0; nt < 16; nt++) {
            O[nt][0] *= al0; O[nt][1] *= al0;
            O[nt][2] *= al1; O[nt][3] *= al1;
        }

#pragma unroll
        for (int kt = 0; kt < 4; kt++) {
            uint32_t Ph[4], Pl[4];
            {
                float p00 = S[2 * kt][0],     p01 = S[2 * kt][1];
                float p10 = S[2 * kt][2],     p11 = S[2 * kt][3];
                float p20 = S[2 * kt + 1][0], p21 = S[2 * kt + 1][1];
                float p30 = S[2 * kt + 1][2], p31 = S[2 * kt + 1][3];
                float h00 = __half2float(__float2half_rn(p00));
                float h01 = __half2float(__float2half_rn(p01));
                float h10 = __half2float(__float2half_rn(p10));
                float h11 = __half2float(__float2half_rn(p11));
                float h20 = __half2float(__float2half_rn(p20));
                float h21 = __half2float(__float2half_rn(p21));
                float h30 = __half2float(__float2half_rn(p30));
                float h31 = __half2float(__float2half_rn(p31));
                Ph[0] = pack_h(h00, h01); Ph[1] = pack_h(h10, h11);
                Ph[2] = pack_h(h20, h21); Ph[3] = pack_h(h30, h31);
                Pl[0] = pack_h(p00 - h00, p01 - h01);
                Pl[1] = pack_h(p10 - h10, p11 - h11);
                Pl[2] = pack_h(p20 - h20, p21 - h21);
                Pl[3] = pack_h(p30 - h30, p31 - h31);
            }
#pragma unroll
            for (int nt = 0; nt < 16; nt++) {
                int base = (nt * 8 + (lane >> 2)) * VSTR + kt * 16 + qpair;
                uint32_t b0 = *(const uint32_t*)&Vsh[base];
                uint32_t b1 = *(const uint32_t*)&Vsh[base + 8];
                mma16816(O[nt], Ph, b0, b1);
                mma16816(O[nt], Pl, b0, b1);
            }
        }
        __syncthreads();
    }

    float il0 = 1.0f / l0, il1 = 1.0f / l1;
#pragma unroll
    for (int nt = 0; nt < 16; nt++) {
        int d = nt * 8 + qpair;
        size_t base0 = (size_t)(b * TT + rg0) * NE + h * HD + d;
        size_t base1 = (size_t)(b * TT + rg1) * NE + h * HD + d;
        float o00 = O[nt][0] * il0, o01 = O[nt][1] * il0;
        float o10 = O[nt][2] * il1, o11 = O[nt][3] * il1;
        float h00 = __half2float(__float2half_rn(o00));
        float h01 = __half2float(__float2half_rn(o01));
        float h10 = __half2float(__float2half_rn(o10));
        float h11 = __half2float(__float2half_rn(o11));
        *(uint32_t*)&yh[base0] = pack_h(h00, h01);
        *(uint32_t*)&yl[base0] = pack_h(o00 - h00, o01 - h01);
        *(uint32_t*)&yh[base1] = pack_h(h10, h11);
        *(uint32_t*)&yl[base1] = pack_h(o10 - h10, o11 - h11);
    }
}

// ---------------------------------------------------------------------------
extern "C" void kernel_launch(void* const* d_in, const int* in_sizes, int n_in,
                              void* d_out, int out_size) {
    const float* x  = (const float*)d_in[0];
    const float* wq = (const float*)d_in[1];
    const float* wk = (const float*)d_in[2];
    const float* wv = (const float*)d_in[3];
    const float* wo = (const float*)d_in[4];
    float* out = (float*)d_out;

    __half *xh, *xl, *wqp, *wkp, *wvp, *wop, *qh, *ql, *kp, *vtp, *yh, *yl;
    cudaGetSymbolAddress((void**)&xh,  g_xh);  cudaGetSymbolAddress((void**)&xl, g_xl);
    cudaGetSymbolAddress((void**)&wqp, g_wq);  cudaGetSymbolAddress((void**)&wkp, g_wk);
    cudaGetSymbolAddress((void**)&wvp, g_wv);  cudaGetSymbolAddress((void**)&wop, g_wo);
    cudaGetSymbolAddress((void**)&qh,  g_qh);  cudaGetSymbolAddress((void**)&ql,  g_ql);
    cudaGetSymbolAddress((void**)&kp,  g_k);   cudaGetSymbolAddress((void**)&vtp, g_vt);
    cudaGetSymbolAddress((void**)&yh,  g_yh);  cudaGetSymbolAddress((void**)&yl,  g_yl);

    prep_all<<<(PREP_TOTAL + 255) / 256, 256>>>(x, wq, wk, wv, wo,
                                                xh, xl, wqp, wkp, wvp, wop);

    cudaFuncSetAttribute(gemm_qkv, cudaFuncAttributeMaxDynamicSharedMemorySize, GEMM_SMEM);
    cudaFuncSetAttribute(gemm_wo,  cudaFuncAttributeMaxDynamicSharedMemorySize, GEMM_SMEM);

    dim3 blk(256);
    gemm_qkv<<<dim3(24, 32), blk, GEMM_SMEM>>>(xh, xl, wqp, wkp, wvp,
                                               qh, ql, kp, vtp);

    cudaFuncSetAttribute(attn_mma, cudaFuncAttributeMaxDynamicSharedMemorySize, SM_ATT_BYTES);
    attn_mma<<<dim3(TT / BQ, BB * NH), blk, SM_ATT_BYTES>>>(qh, ql, kp, vtp, yh, yl);

    gemm_wo<<<dim3(16, 32), blk, GEMM_SMEM>>>(yh, yl, wop, out);
}

// round 11
// speedup vs baseline: 4.4162x; 1.0581x over previous
#include <cuda_runtime.h>
#include <cuda_fp16.h>
#include <math_constants.h>
#include <mma.h>
#include <cstdint>

using namespace nvcuda;

#define BB 2
#define TT 2048
#define NE 2048
#define NH 16
#define NKV 4
#define HD 128
#define GRP (NH / NKV)
#define MROWS (BB * TT)
#define KVE (NKV * HD)

// fp16 scratch
__device__ __half g_xh[MROWS * NE], g_xl[MROWS * NE];
__device__ __half g_wq[NE * NE];
__device__ __half g_wk[KVE * NE];
__device__ __half g_wv[KVE * NE];
__device__ __half g_wo[NE * NE];
__device__ __half g_qh[MROWS * NE], g_ql[MROWS * NE];   // (B,T,H,D) split
__device__ __half g_k[MROWS * KVE];                     // (B,T,Hkv,D)
__device__ __half g_vt[MROWS * KVE];                    // (B,Hkv,D,T)
__device__ __half g_yh[MROWS * NE], g_yl[MROWS * NE];

__device__ __forceinline__ uint32_t pack_h(float x, float y) {
    __half2 r = __floats2half2_rn(x, y);
    return *(uint32_t*)&r;
}
__device__ __forceinline__ float fast_exp2(float x) {
    float y; asm("ex2.approx.f32 %0, %1;" : "=f"(y) : "f"(x)); return y;
}
__device__ __forceinline__ void mma16816(float* c, const uint32_t* a, uint32_t b0, uint32_t b1) {
    asm volatile("mma.sync.aligned.m16n8k16.row.col.f32.f16.f16.f32 "
                 "{%0,%1,%2,%3}, {%4,%5,%6,%7}, {%8,%9}, {%0,%1,%2,%3};\n"
                 : "+f"(c[0]), "+f"(c[1]), "+f"(c[2]), "+f"(c[3])
                 : "r"(a[0]), "r"(a[1]), "r"(a[2]), "r"(a[3]), "r"(b0), "r"(b1));
}
__device__ __forceinline__ void cp16(__half* s, const __half* g) {
    uint32_t sa = (uint32_t)__cvta_generic_to_shared(s);
    asm volatile("cp.async.cg.shared.global [%0], [%1], 16;" :: "r"(sa), "l"(g));
}

// ---------------------------------------------------------------------------
// Fused prep: split x -> (xh,xl); convert wq/wk/wv/wo -> fp16
// ---------------------------------------------------------------------------
#define NX4  (MROWS * NE / 4)
#define NW4  (NE * NE / 4)
#define NWK4 (KVE * NE / 4)
#define PREP_TOTAL (NX4 + NW4 + 2 * NWK4 + NW4)

__global__ __launch_bounds__(256) void prep_all(
    const float* __restrict__ x,  const float* __restrict__ wq,
    const float* __restrict__ wk, const float* __restrict__ wv,
    const float* __restrict__ wo,
    __half* __restrict__ xh, __half* __restrict__ xl,
    __half* __restrict__ wqp, __half* __restrict__ wkp,
    __half* __restrict__ wvp, __half* __restrict__ wop)
{
    int i = blockIdx.x * blockDim.x + threadIdx.x;
    if (i >= PREP_TOTAL) return;
    if (i < NX4) {
        float4 v = ((const float4*)x)[i];
        union { __half b[4]; uint2 u; } H, L;
        float vv[4] = {v.x, v.y, v.z, v.w};
#pragma unroll
        for (int j = 0; j < 4; j++) {
            __half h = __float2half_rn(vv[j]);
            H.b[j] = h;
            L.b[j] = __float2half_rn(vv[j] - __half2float(h));
        }
        ((uint2*)xh)[i] = H.u;
        ((uint2*)xl)[i] = L.u;
        return;
    }
    const float* src; __half* dst; int j;
    i -= NX4;
    if (i < NW4)                { src = wq; dst = wqp; j = i; }
    else if (i < NW4 + NWK4)    { src = wk; dst = wkp; j = i - NW4; }
    else if (i < NW4 + 2*NWK4)  { src = wv; dst = wvp; j = i - NW4 - NWK4; }
    else                        { src = wo; dst = wop; j = i - NW4 - 2*NWK4; }
    float4 v = ((const float4*)src)[j];
    union { __half b[4]; uint2 u; } H;
    H.b[0] = __float2half_rn(v.x); H.b[1] = __float2half_rn(v.y);
    H.b[2] = __float2half_rn(v.z); H.b[3] = __float2half_rn(v.w);
    ((uint2*)dst)[j] = H.u;
}

// ---------------------------------------------------------------------------
// GEMM core: 2-stage cp.async, K-step 64, fp16 2-term (A split, B single).
// Block tile 128x128, 256 threads, 8 warps as 4x2, warp tile 32x64.
// 110,592 B smem/CTA -> 2 CTAs/SM; <=128 regs.
// ---------------------------------------------------------------------------
#define TBM 128
#define TBN 128
#define TBK 64
#define TLD 72
#define TILE_ELEMS (TBM * TLD)     // 9216 halves
#define NSTAGE 2
#define SEPI 132
#define GEMM_SMEM (NSTAGE * 3 * TILE_ELEMS * 2)   // 110,592 B

__device__ __forceinline__ void g_load_stage(
    __half* gsm, int st, int kb, int t,
    const __half* Ah, const __half* Al, const __half* B,
    int row0, int col0, int K)
{
    __half* tAh = gsm + (st * 3 + 0) * TILE_ELEMS;
    __half* tAl = gsm + (st * 3 + 1) * TILE_ELEMS;
    __half* tB  = gsm + (st * 3 + 2) * TILE_ELEMS;
#pragma unroll
    for (int i = 0; i < 4; i++) {
        int p = t + i * 256;              // 0..1023
        int r = p >> 3, ch = p & 7;       // row, 16B chunk
        size_t ga = (size_t)(row0 + r) * K + kb * TBK + ch * 8;
        size_t gb = (size_t)(col0 + r) * K + kb * TBK + ch * 8;
        int so = r * TLD + ch * 8;
        cp16(tAh + so, Ah + ga);
        cp16(tAl + so, Al + ga);
        cp16(tB  + so, B  + gb);
    }
    asm volatile("cp.async.commit_group;" ::: "memory");
}

__device__ __forceinline__ void g_core(
    __half* gsm, int t,
    const __half* Ah, const __half* Al, const __half* B,
    int row0, int col0, int K)
{
    const int w  = t >> 5;
    const int wm = w & 3;     // 0..3 : 32-row group
    const int wn = w >> 2;    // 0..1 : 64-col group

    wmma::fragment<wmma::accumulator, 16, 16, 16, float> acc[2][4];
#pragma unroll
    for (int i = 0; i < 2; i++)
#pragma unroll
        for (int j = 0; j < 4; j++) wmma::fill_fragment(acc[i][j], 0.0f);

    const int nk = K / TBK;
    g_load_stage(gsm, 0, 0, t, Ah, Al, B, row0, col0, K);

    for (int kb = 0; kb < nk; kb++) {
        const int cur = kb & 1;
        if (kb + 1 < nk) {
            g_load_stage(gsm, cur ^ 1, kb + 1, t, Ah, Al, B, row0, col0, K);
            asm volatile("cp.async.wait_group 1;" ::: "memory");
        } else {
            asm volatile("cp.async.wait_group 0;" ::: "memory");
        }
        __syncthreads();

        const __half* tAh = gsm + (cur * 3 + 0) * TILE_ELEMS;
        const __half* tAl = gsm + (cur * 3 + 1) * TILE_ELEMS;
        const __half* tB  = gsm + (cur * 3 + 2) * TILE_ELEMS;

#pragma unroll
        for (int kk = 0; kk < TBK; kk += 16) {
            wmma::fragment<wmma::matrix_b, 16, 16, 16, __half, wmma::col_major> bf[4];
#pragma unroll
            for (int j = 0; j < 4; j++)
                wmma::load_matrix_sync(bf[j], tB + (wn * 64 + j * 16) * TLD + kk, TLD);
#pragma unroll
            for (int i = 0; i < 2; i++) {
                wmma::fragment<wmma::matrix_a, 16, 16, 16, __half, wmma::row_major> ah, al;
                wmma::load_matrix_sync(ah, tAh + (wm * 32 + i * 16) * TLD + kk, TLD);
                wmma::load_matrix_sync(al, tAl + (wm * 32 + i * 16) * TLD + kk, TLD);
#pragma unroll
                for (int j = 0; j < 4; j++) {
                    wmma::mma_sync(acc[i][j], ah, bf[j], acc[i][j]);
                    wmma::mma_sync(acc[i][j], al, bf[j], acc[i][j]);
                }
            }
        }
        __syncthreads();
    }

    float* smf = (float*)gsm;
#pragma unroll
    for (int i = 0; i < 2; i++)
#pragma unroll
        for (int j = 0; j < 4; j++)
            wmma::store_matrix_sync(&smf[(wm * 32 + i * 16) * SEPI + wn * 64 + j * 16],
                                    acc[i][j], SEPI, wmma::mem_row_major);
    __syncthreads();
}

// Fused Q/K/V projection. grid = (24, 32). 2 CTAs/SM.
__global__ __launch_bounds__(256, 2) void gemm_qkv(
    const __half* __restrict__ xh, const __half* __restrict__ xl,
    const __half* __restrict__ wq, const __half* __restrict__ wk,
    const __half* __restrict__ wv,
    __half* __restrict__ qh, __half* __restrict__ ql,
    __half* __restrict__ kp, __half* __restrict__ vtp)
{
    extern __shared__ __half gsm[];
    const int t  = threadIdx.x;
    const int bx = blockIdx.x;
    const int row0 = blockIdx.y * TBM;

    const __half* B; int mode, N, cb;
    if (bx < 16)      { B = wq; mode = 1; N = NE;  cb = bx; }
    else if (bx < 20) { B = wk; mode = 2; N = KVE; cb = bx - 16; }
    else              { B = wv; mode = 3; N = KVE; cb = bx - 20; }
    const int col0 = cb * TBN;

    g_core(gsm, t, xh, xl, B, row0, col0, NE);
    float* smf = (float*)gsm;

    if (mode == 1) {
#pragma unroll
        for (int i = 0; i < 32; i++) {
            int p = t + i * 256;
            int r = p >> 6, c2 = (p & 63) * 2;
            float x0 = smf[r * SEPI + c2], x1 = smf[r * SEPI + c2 + 1];
            float h0 = __half2float(__float2half_rn(x0));
            float h1 = __half2float(__float2half_rn(x1));
            size_t gidx = (size_t)(row0 + r) * N + col0 + c2;
            *(uint32_t*)&qh[gidx] = pack_h(h0, h1);
            *(uint32_t*)&ql[gidx] = pack_h(x0 - h0, x1 - h1);
        }
    } else if (mode == 2) {
#pragma unroll
        for (int i = 0; i < 32; i++) {
            int p = t + i * 256;
            int r = p >> 6, c2 = (p & 63) * 2;
            float x0 = smf[r * SEPI + c2], x1 = smf[r * SEPI + c2 + 1];
            size_t gidx = (size_t)(row0 + r) * N + col0 + c2;
            *(uint32_t*)&kp[gidx] = pack_h(x0, x1);
        }
    } else {
        const int b  = row0 >> 11;
        const int t0 = row0 & 2047;
        const int hk = col0 >> 7;
#pragma unroll
        for (int i = 0; i < 32; i++) {
            int p = t + i * 256;
            int c = p >> 6, rp = (p & 63) * 2;
            float x0 = smf[rp * SEPI + c], x1 = smf[(rp + 1) * SEPI + c];
            size_t gidx = ((size_t)(b * NKV + hk) * HD + c) * TT + t0 + rp;
            *(uint32_t*)&vtp[gidx] = pack_h(x0, x1);
        }
    }
}

// Output projection: fp32 out. grid = (16, 32). 2 CTAs/SM.
__global__ __launch_bounds__(256, 2) void gemm_wo(
    const __half* __restrict__ yh, const __half* __restrict__ yl,
    const __half* __restrict__ wo, float* __restrict__ out)
{
    extern __shared__ __half gsm[];
    const int t = threadIdx.x;
    const int row0 = blockIdx.y * TBM;
    const int col0 = blockIdx.x * TBN;

    g_core(gsm, t, yh, yl, wo, row0, col0, NE);
    float* smf = (float*)gsm;
#pragma unroll
    for (int i = 0; i < 32; i++) {
        int p = t + i * 256;
        int r = p >> 6, c2 = (p & 63) * 2;
        float2 v = *(float2*)&smf[r * SEPI + c2];
        *(float2*)&out[(size_t)(row0 + r) * NE + col0 + c2] = v;
    }
}

// ---------------------------------------------------------------------------
// FA2 mma.sync causal GQA attention, fp16 2-term, KV tile 128.
// CTA: 128 Q rows, 8 warps. Double-buffered cp.async.
// ---------------------------------------------------------------------------
#define BQ 128
#define BKV 128
#define KSTR 136                      // 128 d + 8 pad
#define VSTR 136                      // 128 t + 8 pad
#define KTILE (BKV * KSTR)            // 17408 halves
#define VTILE (HD * VSTR)             // 17408 halves
#define ASTAGE (KTILE + VTILE)        // 34816 halves
#define SM_ATT_BYTES (2 * ASTAGE * 2) // 139,264 B

__global__ __launch_bounds__(256, 1) void attn_mma(
    const __half* __restrict__ qh, const __half* __restrict__ ql,
    const __half* __restrict__ kf, const __half* __restrict__ vtf,
    __half* __restrict__ yh, __half* __restrict__ yl) {
    extern __shared__ __half smA[];

    const int t    = threadIdx.x;
    const int w    = t >> 5;
    const int lane = t & 31;
    const int qb   = (gridDim.x - 1) - blockIdx.x;   // heavy CTAs first
    const int bh   = blockIdx.y;
    const int b    = bh >> 4;
    const int h    = bh & 15;
    const int hk   = h / GRP;
    const int q0   = qb * BQ;
    const int rg0  = q0 + w * 16 + (lane >> 2);
    const int rg1  = rg0 + 8;
    const int qpair = (lane & 3) * 2;

    uint32_t Qh[8][4], Ql[8][4];
#pragma unroll
    for (int kt = 0; kt < 8; kt++) {
#pragma unroll
        for (int half = 0; half < 2; half++) {
#pragma unroll
            for (int ri = 0; ri < 2; ri++) {
                int row = ri ? rg1 : rg0;
                size_t gi = ((size_t)(b * TT + row) * NH + h) * HD + kt * 16 + half * 8 + qpair;
                Qh[kt][half * 2 + ri] = *(const uint32_t*)&qh[gi];
                Ql[kt][half * 2 + ri] = *(const uint32_t*)&ql[gi];
            }
        }
    }

    float O[16][4];
#pragma unroll
    for (int nt = 0; nt < 16; nt++)
#pragma unroll
        for (int e = 0; e < 4; e++) O[nt][e] = 0.0f;
    float m0 = -CUDART_INF_F, m1 = -CUDART_INF_F, l0 = 0.0f, l1 = 0.0f;

    const float SCL = 0.08838834764831845f * 1.4426950408889634f;
    const int kb_end = qb + 1;

    auto fill = [&](int st, int kb) {
        __half* Ksh = smA + st * ASTAGE;
        __half* Vsh = Ksh + KTILE;
        const int k0 = kb * BKV;
        // K: 128 rows x 128 d -> 2048 chunks
#pragma unroll
        for (int i = 0; i < 8; i++) {
            int p = t + i * 256;
            int c = p >> 4, ch = p & 15;
            size_t g = ((size_t)(b * TT + k0 + c) * NKV + hk) * HD + ch * 8;
            cp16(Ksh + c * KSTR + ch * 8, kf + g);
        }
        // V^T: 128 d-rows x 128 t -> 2048 chunks
#pragma unroll
        for (int i = 0; i < 8; i++) {
            int p = t + i * 256;
            int d = p >> 4, ch = p & 15;
            size_t g = ((size_t)(b * NKV + hk) * HD + d) * TT + k0 + ch * 8;
            cp16(Vsh + d * VSTR + ch * 8, vtf + g);
        }
        asm volatile("cp.async.commit_group;" ::: "memory");
    };

    fill(0, 0);

    for (int kb = 0; kb < kb_end; kb++) {
        const int cur = kb & 1;
        const int k0 = kb * BKV;
        if (kb + 1 < kb_end) {
            fill(cur ^ 1, kb + 1);
            asm volatile("cp.async.wait_group 1;" ::: "memory");
        } else {
            asm volatile("cp.async.wait_group 0;" ::: "memory");
        }
        __syncthreads();

        const __half* Ksh = smA + cur * ASTAGE;
        const __half* Vsh = Ksh + KTILE;

        // ---- S = Q K^T (128 wide) ----
        float S[16][4];
#pragma unroll
        for (int jt = 0; jt < 16; jt++)
#pragma unroll
            for (int e = 0; e < 4; e++) S[jt][e] = 0.0f;

#pragma unroll
        for (int kt = 0; kt < 8; kt++) {
#pragma unroll
            for (int jt = 0; jt < 16; jt++) {
                int base = (jt * 8 + (lane >> 2)) * KSTR + kt * 16 + qpair;
                uint32_t b0 = *(const uint32_t*)&Ksh[base];
                uint32_t b1 = *(const uint32_t*)&Ksh[base + 8];
                mma16816(S[jt], Qh[kt], b0, b1);
                mma16816(S[jt], Ql[kt], b0, b1);
            }
        }

        // ---- scale + causal mask ----
        const bool diag = (kb == qb);
#pragma unroll
        for (int jt = 0; jt < 16; jt++) {
            int c0 = k0 + jt * 8 + qpair;
            S[jt][0] *= SCL; S[jt][1] *= SCL; S[jt][2] *= SCL; S[jt][3] *= SCL;
            if (diag) {
                if (c0 > rg0)     S[jt][0] = -CUDART_INF_F;
                if (c0 + 1 > rg0) S[jt][1] = -CUDART_INF_F;
                if (c0 > rg1)     S[jt][2] = -CUDART_INF_F;
                if (c0 + 1 > rg1) S[jt][3] = -CUDART_INF_F;
            }
        }

        // ---- online softmax (base-2) ----
        float mx0 = -CUDART_INF_F, mx1 = -CUDART_INF_F;
#pragma unroll
        for (int jt = 0; jt < 16; jt++) {
            mx0 = fmaxf(mx0, fmaxf(S[jt][0], S[jt][1]));
            mx1 = fmaxf(mx1, fmaxf(S[jt][2], S[jt][3]));
        }
#pragma unroll
        for (int off = 1; off <= 2; off <<= 1) {
            mx0 = fmaxf(mx0, __shfl_xor_sync(0xffffffffu, mx0, off));
            mx1 = fmaxf(mx1, __shfl_xor_sync(0xffffffffu, mx1, off));
        }
        float mn0 = fmaxf(m0, mx0), mn1 = fmaxf(m1, mx1);
        float al0 = fast_exp2(m0 - mn0), al1 = fast_exp2(m1 - mn1);
        float s0 = 0.0f, s1 = 0.0f;
#pragma unroll
        for (int jt = 0; jt < 16; jt++) {
            S[jt][0] = fast_exp2(S[jt][0] - mn0); s0 += S[jt][0];
            S[jt][1] = fast_exp2(S[jt][1] - mn0); s0 += S[jt][1];
            S[jt][2] = fast_exp2(S[jt][2] - mn1); s1 += S[jt][2];
            S[jt][3] = fast_exp2(S[jt][3] - mn1); s1 += S[jt][3];
        }
#pragma unroll
        for (int off = 1; off <= 2; off <<= 1) {
            s0 += __shfl_xor_sync(0xffffffffu, s0, off);
            s1 += __shfl_xor_sync(0xffffffffu, s1, off);
        }
        l0 = l0 * al0 + s0; l1 = l1 * al1 + s1;
        m0 = mn0; m1 = mn1;
#pragma unroll
        for (int nt = 0; nt < 16; nt++) {
            O[nt][0] *= al0; O[nt][1] *= al0;
            O[nt][2] *= al1; O[nt][3] *= al1;
        }

        // ---- O += P V (k-dim now 128: kt 0..7) ----
#pragma unroll
        for (int kt = 0; kt < 8; kt++) {
            uint32_t Ph[4], Pl[4];
            {
                float p00 = S[2 * kt][0],     p01 = S[2 * kt][1];
                float p10 = S[2 * kt][2],     p11 = S[2 * kt][3];
                float p20 = S[2 * kt + 1][0], p21 = S[2 * kt + 1][1];
                float p30 = S[2 * kt + 1][2], p31 = S[2 * kt + 1][3];
                float h00 = __half2float(__float2half_rn(p00));
                float h01 = __half2float(__float2half_rn(p01));
                float h10 = __half2float(__float2half_rn(p10));
                float h11 = __half2float(__float2half_rn(p11));
                float h20 = __half2float(__float2half_rn(p20));
                float h21 = __half2float(__float2half_rn(p21));
                float h30 = __half2float(__float2half_rn(p30));
                float h31 = __half2float(__float2half_rn(p31));
                Ph[0] = pack_h(h00, h01); Ph[1] = pack_h(h10, h11);
                Ph[2] = pack_h(h20, h21); Ph[3] = pack_h(h30, h31);
                Pl[0] = pack_h(p00 - h00, p01 - h01);
                Pl[1] = pack_h(p10 - h10, p11 - h11);
                Pl[2] = pack_h(p20 - h20, p21 - h21);
                Pl[3] = pack_h(p30 - h30, p31 - h31);
            }
#pragma unroll
            for (int nt = 0; nt < 16; nt++) {
                int base = (nt * 8 + (lane >> 2)) * VSTR + kt * 16 + qpair;
                uint32_t b0 = *(const uint32_t*)&Vsh[base];
                uint32_t b1 = *(const uint32_t*)&Vsh[base + 8];
                mma16816(O[nt], Ph, b0, b1);
                mma16816(O[nt], Pl, b0, b1);
            }
        }
        __syncthreads();
    }

    float il0 = 1.0f / l0, il1 = 1.0f / l1;
#pragma unroll
    for (int nt = 0; nt < 16; nt++) {
        int d = nt * 8 + qpair;
        size_t base0 = (size_t)(b * TT + rg0) * NE + h * HD + d;
        size_t base1 = (size_t)(b * TT + rg1) * NE + h * HD + d;
        float o00 = O[nt][0] * il0, o01 = O[nt][1] * il0;
        float o10 = O[nt][2] * il1, o11 = O[nt][3] * il1;
        float h00 = __half2float(__float2half_rn(o00));
        float h01 = __half2float(__float2half_rn(o01));
        float h10 = __half2float(__float2half_rn(o10));
        float h11 = __half2float(__float2half_rn(o11));
        *(uint32_t*)&yh[base0] = pack_h(h00, h01);
        *(uint32_t*)&yl[base0] = pack_h(o00 - h00, o01 - h01);
        *(uint32_t*)&yh[base1] = pack_h(h10, h11);
        *(uint32_t*)&yl[base1] = pack_h(o10 - h10, o11 - h11);
    }
}

// ---------------------------------------------------------------------------
extern "C" void kernel_launch(void* const* d_in, const int* in_sizes, int n_in,
                              void* d_out, int out_size) {
    const float* x  = (const float*)d_in[0];
    const float* wq = (const float*)d_in[1];
    const float* wk = (const float*)d_in[2];
    const float* wv = (const float*)d_in[3];
    const float* wo = (const float*)d_in[4];
    float* out = (float*)d_out;

    __half *xh, *xl, *wqp, *wkp, *wvp, *wop, *qh, *ql, *kp, *vtp, *yh, *yl;
    cudaGetSymbolAddress((void**)&xh,  g_xh);  cudaGetSymbolAddress((void**)&xl, g_xl);
    cudaGetSymbolAddress((void**)&wqp, g_wq);  cudaGetSymbolAddress((void**)&wkp, g_wk);
    cudaGetSymbolAddress((void**)&wvp, g_wv);  cudaGetSymbolAddress((void**)&wop, g_wo);
    cudaGetSymbolAddress((void**)&qh,  g_qh);  cudaGetSymbolAddress((void**)&ql,  g_ql);
    cudaGetSymbolAddress((void**)&kp,  g_k);   cudaGetSymbolAddress((void**)&vtp, g_vt);
    cudaGetSymbolAddress((void**)&yh,  g_yh);  cudaGetSymbolAddress((void**)&yl,  g_yl);

    prep_all<<<(PREP_TOTAL + 255) / 256, 256>>>(x, wq, wk, wv, wo,
                                                xh, xl, wqp, wkp, wvp, wop);

    cudaFuncSetAttribute(gemm_qkv, cudaFuncAttributeMaxDynamicSharedMemorySize, GEMM_SMEM);
    cudaFuncSetAttribute(gemm_wo,  cudaFuncAttributeMaxDynamicSharedMemorySize, GEMM_SMEM);

    dim3 blk(256);
    gemm_qkv<<<dim3(24, 32), blk, GEMM_SMEM>>>(xh, xl, wqp, wkp, wvp,
                                               qh, ql, kp, vtp);

    cudaFuncSetAttribute(attn_mma, cudaFuncAttributeMaxDynamicSharedMemorySize, SM_ATT_BYTES);
    attn_mma<<<dim3(TT / BQ, BB * NH), blk, SM_ATT_BYTES>>>(qh, ql, kp, vtp, yh, yl);

    gemm_wo<<<dim3(16, 32), blk, GEMM_SMEM>>>(yh, yl, wop, out);
}

// round 12
// speedup vs baseline: 6.1452x; 1.3915x over previous
#include <cuda_runtime.h>
#include <cuda_fp16.h>
#include <math_constants.h>
#include <mma.h>
#include <cstdint>

using namespace nvcuda;

#define BB 2
#define TT 2048
#define NE 2048
#define NH 16
#define NKV 4
#define HD 128
#define GRP (NH / NKV)
#define MROWS (BB * TT)
#define KVE (NKV * HD)

// fp16 scratch
__device__ __half g_x[MROWS * NE];                      // x single fp16
__device__ __half g_wq[NE * NE];
__device__ __half g_wk[KVE * NE];
__device__ __half g_wv[KVE * NE];
__device__ __half g_wo[NE * NE];
__device__ __half g_qh[MROWS * NE], g_ql[MROWS * NE];   // Q split (B,T,H,D)
__device__ __half g_k[MROWS * KVE];                     // (B,T,Hkv,D)
__device__ __half g_vt[MROWS * KVE];                    // (B,Hkv,D,T)
__device__ __half g_y[MROWS * NE];                      // attention out single

__device__ __forceinline__ uint32_t pack_h(float x, float y) {
    __half2 r = __floats2half2_rn(x, y);
    return *(uint32_t*)&r;
}
__device__ __forceinline__ float fast_exp2(float x) {
    float y; asm("ex2.approx.f32 %0, %1;" : "=f"(y) : "f"(x)); return y;
}
__device__ __forceinline__ void mma16816(float* c, const uint32_t* a, uint32_t b0, uint32_t b1) {
    asm volatile("mma.sync.aligned.m16n8k16.row.col.f32.f16.f16.f32 "
                 "{%0,%1,%2,%3}, {%4,%5,%6,%7}, {%8,%9}, {%0,%1,%2,%3};\n"
                 : "+f"(c[0]), "+f"(c[1]), "+f"(c[2]), "+f"(c[3])
                 : "r"(a[0]), "r"(a[1]), "r"(a[2]), "r"(a[3]), "r"(b0), "r"(b1));
}
__device__ __forceinline__ void cp16(__half* s, const __half* g) {
    uint32_t sa = (uint32_t)__cvta_generic_to_shared(s);
    asm volatile("cp.async.cg.shared.global [%0], [%1], 16;" :: "r"(sa), "l"(g));
}

// ---------------------------------------------------------------------------
// Fused prep: convert x, wq, wk, wv, wo -> single fp16
// ---------------------------------------------------------------------------
#define NX4  (MROWS * NE / 4)
#define NW4  (NE * NE / 4)
#define NWK4 (KVE * NE / 4)
#define PREP_TOTAL (NX4 + NW4 + 2 * NWK4 + NW4)

__global__ __launch_bounds__(256) void prep_all(
    const float* __restrict__ x,  const float* __restrict__ wq,
    const float* __restrict__ wk, const float* __restrict__ wv,
    const float* __restrict__ wo,
    __half* __restrict__ xp, __half* __restrict__ wqp,
    __half* __restrict__ wkp, __half* __restrict__ wvp,
    __half* __restrict__ wop)
{
    int i = blockIdx.x * blockDim.x + threadIdx.x;
    if (i >= PREP_TOTAL) return;
    const float* src; __half* dst; int j;
    if (i < NX4)                        { src = x;  dst = xp;  j = i; }
    else if (i < NX4 + NW4)             { src = wq; dst = wqp; j = i - NX4; }
    else if (i < NX4 + NW4 + NWK4)      { src = wk; dst = wkp; j = i - NX4 - NW4; }
    else if (i < NX4 + NW4 + 2*NWK4)    { src = wv; dst = wvp; j = i - NX4 - NW4 - NWK4; }
    else                                { src = wo; dst = wop; j = i - NX4 - NW4 - 2*NWK4; }
    float4 v = ((const float4*)src)[j];
    union { __half b[4]; uint2 u; } H;
    H.b[0] = __float2half_rn(v.x); H.b[1] = __float2half_rn(v.y);
    H.b[2] = __float2half_rn(v.z); H.b[3] = __float2half_rn(v.w);
    ((uint2*)dst)[j] = H.u;
}

// ---------------------------------------------------------------------------
// GEMM core: 2-stage cp.async, K-step 64, fp16 1-term (A single, B single).
// Block tile 128x128, 256 threads, 8 warps as 4x2, warp tile 32x64.
// 73,728 B smem/CTA -> 2 CTAs/SM.
// ---------------------------------------------------------------------------
#define TBM 128
#define TBN 128
#define TBK 64
#define TLD 72
#define TILE_ELEMS (TBM * TLD)     // 9216 halves
#define NSTAGE 2
#define SEPI 132
#define GEMM_SMEM (NSTAGE * 2 * TILE_ELEMS * 2)   // 73,728 B

__device__ __forceinline__ void g_load_stage(
    __half* gsm, int st, int kb, int t,
    const __half* A, const __half* B,
    int row0, int col0, int K)
{
    __half* tA = gsm + (st * 2 + 0) * TILE_ELEMS;
    __half* tB = gsm + (st * 2 + 1) * TILE_ELEMS;
#pragma unroll
    for (int i = 0; i < 4; i++) {
        int p = t + i * 256;              // 0..1023
        int r = p >> 3, ch = p & 7;       // row, 16B chunk
        size_t ga = (size_t)(row0 + r) * K + kb * TBK + ch * 8;
        size_t gb = (size_t)(col0 + r) * K + kb * TBK + ch * 8;
        int so = r * TLD + ch * 8;
        cp16(tA + so, A + ga);
        cp16(tB + so, B + gb);
    }
    asm volatile("cp.async.commit_group;" ::: "memory");
}

__device__ __forceinline__ void g_core(
    __half* gsm, int t,
    const __half* A, const __half* B,
    int row0, int col0, int K)
{
    const int w  = t >> 5;
    const int wm = w & 3;     // 0..3 : 32-row group
    const int wn = w >> 2;    // 0..1 : 64-col group

    wmma::fragment<wmma::accumulator, 16, 16, 16, float> acc[2][4];
#pragma unroll
    for (int i = 0; i < 2; i++)
#pragma unroll
        for (int j = 0; j < 4; j++) wmma::fill_fragment(acc[i][j], 0.0f);

    const int nk = K / TBK;
    g_load_stage(gsm, 0, 0, t, A, B, row0, col0, K);

    for (int kb = 0; kb < nk; kb++) {
        const int cur = kb & 1;
        if (kb + 1 < nk) {
            g_load_stage(gsm, cur ^ 1, kb + 1, t, A, B, row0, col0, K);
            asm volatile("cp.async.wait_group 1;" ::: "memory");
        } else {
            asm volatile("cp.async.wait_group 0;" ::: "memory");
        }
        __syncthreads();

        const __half* tA = gsm + (cur * 2 + 0) * TILE_ELEMS;
        const __half* tB = gsm + (cur * 2 + 1) * TILE_ELEMS;

#pragma unroll
        for (int kk = 0; kk < TBK; kk += 16) {
            wmma::fragment<wmma::matrix_b, 16, 16, 16, __half, wmma::col_major> bf[4];
#pragma unroll
            for (int j = 0; j < 4; j++)
                wmma::load_matrix_sync(bf[j], tB + (wn * 64 + j * 16) * TLD + kk, TLD);
#pragma unroll
            for (int i = 0; i < 2; i++) {
                wmma::fragment<wmma::matrix_a, 16, 16, 16, __half, wmma::row_major> af;
                wmma::load_matrix_sync(af, tA + (wm * 32 + i * 16) * TLD + kk, TLD);
#pragma unroll
                for (int j = 0; j < 4; j++)
                    wmma::mma_sync(acc[i][j], af, bf[j], acc[i][j]);
            }
        }
        __syncthreads();
    }

    float* smf = (float*)gsm;
#pragma unroll
    for (int i = 0; i < 2; i++)
#pragma unroll
        for (int j = 0; j < 4; j++)
            wmma::store_matrix_sync(&smf[(wm * 32 + i * 16) * SEPI + wn * 64 + j * 16],
                                    acc[i][j], SEPI, wmma::mem_row_major);
    __syncthreads();
}

// Fused Q/K/V projection. grid = (24, 32). 2 CTAs/SM.
__global__ __launch_bounds__(256, 2) void gemm_qkv(
    const __half* __restrict__ xp,
    const __half* __restrict__ wq, const __half* __restrict__ wk,
    const __half* __restrict__ wv,
    __half* __restrict__ qh, __half* __restrict__ ql,
    __half* __restrict__ kp, __half* __restrict__ vtp)
{
    extern __shared__ __half gsm[];
    const int t  = threadIdx.x;
    const int bx = blockIdx.x;
    const int row0 = blockIdx.y * TBM;

    const __half* B; int mode, N, cb;
    if (bx < 16)      { B = wq; mode = 1; N = NE;  cb = bx; }
    else if (bx < 20) { B = wk; mode = 2; N = KVE; cb = bx - 16; }
    else              { B = wv; mode = 3; N = KVE; cb = bx - 20; }
    const int col0 = cb * TBN;

    g_core(gsm, t, xp, B, row0, col0, NE);
    float* smf = (float*)gsm;

    if (mode == 1) {
        // Q: split output into hi/lo fp16
#pragma unroll
        for (int i = 0; i < 32; i++) {
            int p = t + i * 256;
            int r = p >> 6, c2 = (p & 63) * 2;
            float x0 = smf[r * SEPI + c2], x1 = smf[r * SEPI + c2 + 1];
            float h0 = __half2float(__float2half_rn(x0));
            float h1 = __half2float(__float2half_rn(x1));
            size_t gidx = (size_t)(row0 + r) * N + col0 + c2;
            *(uint32_t*)&qh[gidx] = pack_h(h0, h1);
            *(uint32_t*)&ql[gidx] = pack_h(x0 - h0, x1 - h1);
        }
    } else if (mode == 2) {
#pragma unroll
        for (int i = 0; i < 32; i++) {
            int p = t + i * 256;
            int r = p >> 6, c2 = (p & 63) * 2;
            float x0 = smf[r * SEPI + c2], x1 = smf[r * SEPI + c2 + 1];
            size_t gidx = (size_t)(row0 + r) * N + col0 + c2;
            *(uint32_t*)&kp[gidx] = pack_h(x0, x1);
        }
    } else {
        const int b  = row0 >> 11;
        const int t0 = row0 & 2047;
        const int hk = col0 >> 7;
#pragma unroll
        for (int i = 0; i < 32; i++) {
            int p = t + i * 256;
            int c = p >> 6, rp = (p & 63) * 2;
            float x0 = smf[rp * SEPI + c], x1 = smf[(rp + 1) * SEPI + c];
            size_t gidx = ((size_t)(b * NKV + hk) * HD + c) * TT + t0 + rp;
            *(uint32_t*)&vtp[gidx] = pack_h(x0, x1);
        }
    }
}

// Output projection: fp32 out. grid = (16, 32). 2 CTAs/SM.
__global__ __launch_bounds__(256, 2) void gemm_wo(
    const __half* __restrict__ yp,
    const __half* __restrict__ wo, float* __restrict__ out)
{
    extern __shared__ __half gsm[];
    const int t = threadIdx.x;
    const int row0 = blockIdx.y * TBM;
    const int col0 = blockIdx.x * TBN;

    g_core(gsm, t, yp, wo, row0, col0, NE);
    float* smf = (float*)gsm;
#pragma unroll
    for (int i = 0; i < 32; i++) {
        int p = t + i * 256;
        int r = p >> 6, c2 = (p & 63) * 2;
        float2 v = *(float2*)&smf[r * SEPI + c2];
        *(float2*)&out[(size_t)(row0 + r) * NE + col0 + c2] = v;
    }
}

// ---------------------------------------------------------------------------
// FA2 mma.sync causal GQA attention, fp16 2-term (Q split, P split),
// KV tile 128, double-buffered cp.async. Writes single fp16 y.
// ---------------------------------------------------------------------------
#define BQ 128
#define BKV 128
#define KSTR 136
#define VSTR 136
#define KTILE (BKV * KSTR)
#define VTILE (HD * VSTR)
#define ASTAGE (KTILE + VTILE)
#define SM_ATT_BYTES (2 * ASTAGE * 2) // 139,264 B

__global__ __launch_bounds__(256, 1) void attn_mma(
    const __half* __restrict__ qh, const __half* __restrict__ ql,
    const __half* __restrict__ kf, const __half* __restrict__ vtf,
    __half* __restrict__ yp) {
    extern __shared__ __half smA[];

    const int t    = threadIdx.x;
    const int w    = t >> 5;
    const int lane = t & 31;
    const int qb   = (gridDim.x - 1) - blockIdx.x;   // heavy CTAs first
    const int bh   = blockIdx.y;
    const int b    = bh >> 4;
    const int h    = bh & 15;
    const int hk   = h / GRP;
    const int q0   = qb * BQ;
    const int rg0  = q0 + w * 16 + (lane >> 2);
    const int rg1  = rg0 + 8;
    const int qpair = (lane & 3) * 2;

    uint32_t Qh[8][4], Ql[8][4];
#pragma unroll
    for (int kt = 0; kt < 8; kt++) {
#pragma unroll
        for (int half = 0; half < 2; half++) {
#pragma unroll
            for (int ri = 0; ri < 2; ri++) {
                int row = ri ? rg1 : rg0;
                size_t gi = ((size_t)(b * TT + row) * NH + h) * HD + kt * 16 + half * 8 + qpair;
                Qh[kt][half * 2 + ri] = *(const uint32_t*)&qh[gi];
                Ql[kt][half * 2 + ri] = *(const uint32_t*)&ql[gi];
            }
        }
    }

    float O[16][4];
#pragma unroll
    for (int nt = 0; nt < 16; nt++)
#pragma unroll
        for (int e = 0; e < 4; e++) O[nt][e] = 0.0f;
    float m0 = -CUDART_INF_F, m1 = -CUDART_INF_F, l0 = 0.0f, l1 = 0.0f;

    const float SCL = 0.08838834764831845f * 1.4426950408889634f;
    const int kb_end = qb + 1;

    auto fill = [&](int st, int kb) {
        __half* Ksh = smA + st * ASTAGE;
        __half* Vsh = Ksh + KTILE;
        const int k0 = kb * BKV;
#pragma unroll
        for (int i = 0; i < 8; i++) {
            int p = t + i * 256;
            int c = p >> 4, ch = p & 15;
            size_t g = ((size_t)(b * TT + k0 + c) * NKV + hk) * HD + ch * 8;
            cp16(Ksh + c * KSTR + ch * 8, kf + g);
        }
#pragma unroll
        for (int i = 0; i < 8; i++) {
            int p = t + i * 256;
            int d = p >> 4, ch = p & 15;
            size_t g = ((size_t)(b * NKV + hk) * HD + d) * TT + k0 + ch * 8;
            cp16(Vsh + d * VSTR + ch * 8, vtf + g);
        }
        asm volatile("cp.async.commit_group;" ::: "memory");
    };

    fill(0, 0);

    for (int kb = 0; kb < kb_end; kb++) {
        const int cur = kb & 1;
        const int k0 = kb * BKV;
        if (kb + 1 < kb_end) {
            fill(cur ^ 1, kb + 1);
            asm volatile("cp.async.wait_group 1;" ::: "memory");
        } else {
            asm volatile("cp.async.wait_group 0;" ::: "memory");
        }
        __syncthreads();

        const __half* Ksh = smA + cur * ASTAGE;
        const __half* Vsh = Ksh + KTILE;

        float S[16][4];
#pragma unroll
        for (int jt = 0; jt < 16; jt++)
#pragma unroll
            for (int e = 0; e < 4; e++) S[jt][e] = 0.0f;

#pragma unroll
        for (int kt = 0; kt < 8; kt++) {
#pragma unroll
            for (int jt = 0; jt < 16; jt++) {
                int base = (jt * 8 + (lane >> 2)) * KSTR + kt * 16 + qpair;
                uint32_t b0 = *(const uint32_t*)&Ksh[base];
                uint32_t b1 = *(const uint32_t*)&Ksh[base + 8];
                mma16816(S[jt], Qh[kt], b0, b1);
                mma16816(S[jt], Ql[kt], b0, b1);
            }
        }

        const bool diag = (kb == qb);
#pragma unroll
        for (int jt = 0; jt < 16; jt++) {
            int c0 = k0 + jt * 8 + qpair;
            S[jt][0] *= SCL; S[jt][1] *= SCL; S[jt][2] *= SCL; S[jt][3] *= SCL;
            if (diag) {
                if (c0 > rg0)     S[jt][0] = -CUDART_INF_F;
                if (c0 + 1 > rg0) S[jt][1] = -CUDART_INF_F;
                if (c0 > rg1)     S[jt][2] = -CUDART_INF_F;
                if (c0 + 1 > rg1) S[jt][3] = -CUDART_INF_F;
            }
        }

        float mx0 = -CUDART_INF_F, mx1 = -CUDART_INF_F;
#pragma unroll
        for (int jt = 0; jt < 16; jt++) {
            mx0 = fmaxf(mx0, fmaxf(S[jt][0], S[jt][1]));
            mx1 = fmaxf(mx1, fmaxf(S[jt][2], S[jt][3]));
        }
#pragma unroll
        for (int off = 1; off <= 2; off <<= 1) {
            mx0 = fmaxf(mx0, __shfl_xor_sync(0xffffffffu, mx0, off));
            mx1 = fmaxf(mx1, __shfl_xor_sync(0xffffffffu, mx1, off));
        }
        float mn0 = fmaxf(m0, mx0), mn1 = fmaxf(m1, mx1);
        float al0 = fast_exp2(m0 - mn0), al1 = fast_exp2(m1 - mn1);
        float s0 = 0.0f, s1 = 0.0f;
#pragma unroll
        for (int jt = 0; jt < 16; jt++) {
            S[jt][0] = fast_exp2(S[jt][0] - mn0); s0 += S[jt][0];
            S[jt][1] = fast_exp2(S[jt][1] - mn0); s0 += S[jt][1];
            S[jt][2] = fast_exp2(S[jt][2] - mn1); s1 += S[jt][2];
            S[jt][3] = fast_exp2(S[jt][3] - mn1); s1 += S[jt][3];
        }
#pragma unroll
        for (int off = 1; off <= 2; off <<= 1) {
            s0 += __shfl_xor_sync(0xffffffffu, s0, off);
            s1 += __shfl_xor_sync(0xffffffffu, s1, off);
        }
        l0 = l0 * al0 + s0; l1 = l1 * al1 + s1;
        m0 = mn0; m1 = mn1;
#pragma unroll
        for (int nt = 0; nt < 16; nt++) {
            O[nt][0] *= al0; O[nt][1] *= al0;
            O[nt][2] *= al1; O[nt][3] *= al1;
        }

#pragma unroll
        for (int kt = 0; kt < 8; kt++) {
            uint32_t Ph[4], Pl[4];
            {
                float p00 = S[2 * kt][0],     p01 = S[2 * kt][1];
                float p10 = S[2 * kt][2],     p11 = S[2 * kt][3];
                float p20 = S[2 * kt + 1][0], p21 = S[2 * kt + 1][1];
                float p30 = S[2 * kt + 1][2], p31 = S[2 * kt + 1][3];
                float h00 = __half2float(__float2half_rn(p00));
                float h01 = __half2float(__float2half_rn(p01));
                float h10 = __half2float(__float2half_rn(p10));
                float h11 = __half2float(__float2half_rn(p11));
                float h20 = __half2float(__float2half_rn(p20));
                float h21 = __half2float(__float2half_rn(p21));
                float h30 = __half2float(__float2half_rn(p30));
                float h31 = __half2float(__float2half_rn(p31));
                Ph[0] = pack_h(h00, h01); Ph[1] = pack_h(h10, h11);
                Ph[2] = pack_h(h20, h21); Ph[3] = pack_h(h30, h31);
                Pl[0] = pack_h(p00 - h00, p01 - h01);
                Pl[1] = pack_h(p10 - h10, p11 - h11);
                Pl[2] = pack_h(p20 - h20, p21 - h21);
                Pl[3] = pack_h(p30 - h30, p31 - h31);
            }
#pragma unroll
            for (int nt = 0; nt < 16; nt++) {
                int base = (nt * 8 + (lane >> 2)) * VSTR + kt * 16 + qpair;
                uint32_t b0 = *(const uint32_t*)&Vsh[base];
                uint32_t b1 = *(const uint32_t*)&Vsh[base + 8];
                mma16816(O[nt], Ph, b0, b1);
                mma16816(O[nt], Pl, b0, b1);
            }
        }
        __syncthreads();
    }

    float il0 = 1.0f / l0, il1 = 1.0f / l1;
#pragma unroll
    for (int nt = 0; nt < 16; nt++) {
        int d = nt * 8 + qpair;
        size_t base0 = (size_t)(b * TT + rg0) * NE + h * HD + d;
        size_t base1 = (size_t)(b * TT + rg1) * NE + h * HD + d;
        *(uint32_t*)&yp[base0] = pack_h(O[nt][0] * il0, O[nt][1] * il0);
        *(uint32_t*)&yp[base1] = pack_h(O[nt][2] * il1, O[nt][3] * il1);
    }
}

// ---------------------------------------------------------------------------
extern "C" void kernel_launch(void* const* d_in, const int* in_sizes, int n_in,
                              void* d_out, int out_size) {
    const float* x  = (const float*)d_in[0];
    const float* wq = (const float*)d_in[1];
    const float* wk = (const float*)d_in[2];
    const float* wv = (const float*)d_in[3];
    const float* wo = (const float*)d_in[4];
    float* out = (float*)d_out;

    __half *xp, *wqp, *wkp, *wvp, *wop, *qh, *ql, *kp, *vtp, *yp;
    cudaGetSymbolAddress((void**)&xp,  g_x);
    cudaGetSymbolAddress((void**)&wqp, g_wq);  cudaGetSymbolAddress((void**)&wkp, g_wk);
    cudaGetSymbolAddress((void**)&wvp, g_wv);  cudaGetSymbolAddress((void**)&wop, g_wo);
    cudaGetSymbolAddress((void**)&qh,  g_qh);  cudaGetSymbolAddress((void**)&ql,  g_ql);
    cudaGetSymbolAddress((void**)&kp,  g_k);   cudaGetSymbolAddress((void**)&vtp, g_vt);
    cudaGetSymbolAddress((void**)&yp,  g_y);

    prep_all<<<(PREP_TOTAL + 255) / 256, 256>>>(x, wq, wk, wv, wo,
                                                xp, wqp, wkp, wvp, wop);

    cudaFuncSetAttribute(gemm_qkv, cudaFuncAttributeMaxDynamicSharedMemorySize, GEMM_SMEM);
    cudaFuncSetAttribute(gemm_wo,  cudaFuncAttributeMaxDynamicSharedMemorySize, GEMM_SMEM);

    dim3 blk(256);
    gemm_qkv<<<dim3(24, 32), blk, GEMM_SMEM>>>(xp, wqp, wkp, wvp,
                                               qh, ql, kp, vtp);

    cudaFuncSetAttribute(attn_mma, cudaFuncAttributeMaxDynamicSharedMemorySize, SM_ATT_BYTES);
    attn_mma<<<dim3(TT / BQ, BB * NH), blk, SM_ATT_BYTES>>>(qh, ql, kp, vtp, yp);

    gemm_wo<<<dim3(16, 32), blk, GEMM_SMEM>>>(yp, wop, out);
}

// round 13
// speedup vs baseline: 7.4732x; 1.2161x over previous
#include <cuda_runtime.h>
#include <cuda_fp16.h>
#include <math_constants.h>
#include <mma.h>
#include <cstdint>

using namespace nvcuda;

#define BB 2
#define TT 2048
#define NE 2048
#define NH 16
#define NKV 4
#define HD 128
#define GRP (NH / NKV)
#define MROWS (BB * TT)
#define KVE (NKV * HD)

// fp16 scratch
__device__ __half g_x[MROWS * NE];
__device__ __half g_wq[NE * NE];
__device__ __half g_wk[KVE * NE];
__device__ __half g_wv[KVE * NE];
__device__ __half g_wo[NE * NE];
__device__ __half g_q[MROWS * NE];     // (B,T,H,D) single fp16
__device__ __half g_k[MROWS * KVE];    // (B,T,Hkv,D)
__device__ __half g_vt[MROWS * KVE];   // (B,Hkv,D,T)
__device__ __half g_y[MROWS * NE];     // attention out single

__device__ __forceinline__ uint32_t pack_h(float x, float y) {
    __half2 r = __floats2half2_rn(x, y);
    return *(uint32_t*)&r;
}
__device__ __forceinline__ float fast_exp2(float x) {
    float y; asm("ex2.approx.f32 %0, %1;" : "=f"(y) : "f"(x)); return y;
}
__device__ __forceinline__ void mma16816(float* c, const uint32_t* a, uint32_t b0, uint32_t b1) {
    asm volatile("mma.sync.aligned.m16n8k16.row.col.f32.f16.f16.f32 "
                 "{%0,%1,%2,%3}, {%4,%5,%6,%7}, {%8,%9}, {%0,%1,%2,%3};\n"
                 : "+f"(c[0]), "+f"(c[1]), "+f"(c[2]), "+f"(c[3])
                 : "r"(a[0]), "r"(a[1]), "r"(a[2]), "r"(a[3]), "r"(b0), "r"(b1));
}
__device__ __forceinline__ void cp16(__half* s, const __half* g) {
    uint32_t sa = (uint32_t)__cvta_generic_to_shared(s);
    asm volatile("cp.async.cg.shared.global [%0], [%1], 16;" :: "r"(sa), "l"(g));
}

// ---------------------------------------------------------------------------
// Fused prep: convert x, wq, wk, wv, wo -> single fp16
// ---------------------------------------------------------------------------
#define NX4  (MROWS * NE / 4)
#define NW4  (NE * NE / 4)
#define NWK4 (KVE * NE / 4)
#define PREP_TOTAL (NX4 + NW4 + 2 * NWK4 + NW4)

__global__ __launch_bounds__(256) void prep_all(
    const float* __restrict__ x,  const float* __restrict__ wq,
    const float* __restrict__ wk, const float* __restrict__ wv,
    const float* __restrict__ wo,
    __half* __restrict__ xp, __half* __restrict__ wqp,
    __half* __restrict__ wkp, __half* __restrict__ wvp,
    __half* __restrict__ wop)
{
    int i = blockIdx.x * blockDim.x + threadIdx.x;
    if (i >= PREP_TOTAL) return;
    const float* src; __half* dst; int j;
    if (i < NX4)                        { src = x;  dst = xp;  j = i; }
    else if (i < NX4 + NW4)             { src = wq; dst = wqp; j = i - NX4; }
    else if (i < NX4 + NW4 + NWK4)      { src = wk; dst = wkp; j = i - NX4 - NW4; }
    else if (i < NX4 + NW4 + 2*NWK4)    { src = wv; dst = wvp; j = i - NX4 - NW4 - NWK4; }
    else                                { src = wo; dst = wop; j = i - NX4 - NW4 - 2*NWK4; }
    float4 v = ((const float4*)src)[j];
    union { __half b[4]; uint2 u; } H;
    H.b[0] = __float2half_rn(v.x); H.b[1] = __float2half_rn(v.y);
    H.b[2] = __float2half_rn(v.z); H.b[3] = __float2half_rn(v.w);
    ((uint2*)dst)[j] = H.u;
}

// ---------------------------------------------------------------------------
// GEMM core: 2-stage cp.async, K-step 64, fp16 1-term.
// Block tile 128x128, 256 threads, 8 warps as 4x2, warp tile 32x64.
// 73,728 B smem/CTA -> 2 CTAs/SM.
// ---------------------------------------------------------------------------
#define TBM 128
#define TBN 128
#define TBK 64
#define TLD 72
#define TILE_ELEMS (TBM * TLD)     // 9216 halves
#define NSTAGE 2
#define SEPI 132
#define GEMM_SMEM (NSTAGE * 2 * TILE_ELEMS * 2)   // 73,728 B

__device__ __forceinline__ void g_load_stage(
    __half* gsm, int st, int kb, int t,
    const __half* A, const __half* B,
    int row0, int col0, int K)
{
    __half* tA = gsm + (st * 2 + 0) * TILE_ELEMS;
    __half* tB = gsm + (st * 2 + 1) * TILE_ELEMS;
#pragma unroll
    for (int i = 0; i < 4; i++) {
        int p = t + i * 256;
        int r = p >> 3, ch = p & 7;
        size_t ga = (size_t)(row0 + r) * K + kb * TBK + ch * 8;
        size_t gb = (size_t)(col0 + r) * K + kb * TBK + ch * 8;
        int so = r * TLD + ch * 8;
        cp16(tA + so, A + ga);
        cp16(tB + so, B + gb);
    }
    asm volatile("cp.async.commit_group;" ::: "memory");
}

__device__ __forceinline__ void g_core(
    __half* gsm, int t,
    const __half* A, const __half* B,
    int row0, int col0, int K)
{
    const int w  = t >> 5;
    const int wm = w & 3;
    const int wn = w >> 2;

    wmma::fragment<wmma::accumulator, 16, 16, 16, float> acc[2][4];
#pragma unroll
    for (int i = 0; i < 2; i++)
#pragma unroll
        for (int j = 0; j < 4; j++) wmma::fill_fragment(acc[i][j], 0.0f);

    const int nk = K / TBK;
    g_load_stage(gsm, 0, 0, t, A, B, row0, col0, K);

    for (int kb = 0; kb < nk; kb++) {
        const int cur = kb & 1;
        if (kb + 1 < nk) {
            g_load_stage(gsm, cur ^ 1, kb + 1, t, A, B, row0, col0, K);
            asm volatile("cp.async.wait_group 1;" ::: "memory");
        } else {
            asm volatile("cp.async.wait_group 0;" ::: "memory");
        }
        __syncthreads();

        const __half* tA = gsm + (cur * 2 + 0) * TILE_ELEMS;
        const __half* tB = gsm + (cur * 2 + 1) * TILE_ELEMS;

#pragma unroll
        for (int kk = 0; kk < TBK; kk += 16) {
            wmma::fragment<wmma::matrix_b, 16, 16, 16, __half, wmma::col_major> bf[4];
#pragma unroll
            for (int j = 0; j < 4; j++)
                wmma::load_matrix_sync(bf[j], tB + (wn * 64 + j * 16) * TLD + kk, TLD);
#pragma unroll
            for (int i = 0; i < 2; i++) {
                wmma::fragment<wmma::matrix_a, 16, 16, 16, __half, wmma::row_major> af;
                wmma::load_matrix_sync(af, tA + (wm * 32 + i * 16) * TLD + kk, TLD);
#pragma unroll
                for (int j = 0; j < 4; j++)
                    wmma::mma_sync(acc[i][j], af, bf[j], acc[i][j]);
            }
        }
        __syncthreads();
    }

    float* smf = (float*)gsm;
#pragma unroll
    for (int i = 0; i < 2; i++)
#pragma unroll
        for (int j = 0; j < 4; j++)
            wmma::store_matrix_sync(&smf[(wm * 32 + i * 16) * SEPI + wn * 64 + j * 16],
                                    acc[i][j], SEPI, wmma::mem_row_major);
    __syncthreads();
}

// Fused Q/K/V projection. grid = (24, 32). 2 CTAs/SM.
// bx 0..15: Q, bx 16..19: K, bx 20..23: V^T. All single fp16 outputs.
__global__ __launch_bounds__(256, 2) void gemm_qkv(
    const __half* __restrict__ xp,
    const __half* __restrict__ wq, const __half* __restrict__ wk,
    const __half* __restrict__ wv,
    __half* __restrict__ qp, __half* __restrict__ kp,
    __half* __restrict__ vtp)
{
    extern __shared__ __half gsm[];
    const int t  = threadIdx.x;
    const int bx = blockIdx.x;
    const int row0 = blockIdx.y * TBM;

    const __half* B; int mode, N, cb;
    __half* C;
    if (bx < 16)      { B = wq; mode = 0; N = NE;  cb = bx;      C = qp; }
    else if (bx < 20) { B = wk; mode = 0; N = KVE; cb = bx - 16; C = kp; }
    else              { B = wv; mode = 1; N = KVE; cb = bx - 20; C = vtp; }
    const int col0 = cb * TBN;

    g_core(gsm, t, xp, B, row0, col0, NE);
    float* smf = (float*)gsm;

    if (mode == 0) {
#pragma unroll
        for (int i = 0; i < 32; i++) {
            int p = t + i * 256;
            int r = p >> 6, c2 = (p & 63) * 2;
            float x0 = smf[r * SEPI + c2], x1 = smf[r * SEPI + c2 + 1];
            size_t gidx = (size_t)(row0 + r) * N + col0 + c2;
            *(uint32_t*)&C[gidx] = pack_h(x0, x1);
        }
    } else {
        const int b  = row0 >> 11;
        const int t0 = row0 & 2047;
        const int hk = col0 >> 7;
#pragma unroll
        for (int i = 0; i < 32; i++) {
            int p = t + i * 256;
            int c = p >> 6, rp = (p & 63) * 2;
            float x0 = smf[rp * SEPI + c], x1 = smf[(rp + 1) * SEPI + c];
            size_t gidx = ((size_t)(b * NKV + hk) * HD + c) * TT + t0 + rp;
            *(uint32_t*)&C[gidx] = pack_h(x0, x1);
        }
    }
}

// Output projection: fp32 out. grid = (16, 32). 2 CTAs/SM.
__global__ __launch_bounds__(256, 2) void gemm_wo(
    const __half* __restrict__ yp,
    const __half* __restrict__ wo, float* __restrict__ out)
{
    extern __shared__ __half gsm[];
    const int t = threadIdx.x;
    const int row0 = blockIdx.y * TBM;
    const int col0 = blockIdx.x * TBN;

    g_core(gsm, t, yp, wo, row0, col0, NE);
    float* smf = (float*)gsm;
#pragma unroll
    for (int i = 0; i < 32; i++) {
        int p = t + i * 256;
        int r = p >> 6, c2 = (p & 63) * 2;
        float2 v = *(float2*)&smf[r * SEPI + c2];
        *(float2*)&out[(size_t)(row0 + r) * NE + col0 + c2] = v;
    }
}

// ---------------------------------------------------------------------------
// FA2 mma.sync causal GQA attention, fp16 1-term (Q single, P single),
// KV tile 128, double-buffered cp.async. Writes single fp16 y.
// ---------------------------------------------------------------------------
#define BQ 128
#define BKV 128
#define KSTR 136
#define VSTR 136
#define KTILE (BKV * KSTR)
#define VTILE (HD * VSTR)
#define ASTAGE (KTILE + VTILE)
#define SM_ATT_BYTES (2 * ASTAGE * 2) // 139,264 B

__global__ __launch_bounds__(256, 1) void attn_mma(
    const __half* __restrict__ qp,
    const __half* __restrict__ kf, const __half* __restrict__ vtf,
    __half* __restrict__ yp) {
    extern __shared__ __half smA[];

    const int t    = threadIdx.x;
    const int w    = t >> 5;
    const int lane = t & 31;
    const int qb   = (gridDim.x - 1) - blockIdx.x;   // heavy CTAs first
    const int bh   = blockIdx.y;
    const int b    = bh >> 4;
    const int h    = bh & 15;
    const int hk   = h / GRP;
    const int q0   = qb * BQ;
    const int rg0  = q0 + w * 16 + (lane >> 2);
    const int rg1  = rg0 + 8;
    const int qpair = (lane & 3) * 2;

    uint32_t Qf[8][4];
#pragma unroll
    for (int kt = 0; kt < 8; kt++) {
#pragma unroll
        for (int half = 0; half < 2; half++) {
#pragma unroll
            for (int ri = 0; ri < 2; ri++) {
                int row = ri ? rg1 : rg0;
                size_t gi = ((size_t)(b * TT + row) * NH + h) * HD + kt * 16 + half * 8 + qpair;
                Qf[kt][half * 2 + ri] = *(const uint32_t*)&qp[gi];
            }
        }
    }

    float O[16][4];
#pragma unroll
    for (int nt = 0; nt < 16; nt++)
#pragma unroll
        for (int e = 0; e < 4; e++) O[nt][e] = 0.0f;
    float m0 = -CUDART_INF_F, m1 = -CUDART_INF_F, l0 = 0.0f, l1 = 0.0f;

    const float SCL = 0.08838834764831845f * 1.4426950408889634f;
    const int kb_end = qb + 1;

    auto fill = [&](int st, int kb) {
        __half* Ksh = smA + st * ASTAGE;
        __half* Vsh = Ksh + KTILE;
        const int k0 = kb * BKV;
#pragma unroll
        for (int i = 0; i < 8; i++) {
            int p = t + i * 256;
            int c = p >> 4, ch = p & 15;
            size_t g = ((size_t)(b * TT + k0 + c) * NKV + hk) * HD + ch * 8;
            cp16(Ksh + c * KSTR + ch * 8, kf + g);
        }
#pragma unroll
        for (int i = 0; i < 8; i++) {
            int p = t + i * 256;
            int d = p >> 4, ch = p & 15;
            size_t g = ((size_t)(b * NKV + hk) * HD + d) * TT + k0 + ch * 8;
            cp16(Vsh + d * VSTR + ch * 8, vtf + g);
        }
        asm volatile("cp.async.commit_group;" ::: "memory");
    };

    fill(0, 0);

    for (int kb = 0; kb < kb_end; kb++) {
        const int cur = kb & 1;
        const int k0 = kb * BKV;
        if (kb + 1 < kb_end) {
            fill(cur ^ 1, kb + 1);
            asm volatile("cp.async.wait_group 1;" ::: "memory");
        } else {
            asm volatile("cp.async.wait_group 0;" ::: "memory");
        }
        __syncthreads();

        const __half* Ksh = smA + cur * ASTAGE;
        const __half* Vsh = Ksh + KTILE;

        float S[16][4];
#pragma unroll
        for (int jt = 0; jt < 16; jt++)
#pragma unroll
            for (int e = 0; e < 4; e++) S[jt][e] = 0.0f;

#pragma unroll
        for (int kt = 0; kt < 8; kt++) {
#pragma unroll
            for (int jt = 0; jt < 16; jt++) {
                int base = (jt * 8 + (lane >> 2)) * KSTR + kt * 16 + qpair;
                uint32_t b0 = *(const uint32_t*)&Ksh[base];
                uint32_t b1 = *(const uint32_t*)&Ksh[base + 8];
                mma16816(S[jt], Qf[kt], b0, b1);
            }
        }

        const bool diag = (kb == qb);
#pragma unroll
        for (int jt = 0; jt < 16; jt++) {
            int c0 = k0 + jt * 8 + qpair;
            S[jt][0] *= SCL; S[jt][1] *= SCL; S[jt][2] *= SCL; S[jt][3] *= SCL;
            if (diag) {
                if (c0 > rg0)     S[jt][0] = -CUDART_INF_F;
                if (c0 + 1 > rg0) S[jt][1] = -CUDART_INF_F;
                if (c0 > rg1)     S[jt][2] = -CUDART_INF_F;
                if (c0 + 1 > rg1) S[jt][3] = -CUDART_INF_F;
            }
        }

        float mx0 = -CUDART_INF_F, mx1 = -CUDART_INF_F;
#pragma unroll
        for (int jt = 0; jt < 16; jt++) {
            mx0 = fmaxf(mx0, fmaxf(S[jt][0], S[jt][1]));
            mx1 = fmaxf(mx1, fmaxf(S[jt][2], S[jt][3]));
        }
#pragma unroll
        for (int off = 1; off <= 2; off <<= 1) {
            mx0 = fmaxf(mx0, __shfl_xor_sync(0xffffffffu, mx0, off));
            mx1 = fmaxf(mx1, __shfl_xor_sync(0xffffffffu, mx1, off));
        }
        float mn0 = fmaxf(m0, mx0), mn1 = fmaxf(m1, mx1);
        float al0 = fast_exp2(m0 - mn0), al1 = fast_exp2(m1 - mn1);
        float s0 = 0.0f, s1 = 0.0f;
#pragma unroll
        for (int jt = 0; jt < 16; jt++) {
            S[jt][0] = fast_exp2(S[jt][0] - mn0); s0 += S[jt][0];
            S[jt][1] = fast_exp2(S[jt][1] - mn0); s0 += S[jt][1];
            S[jt][2] = fast_exp2(S[jt][2] - mn1); s1 += S[jt][2];
            S[jt][3] = fast_exp2(S[jt][3] - mn1); s1 += S[jt][3];
        }
#pragma unroll
        for (int off = 1; off <= 2; off <<= 1) {
            s0 += __shfl_xor_sync(0xffffffffu, s0, off);
            s1 += __shfl_xor_sync(0xffffffffu, s1, off);
        }
        l0 = l0 * al0 + s0; l1 = l1 * al1 + s1;
        m0 = mn0; m1 = mn1;
#pragma unroll
        for (int nt = 0; nt < 16; nt++) {
            O[nt][0] *= al0; O[nt][1] *= al0;
            O[nt][2] *= al1; O[nt][3] *= al1;
        }

        // ---- O += P V (P single fp16) ----
#pragma unroll
        for (int kt = 0; kt < 8; kt++) {
            uint32_t Ph[4];
            Ph[0] = pack_h(S[2 * kt][0],     S[2 * kt][1]);
            Ph[1] = pack_h(S[2 * kt][2],     S[2 * kt][3]);
            Ph[2] = pack_h(S[2 * kt + 1][0], S[2 * kt + 1][1]);
            Ph[3] = pack_h(S[2 * kt + 1][2], S[2 * kt + 1][3]);
#pragma unroll
            for (int nt = 0; nt < 16; nt++) {
                int base = (nt * 8 + (lane >> 2)) * VSTR + kt * 16 + qpair;
                uint32_t b0 = *(const uint32_t*)&Vsh[base];
                uint32_t b1 = *(const uint32_t*)&Vsh[base + 8];
                mma16816(O[nt], Ph, b0, b1);
            }
        }
        __syncthreads();
    }

    float il0 = 1.0f / l0, il1 = 1.0f / l1;
#pragma unroll
    for (int nt = 0; nt < 16; nt++) {
        int d = nt * 8 + qpair;
        size_t base0 = (size_t)(b * TT + rg0) * NE + h * HD + d;
        size_t base1 = (size_t)(b * TT + rg1) * NE + h * HD + d;
        *(uint32_t*)&yp[base0] = pack_h(O[nt][0] * il0, O[nt][1] * il0);
        *(uint32_t*)&yp[base1] = pack_h(O[nt][2] * il1, O[nt][3] * il1);
    }
}

// ---------------------------------------------------------------------------
extern "C" void kernel_launch(void* const* d_in, const int* in_sizes, int n_in,
                              void* d_out, int out_size) {
    const float* x  = (const float*)d_in[0];
    const float* wq = (const float*)d_in[1];
    const float* wk = (const float*)d_in[2];
    const float* wv = (const float*)d_in[3];
    const float* wo = (const float*)d_in[4];
    float* out = (float*)d_out;

    __half *xp, *wqp, *wkp, *wvp, *wop, *qp, *kp, *vtp, *yp;
    cudaGetSymbolAddress((void**)&xp,  g_x);
    cudaGetSymbolAddress((void**)&wqp, g_wq);  cudaGetSymbolAddress((void**)&wkp, g_wk);
    cudaGetSymbolAddress((void**)&wvp, g_wv);  cudaGetSymbolAddress((void**)&wop, g_wo);
    cudaGetSymbolAddress((void**)&qp,  g_q);
    cudaGetSymbolAddress((void**)&kp,  g_k);   cudaGetSymbolAddress((void**)&vtp, g_vt);
    cudaGetSymbolAddress((void**)&yp,  g_y);

    prep_all<<<(PREP_TOTAL + 255) / 256, 256>>>(x, wq, wk, wv, wo,
                                                xp, wqp, wkp, wvp, wop);

    cudaFuncSetAttribute(gemm_qkv, cudaFuncAttributeMaxDynamicSharedMemorySize, GEMM_SMEM);
    cudaFuncSetAttribute(gemm_wo,  cudaFuncAttributeMaxDynamicSharedMemorySize, GEMM_SMEM);

    dim3 blk(256);
    gemm_qkv<<<dim3(24, 32), blk, GEMM_SMEM>>>(xp, wqp, wkp, wvp, qp, kp, vtp);

    cudaFuncSetAttribute(attn_mma, cudaFuncAttributeMaxDynamicSharedMemorySize, SM_ATT_BYTES);
    attn_mma<<<dim3(TT / BQ, BB * NH), blk, SM_ATT_BYTES>>>(qp, kp, vtp, yp);

    gemm_wo<<<dim3(16, 32), blk, GEMM_SMEM>>>(yp, wop, out);
}